// round 10
// baseline (speedup 1.0000x reference)
#include <cuda_runtime.h>
#include <cuda_bf16.h>
#include <math.h>
#include <stdint.h>

// ---------------- problem constants ----------------
#define BSZ     2
#define SEQL    4096
#define DMODEL  768
#define DSTATE  128
#define HD      64
#define DIN     1536
#define NH      24
#define DXBC    1792          // DIN + 2*DSTATE
#define DPROJ   3352          // 2*DIN + 2*DSTATE + NH
#define CHUNKQ  128
#define NCH     32            // SEQL / CHUNKQ
#define NROWS   (BSZ*SEQL)    // 8192
#define NBC     (BSZ*NCH)     // 64

#define KP1     (3*DMODEL)    // 2304
#define KP2     (3*DIN)       // 4608
#define NPAD1   3456          // 27*128

// single shared-memory extern symbol (consistent across all kernels)
extern __shared__ __align__(128) char smbuf[];

// ---------------- scratch (static device memory; no runtime allocs) ----------------
__device__ float g_zx[(size_t)NROWS*DPROJ];
__device__ float g_xbc[(size_t)NROWS*DXBC];
__device__ float g_dt[NROWS*NH];
__device__ float g_acum[NROWS*NH];
__device__ float g_alast[NBC*NH];
__device__ float g_cb[(size_t)NBC*CHUNKQ*CHUNKQ];
__device__ float g_states[(size_t)NBC*NH*HD*DSTATE];
__device__ float g_prev[(size_t)NBC*NH*HD*DSTATE];
__device__ float g_y[(size_t)NROWS*DIN];
__device__ __nv_bfloat16 g_a2[(size_t)NROWS*KP2];
__device__ __nv_bfloat16 g_b2[(size_t)NPAD1*KP1];

// ================= helpers (family-target safe) =================
__device__ __forceinline__ uint32_t smem_u32(const void* p) {
    uint32_t a;
    asm("{ .reg .u64 t; cvta.to.shared.u64 t, %1; cvt.u32.u64 %0, t; }" : "=r"(a) : "l"(p));
    return a;
}
__device__ __forceinline__ void cpasync16(uint32_t dst, const void* src) {
    asm volatile("cp.async.cg.shared.global [%0], [%1], 16;" :: "r"(dst), "l"(src) : "memory");
}
__device__ __forceinline__ void ldsm4(uint32_t* r, uint32_t addr) {
    asm volatile("ldmatrix.sync.aligned.m8n8.x4.shared.b16 {%0,%1,%2,%3}, [%4];"
                 : "=r"(r[0]), "=r"(r[1]), "=r"(r[2]), "=r"(r[3]) : "r"(addr));
}
__device__ __forceinline__ void mma16816(float* d, const uint32_t* a, const uint32_t* b,
                                         const float* c) {
    asm volatile("mma.sync.aligned.m16n8k16.row.col.f32.bf16.bf16.f32 "
        "{%0,%1,%2,%3}, {%4,%5,%6,%7}, {%8,%9}, {%10,%11,%12,%13};"
        : "=f"(d[0]), "=f"(d[1]), "=f"(d[2]), "=f"(d[3])
        : "r"(a[0]), "r"(a[1]), "r"(a[2]), "r"(a[3]), "r"(b[0]), "r"(b[1]),
          "f"(c[0]), "f"(c[1]), "f"(c[2]), "f"(c[3]));
}
#define SWZ128(x) ((x) ^ (((x) >> 3) & 0x70))
#define SWZ256(x) ((x) ^ (((x) >> 4) & 0x70))

__device__ __forceinline__ void split_store(char* hi_base, char* lo_base, uint32_t off, float v) {
    __nv_bfloat16 hi = __float2bfloat16(v);
    __nv_bfloat16 lo = __float2bfloat16(v - __bfloat162float(hi));
    *(__nv_bfloat16*)(hi_base + off) = hi;
    *(__nv_bfloat16*)(lo_base + off) = lo;
}

// ================= split-precision conversion for GEMM1 =================
__global__ void split_a_kernel(const float* __restrict__ X, __nv_bfloat16* __restrict__ O,
                               int M, int K)
{
    int idx = blockIdx.x * blockDim.x + threadIdx.x;
    if (idx >= M * K) return;
    int m = idx / K, k = idx % K;
    float x = X[idx];
    __nv_bfloat16 hi = __float2bfloat16(x);
    __nv_bfloat16 lo = __float2bfloat16(x - __bfloat162float(hi));
    size_t base = (size_t)m * 3 * K;
    O[base + k] = hi; O[base + K + k] = hi; O[base + 2*K + k] = lo;
}
__global__ void split_b_kernel(const float* __restrict__ W, __nv_bfloat16* __restrict__ O,
                               int Nreal, int Npad, int K)
{
    int idx = blockIdx.x * blockDim.x + threadIdx.x;
    if (idx >= Npad * K) return;
    int n = idx / K, k = idx % K;
    __nv_bfloat16 hi = __float2bfloat16(0.f), lo = hi;
    if (n < Nreal) {
        float x = W[(size_t)n * K + k];
        hi = __float2bfloat16(x);
        lo = __float2bfloat16(x - __bfloat162float(hi));
    }
    size_t base = (size_t)n * 3 * K;
    O[base + k] = hi; O[base + K + k] = lo; O[base + 2*K + k] = hi;
}

// ================= mma.sync bf16 GEMM — 3-stage cp.async pipeline =================
#define GEMM_SMEM_BYTES (1024 + 3*32768)
__global__ __launch_bounds__(256, 2)
void gemm_mma(const __nv_bfloat16* __restrict__ A2, const __nv_bfloat16* __restrict__ B2,
              float* __restrict__ C, int KP, int Nreal, int ldc,
              const float* __restrict__ feat, const float* __restrict__ gate1, int ep)
{
    const uint32_t base = (smem_u32(smbuf) + 1023) & ~1023u;
    const int tid  = threadIdx.x;
    const int lane = tid & 31;
    const int wid  = tid >> 5;
    const int m0 = blockIdx.y * 128;
    const int n0 = blockIdx.x * 128;
    const int wm = wid >> 2;
    const int wn = wid & 3;

    const int frow = tid >> 3;
    const int u16  = tid & 7;
    const __nv_bfloat16* ag = A2 + (size_t)(m0 + frow) * KP + u16 * 8;
    const __nv_bfloat16* bg = B2 + (size_t)(n0 + frow) * KP + u16 * 8;

    float acc[4][4][4] = {};
    const int nch = KP >> 6;

    uint32_t foff[4];
    #pragma unroll
    for (int j = 0; j < 4; ++j)
        foff[j] = SWZ128((frow + j*32)*128 + u16*16);

    // prologue: stages 0 and 1
    #pragma unroll
    for (int pc = 0; pc < 2; ++pc) {
        uint32_t ab = base + pc * 32768, bb = ab + 16384;
        const __nv_bfloat16* a = ag + pc * 64;
        const __nv_bfloat16* b = bg + pc * 64;
        #pragma unroll
        for (int j = 0; j < 4; ++j) {
            cpasync16(ab + foff[j], a + (size_t)(j*32)*KP);
            cpasync16(bb + foff[j], b + (size_t)(j*32)*KP);
        }
        asm volatile("cp.async.commit_group;" ::: "memory");
    }

    int stage = 0;        // stage of chunk c
    int nstage = 2;       // stage for chunk c+2
    for (int c = 0; c < nch; ++c) {
        // ensure chunk c resident (allow chunk c+1 in flight)
        if (c < nch - 1)
            asm volatile("cp.async.wait_group 1;" ::: "memory");
        else
            asm volatile("cp.async.wait_group 0;" ::: "memory");
        __syncthreads();   // single barrier per chunk; also releases stage (c-1)%3 for refill

        // issue loads for chunk c+2 into stage (c+2)%3 == (c-1)%3 (safe after the barrier)
        if (c + 2 < nch) {
            uint32_t ab = base + nstage * 32768, bb = ab + 16384;
            const __nv_bfloat16* a = ag + (c+2) * 64;
            const __nv_bfloat16* b = bg + (c+2) * 64;
            #pragma unroll
            for (int j = 0; j < 4; ++j) {
                cpasync16(ab + foff[j], a + (size_t)(j*32)*KP);
                cpasync16(bb + foff[j], b + (size_t)(j*32)*KP);
            }
            asm volatile("cp.async.commit_group;" ::: "memory");
        }

        const uint32_t ab = base + stage * 32768;
        const uint32_t bb = ab + 16384;
        #pragma unroll
        for (int ks = 0; ks < 4; ++ks) {
            uint32_t a_r[4][4];
            uint32_t b_r[2][4];
            {
                const int ra = wm*64 + ((lane>>3)&1)*8 + (lane&7);
                const int ka = ks*32 + ((lane>>4)&1)*16;
                #pragma unroll
                for (int mf = 0; mf < 4; ++mf)
                    ldsm4(a_r[mf], ab + SWZ128((ra + mf*16)*128 + ka));
            }
            {
                const int rb = wn*32 + ((lane>>4)&1)*8 + (lane&7);
                const int kb = ks*32 + ((lane>>3)&1)*16;
                #pragma unroll
                for (int nf2 = 0; nf2 < 2; ++nf2)
                    ldsm4(b_r[nf2], bb + SWZ128((rb + nf2*16)*128 + kb));
            }
            #pragma unroll
            for (int mf = 0; mf < 4; ++mf)
                #pragma unroll
                for (int nf = 0; nf < 4; ++nf)
                    mma16816(acc[mf][nf], a_r[mf], &b_r[nf>>1][(nf&1)*2], acc[mf][nf]);
        }
        stage  = (stage  == 2) ? 0 : stage  + 1;
        nstage = (nstage == 2) ? 0 : nstage + 1;
    }

    float g = 0.f;
    if (ep) g = 1.f / (1.f + expf(-gate1[0]));
    const int mrow = m0 + wm*64 + (lane >> 2);
    const int nbase = n0 + wn*32 + (lane & 3)*2;
    #pragma unroll
    for (int mf = 0; mf < 4; ++mf) {
        #pragma unroll
        for (int nf = 0; nf < 4; ++nf) {
            int m = mrow + mf*16;
            int n = nbase + nf*8;
            if (n < Nreal) {
                float2 v0 = make_float2(acc[mf][nf][0], acc[mf][nf][1]);
                float2 v1 = make_float2(acc[mf][nf][2], acc[mf][nf][3]);
                if (ep) {
                    float2 f0 = *(const float2*)(feat + (size_t)m*ldc + n);
                    float2 f1 = *(const float2*)(feat + (size_t)(m+8)*ldc + n);
                    v0.x = g*v0.x + f0.x; v0.y = g*v0.y + f0.y;
                    v1.x = g*v1.x + f1.x; v1.y = g*v1.y + f1.y;
                }
                *(float2*)(C + (size_t)m*ldc + n)     = v0;
                *(float2*)(C + (size_t)(m+8)*ldc + n) = v1;
            }
        }
    }
}

// ---------------- depthwise causal conv (width 4) + bias + SiLU, 4 rows/thread ----------------
__global__ void conv_silu_kernel(const float* __restrict__ cw, const float* __restrict__ cb)
{
    int ch = blockIdx.x * 256 + threadIdx.x;        // 0..DXBC-1 (DXBC = 7*256)
    int r0 = blockIdx.y * 4;
    int l0 = r0 % SEQL;
    float w0 = cw[ch*4+0], w1 = cw[ch*4+1], w2 = cw[ch*4+2], w3 = cw[ch*4+3];
    float bias = cb[ch];
    float v[7];
    #pragma unroll
    for (int t = 0; t < 7; ++t) {
        int lr = l0 + t - 3;
        v[t] = (lr >= 0) ? g_zx[(size_t)(r0 + t - 3) * DPROJ + DIN + ch] : 0.f;
    }
    #pragma unroll
    for (int j = 0; j < 4; ++j) {
        float acc = bias + w0*v[j] + w1*v[j+1] + w2*v[j+2] + w3*v[j+3];
        g_xbc[(size_t)(r0 + j) * DXBC + ch] = acc / (1.f + __expf(-acc));
    }
}

// ---------------- dt (softplus) + per-chunk inclusive cumsum of dt*A, fused ----------------
__global__ void acum_kernel(const float* __restrict__ A_log, const float* __restrict__ dt_bias)
{
    int h  = blockIdx.x % NH;
    int bc = blockIdx.x / NH;
    int l  = threadIdx.x;
    __shared__ float s[CHUNKQ];
    float Ah = -expf(A_log[h]);
    int row = bc * CHUNKQ + l;
    float v = g_zx[(size_t)row * DPROJ + (DIN + DXBC) + h] + dt_bias[h];
    float dt = (v > 20.f) ? v : log1pf(expf(v));
    g_dt[row * NH + h] = dt;
    s[l] = dt * Ah;
    __syncthreads();
    for (int off = 1; off < CHUNKQ; off <<= 1) {
        float t = (l >= off) ? s[l - off] : 0.f;
        __syncthreads();
        s[l] += t;
        __syncthreads();
    }
    g_acum[row * NH + h] = s[l];
    if (l == CHUNKQ - 1) g_alast[bc * NH + h] = s[l];
}

// ---------------- CB[l,s] = sum_n C[l,n]*B[s,n] per chunk (fp32, feeds W) ----------------
#define CB_SMEM_BYTES ((CHUNKQ*CHUNKQ + CHUNKQ*132) * 4)
__global__ void cb_kernel()
{
    float* sm  = (float*)smbuf;
    float* Cs  = sm;
    float* BsT = sm + CHUNKQ*CHUNKQ;
    int bc  = blockIdx.x;
    int tid = threadIdx.x;
    int row0 = bc * CHUNKQ;
    for (int i = tid; i < CHUNKQ*CHUNKQ; i += 256) {
        int l = i >> 7, n = i & 127;
        const float* base = &g_xbc[(size_t)(row0 + l) * DXBC];
        Cs[i]            = base[DIN + DSTATE + n];
        BsT[n*132 + l]   = base[DIN + n];
    }
    __syncthreads();
    int l  = tid >> 1;
    int s0 = (tid & 1) * 64;
    float acc[64] = {};
    for (int n = 0; n < 128; n++) {
        float cv = Cs[l*128 + n];
        const float4* bp = (const float4*)&BsT[n*132 + s0];
        #pragma unroll
        for (int j4 = 0; j4 < 16; j4++) {
            float4 b = bp[j4];
            acc[4*j4+0] += cv*b.x; acc[4*j4+1] += cv*b.y;
            acc[4*j4+2] += cv*b.z; acc[4*j4+3] += cv*b.w;
        }
    }
    float* outp = &g_cb[(size_t)bc*CHUNKQ*CHUNKQ + l*CHUNKQ + s0];
    #pragma unroll
    for (int j4 = 0; j4 < 16; j4++)
        ((float4*)outp)[j4] = make_float4(acc[4*j4], acc[4*j4+1], acc[4*j4+2], acc[4*j4+3]);
}

// ================= states via mma.sync (split bf16) =================
#define STM_SMEM_BYTES 98304
__global__ __launch_bounds__(128, 2) void states_mma()
{
    char* sm = smbuf;
    __shared__ float wfac[128];
    const int h  = blockIdx.x % NH;
    const int bc = blockIdx.x / NH;
    const int tid = threadIdx.x;
    const int row0 = bc * CHUNKQ;

    if (tid < 128) {
        float alast = g_alast[bc*NH + h];
        wfac[tid] = g_dt[(row0+tid)*NH + h] * __expf(alast - g_acum[(row0+tid)*NH + h]);
    }
    __syncthreads();
    for (int i = tid; i < 8192; i += 128) {
        int l = i >> 6, p = i & 63;
        float v = g_xbc[(size_t)(row0+l)*DXBC + h*HD + p] * wfac[l];
        split_store(sm, sm + 16384, SWZ256(p*256 + l*2), v);
    }
    for (int i = tid; i < 16384; i += 128) {
        int l = i >> 7, n = i & 127;
        float v = g_xbc[(size_t)(row0+l)*DXBC + DIN + n];
        split_store(sm + 32768, sm + 65536, SWZ256(n*256 + l*2), v);
    }
    __syncthreads();

    const int lane = tid & 31;
    const int w = tid >> 5;
    const uint32_t base = smem_u32(sm);
    float acc[4][4][4] = {};
    const uint32_t AO[3] = {0u, 0u, 16384u};
    const uint32_t BO[3] = {32768u, 65536u, 32768u};
    #pragma unroll
    for (int pp = 0; pp < 3; ++pp) {
        const uint32_t ab = base + AO[pp], bb = base + BO[pp];
        #pragma unroll
        for (int ks = 0; ks < 8; ++ks) {
            uint32_t a_r[4][4], b_r[2][4];
            const int ra = ((lane>>3)&1)*8 + (lane&7);
            const int ca = ks*32 + ((lane>>4)&1)*16;
            #pragma unroll
            for (int mf = 0; mf < 4; ++mf)
                ldsm4(a_r[mf], ab + SWZ256((ra + mf*16)*256 + ca));
            const int rb = w*32 + ((lane>>4)&1)*8 + (lane&7);
            const int cb2 = ks*32 + ((lane>>3)&1)*16;
            #pragma unroll
            for (int nf2 = 0; nf2 < 2; ++nf2)
                ldsm4(b_r[nf2], bb + SWZ256((rb + nf2*16)*256 + cb2));
            #pragma unroll
            for (int mf = 0; mf < 4; ++mf)
                #pragma unroll
                for (int nf = 0; nf < 4; ++nf)
                    mma16816(acc[mf][nf], a_r[mf], &b_r[nf>>1][(nf&1)*2], acc[mf][nf]);
        }
    }
    float* outb = &g_states[((size_t)(bc*NH) + h) * HD * DSTATE];
    const int mr = lane >> 2;
    const int nb = w*32 + (lane & 3)*2;
    #pragma unroll
    for (int mf = 0; mf < 4; ++mf) {
        #pragma unroll
        for (int nf = 0; nf < 4; ++nf) {
            int p = mf*16 + mr, n = nb + nf*8;
            *(float2*)&outb[p*DSTATE + n]       = make_float2(acc[mf][nf][0], acc[mf][nf][1]);
            *(float2*)&outb[(p+8)*DSTATE + n]   = make_float2(acc[mf][nf][2], acc[mf][nf][3]);
        }
    }
}

// ---------------- inter-chunk state recurrence (one lane per thread) ----------------
__global__ void scan_kernel()
{
    int gl = blockIdx.x * blockDim.x + threadIdx.x;
    int bh = gl >> 13;
    int b = bh / NH, h = bh % NH;
    int e = gl & 8191;
    float S = 0.f;
    for (int c = 0; c < NCH; c++) {
        int bc = b*NCH + c;
        size_t base = ((size_t)(bc*NH) + h) * HD * DSTATE;
        float ed = __expf(g_alast[bc*NH + h]);
        float st = g_states[base + e];
        g_prev[base + e] = S;
        S = S*ed + st;
    }
}

// ================= Y via mma.sync (split bf16) =================
#define YM_SMEM_BYTES 98304
__device__ __forceinline__ void y_mma_block(float acc[2][4][4], uint32_t base,
                                            int lane, int wm, int wn)
{
    const uint32_t AO[3] = {0u, 0u, 32768u};
    const uint32_t BO[3] = {65536u, 81920u, 65536u};
    #pragma unroll
    for (int pp = 0; pp < 3; ++pp) {
        const uint32_t ab = base + AO[pp], bb = base + BO[pp];
        #pragma unroll
        for (int ks = 0; ks < 8; ++ks) {
            uint32_t a_r[2][4], b_r[2][4];
            const int ra = wm*32 + ((lane>>3)&1)*8 + (lane&7);
            const int ca = ks*32 + ((lane>>4)&1)*16;
            #pragma unroll
            for (int mf = 0; mf < 2; ++mf)
                ldsm4(a_r[mf], ab + SWZ256((ra + mf*16)*256 + ca));
            const int rb = wn*32 + ((lane>>4)&1)*8 + (lane&7);
            const int cb2 = ks*32 + ((lane>>3)&1)*16;
            #pragma unroll
            for (int nf2 = 0; nf2 < 2; ++nf2)
                ldsm4(b_r[nf2], bb + SWZ256((rb + nf2*16)*256 + cb2));
            #pragma unroll
            for (int mf = 0; mf < 2; ++mf)
                #pragma unroll
                for (int nf = 0; nf < 4; ++nf)
                    mma16816(acc[mf][nf], a_r[mf], &b_r[nf>>1][(nf&1)*2], acc[mf][nf]);
        }
    }
}

__global__ __launch_bounds__(256, 2) void y_mma(const float* __restrict__ Dv)
{
    char* sm = smbuf;
    __shared__ float acum_s[128], dt_s[128], eAl_s[128];
    const int h  = blockIdx.x % NH;
    const int bc = blockIdx.x / NH;
    const int tid = threadIdx.x;
    const int row0 = bc * CHUNKQ;

    if (tid < 128) {
        float a = g_acum[(row0+tid)*NH + h];
        acum_s[tid] = a;
        eAl_s[tid]  = __expf(a);
        dt_s[tid]   = g_dt[(row0+tid)*NH + h];
    }
    __syncthreads();

    for (int i = tid; i < 16384; i += 256) {
        int l = i >> 7, n = i & 127;
        float v = g_xbc[(size_t)(row0+l)*DXBC + DIN + DSTATE + n] * eAl_s[l];
        split_store(sm, sm + 32768, SWZ256(l*256 + n*2), v);
    }
    const size_t pbase = ((size_t)(bc*NH) + h) * HD * DSTATE;
    for (int i = tid; i < 8192; i += 256) {
        int p = i >> 7, n = i & 127;
        float v = g_prev[pbase + i];
        split_store(sm + 65536, sm + 81920, SWZ256(p*256 + n*2), v);
    }
    __syncthreads();

    const int lane = tid & 31;
    const int wid = tid >> 5;
    const int wm = wid >> 1;
    const int wn = wid & 1;
    const uint32_t base = smem_u32(sm);
    float acc[2][4][4] = {};
    y_mma_block(acc, base, lane, wm, wn);
    __syncthreads();

    for (int i = tid; i < 16384; i += 256) {
        int l = i >> 7, s = i & 127;
        float v = 0.f;
        if (s <= l)
            v = g_cb[(size_t)bc*CHUNKQ*CHUNKQ + i] * __expf(acum_s[l] - acum_s[s]) * dt_s[s];
        split_store(sm, sm + 32768, SWZ256(l*256 + s*2), v);
    }
    for (int i = tid; i < 8192; i += 256) {
        int l = i >> 6, p = i & 63;
        float v = g_xbc[(size_t)(row0+l)*DXBC + h*HD + p];
        split_store(sm + 65536, sm + 81920, SWZ256(p*256 + l*2), v);
    }
    __syncthreads();
    y_mma_block(acc, base, lane, wm, wn);

    const float dval = Dv[h];
    const int mr = lane >> 2;
    const int nb = (lane & 3)*2;
    #pragma unroll
    for (int mf = 0; mf < 2; ++mf) {
        #pragma unroll
        for (int nf = 0; nf < 4; ++nf) {
            int p = wn*32 + nf*8 + nb;
            #pragma unroll
            for (int rr = 0; rr < 2; ++rr) {
                int l = wm*32 + mf*16 + mr + rr*8;
                uint32_t o0 = SWZ256(p*256 + l*2);
                uint32_t o1 = SWZ256((p+1)*256 + l*2);
                float x0 = __bfloat162float(*(__nv_bfloat16*)(sm + 65536 + o0))
                         + __bfloat162float(*(__nv_bfloat16*)(sm + 81920 + o0));
                float x1 = __bfloat162float(*(__nv_bfloat16*)(sm + 65536 + o1))
                         + __bfloat162float(*(__nv_bfloat16*)(sm + 81920 + o1));
                float2 v = make_float2(acc[mf][nf][rr*2+0] + dval*x0,
                                       acc[mf][nf][rr*2+1] + dval*x1);
                *(float2*)&g_y[(size_t)(row0+l)*DIN + h*HD + p] = v;
            }
        }
    }
}

// ---------------- gating + RMSNorm + fused split_a for GEMM2 ----------------
__global__ void norm_split_kernel(const float* __restrict__ norm_w,
                                  __nv_bfloat16* __restrict__ O)
{
    __shared__ float tbuf[DIN];
    __shared__ float red[256];
    int row = blockIdx.x;
    int tid = threadIdx.x;
    float partial = 0.f;
    for (int i = tid; i < DIN; i += 256) {
        float yv = g_y[(size_t)row*DIN + i];
        float zv = g_zx[(size_t)row*DPROJ + i];
        float t  = yv * (zv / (1.f + __expf(-zv)));
        tbuf[i] = t;
        partial += t*t;
    }
    red[tid] = partial;
    __syncthreads();
    for (int s = 128; s > 0; s >>= 1) {
        if (tid < s) red[tid] += red[tid + s];
        __syncthreads();
    }
    float scale = rsqrtf(red[0] / (float)DIN + 1e-5f);
    __nv_bfloat16* ob = O + (size_t)row * KP2;
    for (int i = tid; i < DIN; i += 256) {
        float v = tbuf[i] * scale * norm_w[i];
        __nv_bfloat16 hi = __float2bfloat16(v);
        __nv_bfloat16 lo = __float2bfloat16(v - __bfloat162float(hi));
        ob[i] = hi; ob[DIN + i] = hi; ob[2*DIN + i] = lo;
    }
}

// ---------------- launch ----------------
extern "C" void kernel_launch(void* const* d_in, const int* in_sizes, int n_in,
                              void* d_out, int out_size)
{
    const float* feature = (const float*)d_in[0];
    const float* gate1   = (const float*)d_in[1];
    const float* in_w    = (const float*)d_in[2];
    const float* conv_w  = (const float*)d_in[3];
    const float* conv_b  = (const float*)d_in[4];
    const float* dt_bias = (const float*)d_in[5];
    const float* A_log   = (const float*)d_in[6];
    const float* Dv      = (const float*)d_in[7];
    const float* norm_w  = (const float*)d_in[8];
    const float* out_w   = (const float*)d_in[9];
    float* out = (float*)d_out;

    void* p_zx; cudaGetSymbolAddress(&p_zx, g_zx);
    void* p_a2; cudaGetSymbolAddress(&p_a2, g_a2);
    void* p_b2; cudaGetSymbolAddress(&p_b2, g_b2);
    __nv_bfloat16* a2 = (__nv_bfloat16*)p_a2;
    __nv_bfloat16* b2 = (__nv_bfloat16*)p_b2;

    cudaFuncSetAttribute(cb_kernel,  cudaFuncAttributeMaxDynamicSharedMemorySize, CB_SMEM_BYTES);
    cudaFuncSetAttribute(states_mma, cudaFuncAttributeMaxDynamicSharedMemorySize, STM_SMEM_BYTES);
    cudaFuncSetAttribute(y_mma,      cudaFuncAttributeMaxDynamicSharedMemorySize, YM_SMEM_BYTES);
    cudaFuncSetAttribute(gemm_mma,   cudaFuncAttributeMaxDynamicSharedMemorySize, GEMM_SMEM_BYTES);

    // 1. split conversion + GEMM1 (tensor cores, 3-stage pipeline)
    split_a_kernel<<<(NROWS*DMODEL + 255)/256, 256>>>(feature, a2, NROWS, DMODEL);
    split_b_kernel<<<(NPAD1*DMODEL + 255)/256, 256>>>(in_w, b2, DPROJ, NPAD1, DMODEL);
    gemm_mma<<<dim3(NPAD1/128, NROWS/128), 256, GEMM_SMEM_BYTES>>>(
        a2, b2, (float*)p_zx, KP1, DPROJ, DPROJ, nullptr, nullptr, 0);
    // 2. conv + silu (4 rows per thread)
    conv_silu_kernel<<<dim3(DXBC/256, NROWS/4), 256>>>(conv_w, conv_b);
    // 3. dt + per-chunk cumsum (fused)
    acum_kernel<<<NBC*NH, CHUNKQ>>>(A_log, dt_bias);
    // 4. CB per chunk (fp32)
    cb_kernel<<<NBC, 256, CB_SMEM_BYTES>>>();
    // 5. chunk states (tensor cores, split bf16)
    states_mma<<<NBC*NH, 128, STM_SMEM_BYTES>>>();
    // 6. inter-chunk recurrence
    scan_kernel<<<(BSZ*NH*HD*DSTATE)/512, 512>>>();
    // 7. Y (tensor cores, split bf16)
    y_mma<<<NBC*NH, 256, YM_SMEM_BYTES>>>(Dv);
    // 8. gating + RMSNorm + split for GEMM2 (fused)
    norm_split_kernel<<<NROWS, 256>>>(norm_w, a2);
    // 9. split B + GEMM2 (tensor cores) + residual epilogue
    split_b_kernel<<<(DMODEL*DIN + 255)/256, 256>>>(out_w, b2, DMODEL, DMODEL, DIN);
    gemm_mma<<<dim3(DMODEL/128, NROWS/128), 256, GEMM_SMEM_BYTES>>>(
        a2, b2, out, KP2, DMODEL, DMODEL, feature, gate1, 1);
}

// round 11
// speedup vs baseline: 1.0585x; 1.0585x over previous
#include <cuda_runtime.h>
#include <cuda_bf16.h>
#include <math.h>
#include <stdint.h>

// ---------------- problem constants ----------------
#define BSZ     2
#define SEQL    4096
#define DMODEL  768
#define DSTATE  128
#define HD      64
#define DIN     1536
#define NH      24
#define DXBC    1792          // DIN + 2*DSTATE
#define DPROJ   3352          // 2*DIN + 2*DSTATE + NH
#define CHUNKQ  128
#define NCH     32            // SEQL / CHUNKQ
#define NROWS   (BSZ*SEQL)    // 8192
#define NBC     (BSZ*NCH)     // 64

#define KP1     (3*DMODEL)    // 2304
#define KP2     (3*DIN)       // 4608
#define NPAD1   3456          // 27*128

// single shared-memory extern symbol (consistent across all kernels)
extern __shared__ __align__(128) char smbuf[];

// ---------------- scratch (static device memory; no runtime allocs) ----------------
__device__ float g_zx[(size_t)NROWS*DPROJ];
__device__ float g_xbc[(size_t)NROWS*DXBC];
__device__ float g_dt[NROWS*NH];
__device__ float g_acum[NROWS*NH];
__device__ float g_alast[NBC*NH];
__device__ float g_cb[(size_t)NBC*CHUNKQ*CHUNKQ];
__device__ float g_states[(size_t)NBC*NH*HD*DSTATE];
__device__ float g_prev[(size_t)NBC*NH*HD*DSTATE];
__device__ float g_y[(size_t)NROWS*DIN];
__device__ __nv_bfloat16 g_a2[(size_t)NROWS*KP2];
__device__ __nv_bfloat16 g_b2[(size_t)NPAD1*KP1];

// ================= helpers (family-target safe) =================
__device__ __forceinline__ uint32_t smem_u32(const void* p) {
    uint32_t a;
    asm("{ .reg .u64 t; cvta.to.shared.u64 t, %1; cvt.u32.u64 %0, t; }" : "=r"(a) : "l"(p));
    return a;
}
__device__ __forceinline__ void cpasync16(uint32_t dst, const void* src) {
    asm volatile("cp.async.cg.shared.global [%0], [%1], 16;" :: "r"(dst), "l"(src) : "memory");
}
__device__ __forceinline__ void ldsm4(uint32_t* r, uint32_t addr) {
    asm volatile("ldmatrix.sync.aligned.m8n8.x4.shared.b16 {%0,%1,%2,%3}, [%4];"
                 : "=r"(r[0]), "=r"(r[1]), "=r"(r[2]), "=r"(r[3]) : "r"(addr));
}
__device__ __forceinline__ void mma16816(float* d, const uint32_t* a, const uint32_t* b,
                                         const float* c) {
    asm volatile("mma.sync.aligned.m16n8k16.row.col.f32.bf16.bf16.f32 "
        "{%0,%1,%2,%3}, {%4,%5,%6,%7}, {%8,%9}, {%10,%11,%12,%13};"
        : "=f"(d[0]), "=f"(d[1]), "=f"(d[2]), "=f"(d[3])
        : "r"(a[0]), "r"(a[1]), "r"(a[2]), "r"(a[3]), "r"(b[0]), "r"(b[1]),
          "f"(c[0]), "f"(c[1]), "f"(c[2]), "f"(c[3]));
}
#define SWZ128(x) ((x) ^ (((x) >> 3) & 0x70))
#define SWZ256(x) ((x) ^ (((x) >> 4) & 0x70))

__device__ __forceinline__ void split_store(char* hi_base, char* lo_base, uint32_t off, float v) {
    __nv_bfloat16 hi = __float2bfloat16(v);
    __nv_bfloat16 lo = __float2bfloat16(v - __bfloat162float(hi));
    *(__nv_bfloat16*)(hi_base + off) = hi;
    *(__nv_bfloat16*)(lo_base + off) = lo;
}

// ================= split-precision conversion for GEMM1 =================
__global__ void split_a_kernel(const float* __restrict__ X, __nv_bfloat16* __restrict__ O,
                               int M, int K)
{
    int idx = blockIdx.x * blockDim.x + threadIdx.x;
    if (idx >= M * K) return;
    int m = idx / K, k = idx % K;
    float x = X[idx];
    __nv_bfloat16 hi = __float2bfloat16(x);
    __nv_bfloat16 lo = __float2bfloat16(x - __bfloat162float(hi));
    size_t base = (size_t)m * 3 * K;
    O[base + k] = hi; O[base + K + k] = hi; O[base + 2*K + k] = lo;
}
__global__ void split_b_kernel(const float* __restrict__ W, __nv_bfloat16* __restrict__ O,
                               int Nreal, int Npad, int K)
{
    int idx = blockIdx.x * blockDim.x + threadIdx.x;
    if (idx >= Npad * K) return;
    int n = idx / K, k = idx % K;
    __nv_bfloat16 hi = __float2bfloat16(0.f), lo = hi;
    if (n < Nreal) {
        float x = W[(size_t)n * K + k];
        hi = __float2bfloat16(x);
        lo = __float2bfloat16(x - __bfloat162float(hi));
    }
    size_t base = (size_t)n * 3 * K;
    O[base + k] = hi; O[base + K + k] = lo; O[base + 2*K + k] = hi;
}

// ================= mma.sync bf16 GEMM (verified R5/R7/R9 2-stage shape) =================
#define GEMM_SMEM_BYTES (1024 + 2*32768)
__global__ __launch_bounds__(256, 2)
void gemm_mma(const __nv_bfloat16* __restrict__ A2, const __nv_bfloat16* __restrict__ B2,
              float* __restrict__ C, int KP, int Nreal, int ldc,
              const float* __restrict__ feat, const float* __restrict__ gate1, int ep)
{
    const uint32_t base = (smem_u32(smbuf) + 1023) & ~1023u;
    const int tid  = threadIdx.x;
    const int lane = tid & 31;
    const int wid  = tid >> 5;
    const int m0 = blockIdx.y * 128;
    const int n0 = blockIdx.x * 128;
    const int wm = wid >> 2;
    const int wn = wid & 3;

    const int frow = tid >> 3;
    const int u16  = tid & 7;
    const __nv_bfloat16* ag = A2 + (size_t)(m0 + frow) * KP + u16 * 8;
    const __nv_bfloat16* bg = B2 + (size_t)(n0 + frow) * KP + u16 * 8;

    float acc[4][4][4] = {};
    const int nch = KP >> 6;

    uint32_t foff[4];
    #pragma unroll
    for (int j = 0; j < 4; ++j)
        foff[j] = SWZ128((frow + j*32)*128 + u16*16);

    {
        uint32_t ab = base, bb = base + 16384;
        #pragma unroll
        for (int j = 0; j < 4; ++j) {
            cpasync16(ab + foff[j], ag + (size_t)(j*32)*KP);
            cpasync16(bb + foff[j], bg + (size_t)(j*32)*KP);
        }
        asm volatile("cp.async.commit_group;" ::: "memory");
    }

    for (int c = 0; c < nch; ++c) {
        if (c + 1 < nch) {
            uint32_t ab = base + ((c+1)&1) * 32768, bb = ab + 16384;
            const __nv_bfloat16* a = ag + (c+1) * 64;
            const __nv_bfloat16* b = bg + (c+1) * 64;
            #pragma unroll
            for (int j = 0; j < 4; ++j) {
                cpasync16(ab + foff[j], a + (size_t)(j*32)*KP);
                cpasync16(bb + foff[j], b + (size_t)(j*32)*KP);
            }
            asm volatile("cp.async.commit_group;" ::: "memory");
            asm volatile("cp.async.wait_group 1;" ::: "memory");
        } else {
            asm volatile("cp.async.wait_group 0;" ::: "memory");
        }
        __syncthreads();

        const uint32_t ab = base + (c&1) * 32768;
        const uint32_t bb = ab + 16384;
        #pragma unroll
        for (int ks = 0; ks < 4; ++ks) {
            uint32_t a_r[4][4];
            uint32_t b_r[2][4];
            {
                const int ra = wm*64 + ((lane>>3)&1)*8 + (lane&7);
                const int ka = ks*32 + ((lane>>4)&1)*16;
                #pragma unroll
                for (int mf = 0; mf < 4; ++mf)
                    ldsm4(a_r[mf], ab + SWZ128((ra + mf*16)*128 + ka));
            }
            {
                const int rb = wn*32 + ((lane>>4)&1)*8 + (lane&7);
                const int kb = ks*32 + ((lane>>3)&1)*16;
                #pragma unroll
                for (int nf2 = 0; nf2 < 2; ++nf2)
                    ldsm4(b_r[nf2], bb + SWZ128((rb + nf2*16)*128 + kb));
            }
            #pragma unroll
            for (int mf = 0; mf < 4; ++mf)
                #pragma unroll
                for (int nf = 0; nf < 4; ++nf)
                    mma16816(acc[mf][nf], a_r[mf], &b_r[nf>>1][(nf&1)*2], acc[mf][nf]);
        }
        __syncthreads();
    }

    float g = 0.f;
    if (ep) g = 1.f / (1.f + expf(-gate1[0]));
    const int mrow = m0 + wm*64 + (lane >> 2);
    const int nbase = n0 + wn*32 + (lane & 3)*2;
    #pragma unroll
    for (int mf = 0; mf < 4; ++mf) {
        #pragma unroll
        for (int nf = 0; nf < 4; ++nf) {
            int m = mrow + mf*16;
            int n = nbase + nf*8;
            if (n < Nreal) {
                float2 v0 = make_float2(acc[mf][nf][0], acc[mf][nf][1]);
                float2 v1 = make_float2(acc[mf][nf][2], acc[mf][nf][3]);
                if (ep) {
                    float2 f0 = *(const float2*)(feat + (size_t)m*ldc + n);
                    float2 f1 = *(const float2*)(feat + (size_t)(m+8)*ldc + n);
                    v0.x = g*v0.x + f0.x; v0.y = g*v0.y + f0.y;
                    v1.x = g*v1.x + f1.x; v1.y = g*v1.y + f1.y;
                }
                *(float2*)(C + (size_t)m*ldc + n)     = v0;
                *(float2*)(C + (size_t)(m+8)*ldc + n) = v1;
            }
        }
    }
}

// ---------------- depthwise causal conv (width 4) + bias + SiLU, 4 rows/thread ----------------
__global__ void conv_silu_kernel(const float* __restrict__ cw, const float* __restrict__ cb)
{
    int ch = blockIdx.x * 256 + threadIdx.x;        // 0..DXBC-1 (DXBC = 7*256)
    int r0 = blockIdx.y * 4;
    int l0 = r0 % SEQL;
    float w0 = cw[ch*4+0], w1 = cw[ch*4+1], w2 = cw[ch*4+2], w3 = cw[ch*4+3];
    float bias = cb[ch];
    float v[7];
    #pragma unroll
    for (int t = 0; t < 7; ++t) {
        int lr = l0 + t - 3;
        v[t] = (lr >= 0) ? g_zx[(size_t)(r0 + t - 3) * DPROJ + DIN + ch] : 0.f;
    }
    #pragma unroll
    for (int j = 0; j < 4; ++j) {
        float acc = bias + w0*v[j] + w1*v[j+1] + w2*v[j+2] + w3*v[j+3];
        g_xbc[(size_t)(r0 + j) * DXBC + ch] = acc / (1.f + __expf(-acc));
    }
}

// ---------------- dt (softplus) + per-chunk inclusive cumsum of dt*A, fused ----------------
__global__ void acum_kernel(const float* __restrict__ A_log, const float* __restrict__ dt_bias)
{
    int h  = blockIdx.x % NH;
    int bc = blockIdx.x / NH;
    int l  = threadIdx.x;
    __shared__ float s[CHUNKQ];
    float Ah = -expf(A_log[h]);
    int row = bc * CHUNKQ + l;
    float v = g_zx[(size_t)row * DPROJ + (DIN + DXBC) + h] + dt_bias[h];
    float dt = (v > 20.f) ? v : log1pf(expf(v));
    g_dt[row * NH + h] = dt;
    s[l] = dt * Ah;
    __syncthreads();
    for (int off = 1; off < CHUNKQ; off <<= 1) {
        float t = (l >= off) ? s[l - off] : 0.f;
        __syncthreads();
        s[l] += t;
        __syncthreads();
    }
    g_acum[row * NH + h] = s[l];
    if (l == CHUNKQ - 1) g_alast[bc * NH + h] = s[l];
}

// ================= CB via mma.sync (split bf16): CB[l,s] = sum_n C[l,n]*B[s,n] =================
// smem: Chi [128][128]@0 (32K), Clo@32K, Bhi@64K, Blo@96K  (256B rows, SWZ256). fp32 out to g_cb.
#define CBM_SMEM_BYTES 131072
__global__ __launch_bounds__(256, 1) void cb_mma()
{
    char* sm = smbuf;
    const int bc  = blockIdx.x;
    const int tid = threadIdx.x;
    const int row0 = bc * CHUNKQ;

    for (int i = tid; i < 16384; i += 256) {
        int l = i >> 7, n = i & 127;
        const float* baseg = &g_xbc[(size_t)(row0 + l) * DXBC + DIN];
        uint32_t off = SWZ256(l*256 + n*2);
        split_store(sm,         sm + 32768, off, baseg[DSTATE + n]);  // C[l][n]
        split_store(sm + 65536, sm + 98304, off, baseg[n]);           // B[s=l][n]
    }
    __syncthreads();

    const int lane = tid & 31;
    const int wid  = tid >> 5;
    const int wm = wid >> 2;      // 0..1 -> l offset wm*64
    const int wn = wid & 3;       // 0..3 -> s offset wn*32
    const uint32_t base = smem_u32(sm);
    float acc[4][4][4] = {};
    const uint32_t AO[3] = {0u, 0u, 32768u};
    const uint32_t BO[3] = {65536u, 98304u, 65536u};
    #pragma unroll
    for (int pp = 0; pp < 3; ++pp) {
        const uint32_t ab = base + AO[pp], bb = base + BO[pp];
        #pragma unroll
        for (int ks = 0; ks < 8; ++ks) {
            uint32_t a_r[4][4], b_r[2][4];
            const int ra = wm*64 + ((lane>>3)&1)*8 + (lane&7);
            const int ca = ks*32 + ((lane>>4)&1)*16;
            #pragma unroll
            for (int mf = 0; mf < 4; ++mf)
                ldsm4(a_r[mf], ab + SWZ256((ra + mf*16)*256 + ca));
            const int rb = wn*32 + ((lane>>4)&1)*8 + (lane&7);
            const int cb2 = ks*32 + ((lane>>3)&1)*16;
            #pragma unroll
            for (int nf2 = 0; nf2 < 2; ++nf2)
                ldsm4(b_r[nf2], bb + SWZ256((rb + nf2*16)*256 + cb2));
            #pragma unroll
            for (int mf = 0; mf < 4; ++mf)
                #pragma unroll
                for (int nf = 0; nf < 4; ++nf)
                    mma16816(acc[mf][nf], a_r[mf], &b_r[nf>>1][(nf&1)*2], acc[mf][nf]);
        }
    }
    float* outb = &g_cb[(size_t)bc * CHUNKQ * CHUNKQ];
    const int mr = lane >> 2;
    const int nb = (lane & 3)*2;
    #pragma unroll
    for (int mf = 0; mf < 4; ++mf) {
        #pragma unroll
        for (int nf = 0; nf < 4; ++nf) {
            int l = wm*64 + mf*16 + mr;
            int s = wn*32 + nf*8 + nb;
            *(float2*)&outb[l*CHUNKQ + s]       = make_float2(acc[mf][nf][0], acc[mf][nf][1]);
            *(float2*)&outb[(l+8)*CHUNKQ + s]   = make_float2(acc[mf][nf][2], acc[mf][nf][3]);
        }
    }
}

// ================= states via mma.sync (split bf16) =================
#define STM_SMEM_BYTES 98304
__global__ __launch_bounds__(128, 2) void states_mma()
{
    char* sm = smbuf;
    __shared__ float wfac[128];
    const int h  = blockIdx.x % NH;
    const int bc = blockIdx.x / NH;
    const int tid = threadIdx.x;
    const int row0 = bc * CHUNKQ;

    if (tid < 128) {
        float alast = g_alast[bc*NH + h];
        wfac[tid] = g_dt[(row0+tid)*NH + h] * __expf(alast - g_acum[(row0+tid)*NH + h]);
    }
    __syncthreads();
    for (int i = tid; i < 8192; i += 128) {
        int l = i >> 6, p = i & 63;
        float v = g_xbc[(size_t)(row0+l)*DXBC + h*HD + p] * wfac[l];
        split_store(sm, sm + 16384, SWZ256(p*256 + l*2), v);
    }
    for (int i = tid; i < 16384; i += 128) {
        int l = i >> 7, n = i & 127;
        float v = g_xbc[(size_t)(row0+l)*DXBC + DIN + n];
        split_store(sm + 32768, sm + 65536, SWZ256(n*256 + l*2), v);
    }
    __syncthreads();

    const int lane = tid & 31;
    const int w = tid >> 5;
    const uint32_t base = smem_u32(sm);
    float acc[4][4][4] = {};
    const uint32_t AO[3] = {0u, 0u, 16384u};
    const uint32_t BO[3] = {32768u, 65536u, 32768u};
    #pragma unroll
    for (int pp = 0; pp < 3; ++pp) {
        const uint32_t ab = base + AO[pp], bb = base + BO[pp];
        #pragma unroll
        for (int ks = 0; ks < 8; ++ks) {
            uint32_t a_r[4][4], b_r[2][4];
            const int ra = ((lane>>3)&1)*8 + (lane&7);
            const int ca = ks*32 + ((lane>>4)&1)*16;
            #pragma unroll
            for (int mf = 0; mf < 4; ++mf)
                ldsm4(a_r[mf], ab + SWZ256((ra + mf*16)*256 + ca));
            const int rb = w*32 + ((lane>>4)&1)*8 + (lane&7);
            const int cb2 = ks*32 + ((lane>>3)&1)*16;
            #pragma unroll
            for (int nf2 = 0; nf2 < 2; ++nf2)
                ldsm4(b_r[nf2], bb + SWZ256((rb + nf2*16)*256 + cb2));
            #pragma unroll
            for (int mf = 0; mf < 4; ++mf)
                #pragma unroll
                for (int nf = 0; nf < 4; ++nf)
                    mma16816(acc[mf][nf], a_r[mf], &b_r[nf>>1][(nf&1)*2], acc[mf][nf]);
        }
    }
    float* outb = &g_states[((size_t)(bc*NH) + h) * HD * DSTATE];
    const int mr = lane >> 2;
    const int nb = w*32 + (lane & 3)*2;
    #pragma unroll
    for (int mf = 0; mf < 4; ++mf) {
        #pragma unroll
        for (int nf = 0; nf < 4; ++nf) {
            int p = mf*16 + mr, n = nb + nf*8;
            *(float2*)&outb[p*DSTATE + n]       = make_float2(acc[mf][nf][0], acc[mf][nf][1]);
            *(float2*)&outb[(p+8)*DSTATE + n]   = make_float2(acc[mf][nf][2], acc[mf][nf][3]);
        }
    }
}

// ---------------- inter-chunk state recurrence (one lane per thread) ----------------
__global__ void scan_kernel()
{
    int gl = blockIdx.x * blockDim.x + threadIdx.x;
    int bh = gl >> 13;
    int b = bh / NH, h = bh % NH;
    int e = gl & 8191;
    float S = 0.f;
    for (int c = 0; c < NCH; c++) {
        int bc = b*NCH + c;
        size_t base = ((size_t)(bc*NH) + h) * HD * DSTATE;
        float ed = __expf(g_alast[bc*NH + h]);
        float st = g_states[base + e];
        g_prev[base + e] = S;
        S = S*ed + st;
    }
}

// ================= Y via mma.sync (split bf16) =================
#define YM_SMEM_BYTES 98304
__device__ __forceinline__ void y_mma_block(float acc[2][4][4], uint32_t base,
                                            int lane, int wm, int wn)
{
    const uint32_t AO[3] = {0u, 0u, 32768u};
    const uint32_t BO[3] = {65536u, 81920u, 65536u};
    #pragma unroll
    for (int pp = 0; pp < 3; ++pp) {
        const uint32_t ab = base + AO[pp], bb = base + BO[pp];
        #pragma unroll
        for (int ks = 0; ks < 8; ++ks) {
            uint32_t a_r[2][4], b_r[2][4];
            const int ra = wm*32 + ((lane>>3)&1)*8 + (lane&7);
            const int ca = ks*32 + ((lane>>4)&1)*16;
            #pragma unroll
            for (int mf = 0; mf < 2; ++mf)
                ldsm4(a_r[mf], ab + SWZ256((ra + mf*16)*256 + ca));
            const int rb = wn*32 + ((lane>>4)&1)*8 + (lane&7);
            const int cb2 = ks*32 + ((lane>>3)&1)*16;
            #pragma unroll
            for (int nf2 = 0; nf2 < 2; ++nf2)
                ldsm4(b_r[nf2], bb + SWZ256((rb + nf2*16)*256 + cb2));
            #pragma unroll
            for (int mf = 0; mf < 2; ++mf)
                #pragma unroll
                for (int nf = 0; nf < 4; ++nf)
                    mma16816(acc[mf][nf], a_r[mf], &b_r[nf>>1][(nf&1)*2], acc[mf][nf]);
        }
    }
}

__global__ __launch_bounds__(256, 2) void y_mma(const float* __restrict__ Dv)
{
    char* sm = smbuf;
    __shared__ float acum_s[128], dt_s[128], eAl_s[128];
    const int h  = blockIdx.x % NH;
    const int bc = blockIdx.x / NH;
    const int tid = threadIdx.x;
    const int row0 = bc * CHUNKQ;

    if (tid < 128) {
        float a = g_acum[(row0+tid)*NH + h];
        acum_s[tid] = a;
        eAl_s[tid]  = __expf(a);
        dt_s[tid]   = g_dt[(row0+tid)*NH + h];
    }
    __syncthreads();

    for (int i = tid; i < 16384; i += 256) {
        int l = i >> 7, n = i & 127;
        float v = g_xbc[(size_t)(row0+l)*DXBC + DIN + DSTATE + n] * eAl_s[l];
        split_store(sm, sm + 32768, SWZ256(l*256 + n*2), v);
    }
    const size_t pbase = ((size_t)(bc*NH) + h) * HD * DSTATE;
    for (int i = tid; i < 8192; i += 256) {
        int p = i >> 7, n = i & 127;
        float v = g_prev[pbase + i];
        split_store(sm + 65536, sm + 81920, SWZ256(p*256 + n*2), v);
    }
    __syncthreads();

    const int lane = tid & 31;
    const int wid = tid >> 5;
    const int wm = wid >> 1;
    const int wn = wid & 1;
    const uint32_t base = smem_u32(sm);
    float acc[2][4][4] = {};
    y_mma_block(acc, base, lane, wm, wn);
    __syncthreads();

    for (int i = tid; i < 16384; i += 256) {
        int l = i >> 7, s = i & 127;
        float v = 0.f;
        if (s <= l)
            v = g_cb[(size_t)bc*CHUNKQ*CHUNKQ + i] * __expf(acum_s[l] - acum_s[s]) * dt_s[s];
        split_store(sm, sm + 32768, SWZ256(l*256 + s*2), v);
    }
    for (int i = tid; i < 8192; i += 256) {
        int l = i >> 6, p = i & 63;
        float v = g_xbc[(size_t)(row0+l)*DXBC + h*HD + p];
        split_store(sm + 65536, sm + 81920, SWZ256(p*256 + l*2), v);
    }
    __syncthreads();
    y_mma_block(acc, base, lane, wm, wn);

    const float dval = Dv[h];
    const int mr = lane >> 2;
    const int nb = (lane & 3)*2;
    #pragma unroll
    for (int mf = 0; mf < 2; ++mf) {
        #pragma unroll
        for (int nf = 0; nf < 4; ++nf) {
            int p = wn*32 + nf*8 + nb;
            #pragma unroll
            for (int rr = 0; rr < 2; ++rr) {
                int l = wm*32 + mf*16 + mr + rr*8;
                uint32_t o0 = SWZ256(p*256 + l*2);
                uint32_t o1 = SWZ256((p+1)*256 + l*2);
                float x0 = __bfloat162float(*(__nv_bfloat16*)(sm + 65536 + o0))
                         + __bfloat162float(*(__nv_bfloat16*)(sm + 81920 + o0));
                float x1 = __bfloat162float(*(__nv_bfloat16*)(sm + 65536 + o1))
                         + __bfloat162float(*(__nv_bfloat16*)(sm + 81920 + o1));
                float2 v = make_float2(acc[mf][nf][rr*2+0] + dval*x0,
                                       acc[mf][nf][rr*2+1] + dval*x1);
                *(float2*)&g_y[(size_t)(row0+l)*DIN + h*HD + p] = v;
            }
        }
    }
}

// ---------------- gating + RMSNorm + fused split_a for GEMM2 ----------------
__global__ void norm_split_kernel(const float* __restrict__ norm_w,
                                  __nv_bfloat16* __restrict__ O)
{
    __shared__ float tbuf[DIN];
    __shared__ float red[256];
    int row = blockIdx.x;
    int tid = threadIdx.x;
    float partial = 0.f;
    for (int i = tid; i < DIN; i += 256) {
        float yv = g_y[(size_t)row*DIN + i];
        float zv = g_zx[(size_t)row*DPROJ + i];
        float t  = yv * (zv / (1.f + __expf(-zv)));
        tbuf[i] = t;
        partial += t*t;
    }
    red[tid] = partial;
    __syncthreads();
    for (int s = 128; s > 0; s >>= 1) {
        if (tid < s) red[tid] += red[tid + s];
        __syncthreads();
    }
    float scale = rsqrtf(red[0] / (float)DIN + 1e-5f);
    __nv_bfloat16* ob = O + (size_t)row * KP2;
    for (int i = tid; i < DIN; i += 256) {
        float v = tbuf[i] * scale * norm_w[i];
        __nv_bfloat16 hi = __float2bfloat16(v);
        __nv_bfloat16 lo = __float2bfloat16(v - __bfloat162float(hi));
        ob[i] = hi; ob[DIN + i] = hi; ob[2*DIN + i] = lo;
    }
}

// ---------------- launch ----------------
extern "C" void kernel_launch(void* const* d_in, const int* in_sizes, int n_in,
                              void* d_out, int out_size)
{
    const float* feature = (const float*)d_in[0];
    const float* gate1   = (const float*)d_in[1];
    const float* in_w    = (const float*)d_in[2];
    const float* conv_w  = (const float*)d_in[3];
    const float* conv_b  = (const float*)d_in[4];
    const float* dt_bias = (const float*)d_in[5];
    const float* A_log   = (const float*)d_in[6];
    const float* Dv      = (const float*)d_in[7];
    const float* norm_w  = (const float*)d_in[8];
    const float* out_w   = (const float*)d_in[9];
    float* out = (float*)d_out;

    void* p_zx; cudaGetSymbolAddress(&p_zx, g_zx);
    void* p_a2; cudaGetSymbolAddress(&p_a2, g_a2);
    void* p_b2; cudaGetSymbolAddress(&p_b2, g_b2);
    __nv_bfloat16* a2 = (__nv_bfloat16*)p_a2;
    __nv_bfloat16* b2 = (__nv_bfloat16*)p_b2;

    cudaFuncSetAttribute(cb_mma,     cudaFuncAttributeMaxDynamicSharedMemorySize, CBM_SMEM_BYTES);
    cudaFuncSetAttribute(states_mma, cudaFuncAttributeMaxDynamicSharedMemorySize, STM_SMEM_BYTES);
    cudaFuncSetAttribute(y_mma,      cudaFuncAttributeMaxDynamicSharedMemorySize, YM_SMEM_BYTES);
    cudaFuncSetAttribute(gemm_mma,   cudaFuncAttributeMaxDynamicSharedMemorySize, GEMM_SMEM_BYTES);

    // 1. split conversion + GEMM1 (tensor cores, 2-stage)
    split_a_kernel<<<(NROWS*DMODEL + 255)/256, 256>>>(feature, a2, NROWS, DMODEL);
    split_b_kernel<<<(NPAD1*DMODEL + 255)/256, 256>>>(in_w, b2, DPROJ, NPAD1, DMODEL);
    gemm_mma<<<dim3(NPAD1/128, NROWS/128), 256, GEMM_SMEM_BYTES>>>(
        a2, b2, (float*)p_zx, KP1, DPROJ, DPROJ, nullptr, nullptr, 0);
    // 2. conv + silu (4 rows per thread)
    conv_silu_kernel<<<dim3(DXBC/256, NROWS/4), 256>>>(conv_w, conv_b);
    // 3. dt + per-chunk cumsum (fused)
    acum_kernel<<<NBC*NH, CHUNKQ>>>(A_log, dt_bias);
    // 4. CB per chunk (tensor cores, split bf16)
    cb_mma<<<NBC, 256, CBM_SMEM_BYTES>>>();
    // 5. chunk states (tensor cores, split bf16)
    states_mma<<<NBC*NH, 128, STM_SMEM_BYTES>>>();
    // 6. inter-chunk recurrence
    scan_kernel<<<(BSZ*NH*HD*DSTATE)/512, 512>>>();
    // 7. Y (tensor cores, split bf16)
    y_mma<<<NBC*NH, 256, YM_SMEM_BYTES>>>(Dv);
    // 8. gating + RMSNorm + split for GEMM2 (fused)
    norm_split_kernel<<<NROWS, 256>>>(norm_w, a2);
    // 9. split B + GEMM2 (tensor cores) + residual epilogue
    split_b_kernel<<<(DMODEL*DIN + 255)/256, 256>>>(out_w, b2, DMODEL, DMODEL, DIN);
    gemm_mma<<<dim3(DMODEL/128, NROWS/128), 256, GEMM_SMEM_BYTES>>>(
        a2, b2, out, KP2, DMODEL, DMODEL, feature, gate1, 1);
}

// round 12
// speedup vs baseline: 1.2340x; 1.1658x over previous
#include <cuda_runtime.h>
#include <cuda_bf16.h>
#include <cuda_fp16.h>
#include <math.h>
#include <stdint.h>

// ---------------- problem constants ----------------
#define BSZ     2
#define SEQL    4096
#define DMODEL  768
#define DSTATE  128
#define HD      64
#define DIN     1536
#define NH      24
#define DXBC    1792          // DIN + 2*DSTATE
#define DPROJ   3352          // 2*DIN + 2*DSTATE + NH
#define CHUNKQ  128
#define NCH     32            // SEQL / CHUNKQ
#define NROWS   (BSZ*SEQL)    // 8192
#define NBC     (BSZ*NCH)     // 64

#define KP1     (2*DMODEL)    // 1536 (fp16 2-term)
#define KP2     (2*DIN)       // 3072
#define NPAD1   3456          // 27*128

// single shared-memory extern symbol (consistent across all kernels)
extern __shared__ __align__(128) char smbuf[];

// ---------------- scratch (static device memory; no runtime allocs) ----------------
__device__ float g_zx[(size_t)NROWS*DPROJ];
__device__ float g_xbc[(size_t)NROWS*DXBC];
__device__ float g_dt[NROWS*NH];
__device__ float g_acum[NROWS*NH];
__device__ float g_alast[NBC*NH];
__device__ float g_cb[(size_t)NBC*CHUNKQ*CHUNKQ];
__device__ float g_states[(size_t)NBC*NH*HD*DSTATE];
__device__ float g_prev[(size_t)NBC*NH*HD*DSTATE];
__device__ float g_y[(size_t)NROWS*DIN];
__device__ __half g_a2[(size_t)NROWS*KP2];            // fp16 split A (max 8192*3072)
__device__ __half g_b2[(size_t)NPAD1*KP1];            // fp16 split B (3456*1536 > 768*3072)

// ================= helpers (family-target safe) =================
__device__ __forceinline__ uint32_t smem_u32(const void* p) {
    uint32_t a;
    asm("{ .reg .u64 t; cvta.to.shared.u64 t, %1; cvt.u32.u64 %0, t; }" : "=r"(a) : "l"(p));
    return a;
}
__device__ __forceinline__ void cpasync16(uint32_t dst, const void* src) {
    asm volatile("cp.async.cg.shared.global [%0], [%1], 16;" :: "r"(dst), "l"(src) : "memory");
}
__device__ __forceinline__ void ldsm4(uint32_t* r, uint32_t addr) {
    asm volatile("ldmatrix.sync.aligned.m8n8.x4.shared.b16 {%0,%1,%2,%3}, [%4];"
                 : "=r"(r[0]), "=r"(r[1]), "=r"(r[2]), "=r"(r[3]) : "r"(addr));
}
// bf16 mma (SSD kernels)
__device__ __forceinline__ void mma16816(float* d, const uint32_t* a, const uint32_t* b,
                                         const float* c) {
    asm volatile("mma.sync.aligned.m16n8k16.row.col.f32.bf16.bf16.f32 "
        "{%0,%1,%2,%3}, {%4,%5,%6,%7}, {%8,%9}, {%10,%11,%12,%13};"
        : "=f"(d[0]), "=f"(d[1]), "=f"(d[2]), "=f"(d[3])
        : "r"(a[0]), "r"(a[1]), "r"(a[2]), "r"(a[3]), "r"(b[0]), "r"(b[1]),
          "f"(c[0]), "f"(c[1]), "f"(c[2]), "f"(c[3]));
}
// fp16 mma (big GEMMs)
__device__ __forceinline__ void mma16816h(float* d, const uint32_t* a, const uint32_t* b,
                                          const float* c) {
    asm volatile("mma.sync.aligned.m16n8k16.row.col.f32.f16.f16.f32 "
        "{%0,%1,%2,%3}, {%4,%5,%6,%7}, {%8,%9}, {%10,%11,%12,%13};"
        : "=f"(d[0]), "=f"(d[1]), "=f"(d[2]), "=f"(d[3])
        : "r"(a[0]), "r"(a[1]), "r"(a[2]), "r"(a[3]), "r"(b[0]), "r"(b[1]),
          "f"(c[0]), "f"(c[1]), "f"(c[2]), "f"(c[3]));
}
#define SWZ128(x) ((x) ^ (((x) >> 3) & 0x70))
#define SWZ256(x) ((x) ^ (((x) >> 4) & 0x70))

__device__ __forceinline__ void split_store(char* hi_base, char* lo_base, uint32_t off, float v) {
    __nv_bfloat16 hi = __float2bfloat16(v);
    __nv_bfloat16 lo = __float2bfloat16(v - __bfloat162float(hi));
    *(__nv_bfloat16*)(hi_base + off) = hi;
    *(__nv_bfloat16*)(lo_base + off) = lo;
}

// ================= fp16 split conversions for big GEMMs =================
// A' per row: [0:K)=hi, [K:2K)=lo   (A represented to ~2^-22)
__global__ void split_a_kernel(const float* __restrict__ X, __half* __restrict__ O,
                               int M, int K)
{
    int idx = blockIdx.x * blockDim.x + threadIdx.x;
    if (idx >= M * K) return;
    int m = idx / K, k = idx % K;
    float x = X[idx];
    __half hi = __float2half(x);
    __half lo = __float2half(x - __half2float(hi));
    size_t base = (size_t)m * 2 * K;
    O[base + k] = hi; O[base + K + k] = lo;
}
// B' per row: [0:K)=hi, [K:2K)=hi   (single fp16 rounding; rows >= Nreal zeroed)
__global__ void split_b_kernel(const float* __restrict__ W, __half* __restrict__ O,
                               int Nreal, int Npad, int K)
{
    int idx = blockIdx.x * blockDim.x + threadIdx.x;
    if (idx >= Npad * K) return;
    int n = idx / K, k = idx % K;
    __half hi = __float2half(0.f);
    if (n < Nreal) hi = __float2half(W[(size_t)n * K + k]);
    size_t base = (size_t)n * 2 * K;
    O[base + k] = hi; O[base + K + k] = hi;
}

// ================= mma.sync fp16 GEMM (2-stage cp.async, verified skeleton) =================
#define GEMM_SMEM_BYTES (1024 + 2*32768)
__global__ __launch_bounds__(256, 2)
void gemm_mma(const __half* __restrict__ A2, const __half* __restrict__ B2,
              float* __restrict__ C, int KP, int Nreal, int ldc,
              const float* __restrict__ feat, const float* __restrict__ gate1, int ep)
{
    const uint32_t base = (smem_u32(smbuf) + 1023) & ~1023u;
    const int tid  = threadIdx.x;
    const int lane = tid & 31;
    const int wid  = tid >> 5;
    const int m0 = blockIdx.y * 128;
    const int n0 = blockIdx.x * 128;
    const int wm = wid >> 2;
    const int wn = wid & 3;

    const int frow = tid >> 3;
    const int u16  = tid & 7;
    const __half* ag = A2 + (size_t)(m0 + frow) * KP + u16 * 8;
    const __half* bg = B2 + (size_t)(n0 + frow) * KP + u16 * 8;

    float acc[4][4][4] = {};
    const int nch = KP >> 6;

    uint32_t foff[4];
    #pragma unroll
    for (int j = 0; j < 4; ++j)
        foff[j] = SWZ128((frow + j*32)*128 + u16*16);

    {
        uint32_t ab = base, bb = base + 16384;
        #pragma unroll
        for (int j = 0; j < 4; ++j) {
            cpasync16(ab + foff[j], ag + (size_t)(j*32)*KP);
            cpasync16(bb + foff[j], bg + (size_t)(j*32)*KP);
        }
        asm volatile("cp.async.commit_group;" ::: "memory");
    }

    for (int c = 0; c < nch; ++c) {
        if (c + 1 < nch) {
            uint32_t ab = base + ((c+1)&1) * 32768, bb = ab + 16384;
            const __half* a = ag + (c+1) * 64;
            const __half* b = bg + (c+1) * 64;
            #pragma unroll
            for (int j = 0; j < 4; ++j) {
                cpasync16(ab + foff[j], a + (size_t)(j*32)*KP);
                cpasync16(bb + foff[j], b + (size_t)(j*32)*KP);
            }
            asm volatile("cp.async.commit_group;" ::: "memory");
            asm volatile("cp.async.wait_group 1;" ::: "memory");
        } else {
            asm volatile("cp.async.wait_group 0;" ::: "memory");
        }
        __syncthreads();

        const uint32_t ab = base + (c&1) * 32768;
        const uint32_t bb = ab + 16384;
        #pragma unroll
        for (int ks = 0; ks < 4; ++ks) {
            uint32_t a_r[4][4];
            uint32_t b_r[2][4];
            {
                const int ra = wm*64 + ((lane>>3)&1)*8 + (lane&7);
                const int ka = ks*32 + ((lane>>4)&1)*16;
                #pragma unroll
                for (int mf = 0; mf < 4; ++mf)
                    ldsm4(a_r[mf], ab + SWZ128((ra + mf*16)*128 + ka));
            }
            {
                const int rb = wn*32 + ((lane>>4)&1)*8 + (lane&7);
                const int kb = ks*32 + ((lane>>3)&1)*16;
                #pragma unroll
                for (int nf2 = 0; nf2 < 2; ++nf2)
                    ldsm4(b_r[nf2], bb + SWZ128((rb + nf2*16)*128 + kb));
            }
            #pragma unroll
            for (int mf = 0; mf < 4; ++mf)
                #pragma unroll
                for (int nf = 0; nf < 4; ++nf)
                    mma16816h(acc[mf][nf], a_r[mf], &b_r[nf>>1][(nf&1)*2], acc[mf][nf]);
        }
        __syncthreads();
    }

    float g = 0.f;
    if (ep) g = 1.f / (1.f + expf(-gate1[0]));
    const int mrow = m0 + wm*64 + (lane >> 2);
    const int nbase = n0 + wn*32 + (lane & 3)*2;
    #pragma unroll
    for (int mf = 0; mf < 4; ++mf) {
        #pragma unroll
        for (int nf = 0; nf < 4; ++nf) {
            int m = mrow + mf*16;
            int n = nbase + nf*8;
            if (n < Nreal) {
                float2 v0 = make_float2(acc[mf][nf][0], acc[mf][nf][1]);
                float2 v1 = make_float2(acc[mf][nf][2], acc[mf][nf][3]);
                if (ep) {
                    float2 f0 = *(const float2*)(feat + (size_t)m*ldc + n);
                    float2 f1 = *(const float2*)(feat + (size_t)(m+8)*ldc + n);
                    v0.x = g*v0.x + f0.x; v0.y = g*v0.y + f0.y;
                    v1.x = g*v1.x + f1.x; v1.y = g*v1.y + f1.y;
                }
                *(float2*)(C + (size_t)m*ldc + n)     = v0;
                *(float2*)(C + (size_t)(m+8)*ldc + n) = v1;
            }
        }
    }
}

// ---------------- depthwise causal conv (width 4) + bias + SiLU, 4 rows/thread ----------------
__global__ void conv_silu_kernel(const float* __restrict__ cw, const float* __restrict__ cb)
{
    int ch = blockIdx.x * 256 + threadIdx.x;
    int r0 = blockIdx.y * 4;
    int l0 = r0 % SEQL;
    float w0 = cw[ch*4+0], w1 = cw[ch*4+1], w2 = cw[ch*4+2], w3 = cw[ch*4+3];
    float bias = cb[ch];
    float v[7];
    #pragma unroll
    for (int t = 0; t < 7; ++t) {
        int lr = l0 + t - 3;
        v[t] = (lr >= 0) ? g_zx[(size_t)(r0 + t - 3) * DPROJ + DIN + ch] : 0.f;
    }
    #pragma unroll
    for (int j = 0; j < 4; ++j) {
        float acc = bias + w0*v[j] + w1*v[j+1] + w2*v[j+2] + w3*v[j+3];
        g_xbc[(size_t)(r0 + j) * DXBC + ch] = acc / (1.f + __expf(-acc));
    }
}

// ---------------- dt (softplus) + per-chunk inclusive cumsum of dt*A, fused ----------------
__global__ void acum_kernel(const float* __restrict__ A_log, const float* __restrict__ dt_bias)
{
    int h  = blockIdx.x % NH;
    int bc = blockIdx.x / NH;
    int l  = threadIdx.x;
    __shared__ float s[CHUNKQ];
    float Ah = -expf(A_log[h]);
    int row = bc * CHUNKQ + l;
    float v = g_zx[(size_t)row * DPROJ + (DIN + DXBC) + h] + dt_bias[h];
    float dt = (v > 20.f) ? v : log1pf(expf(v));
    g_dt[row * NH + h] = dt;
    s[l] = dt * Ah;
    __syncthreads();
    for (int off = 1; off < CHUNKQ; off <<= 1) {
        float t = (l >= off) ? s[l - off] : 0.f;
        __syncthreads();
        s[l] += t;
        __syncthreads();
    }
    g_acum[row * NH + h] = s[l];
    if (l == CHUNKQ - 1) g_alast[bc * NH + h] = s[l];
}

// ================= CB via mma.sync (split bf16) =================
#define CBM_SMEM_BYTES 131072
__global__ __launch_bounds__(256, 1) void cb_mma()
{
    char* sm = smbuf;
    const int bc  = blockIdx.x;
    const int tid = threadIdx.x;
    const int row0 = bc * CHUNKQ;

    for (int i = tid; i < 16384; i += 256) {
        int l = i >> 7, n = i & 127;
        const float* baseg = &g_xbc[(size_t)(row0 + l) * DXBC + DIN];
        uint32_t off = SWZ256(l*256 + n*2);
        split_store(sm,         sm + 32768, off, baseg[DSTATE + n]);  // C[l][n]
        split_store(sm + 65536, sm + 98304, off, baseg[n]);           // B[s=l][n]
    }
    __syncthreads();

    const int lane = tid & 31;
    const int wid  = tid >> 5;
    const int wm = wid >> 2;
    const int wn = wid & 3;
    const uint32_t base = smem_u32(sm);
    float acc[4][4][4] = {};
    const uint32_t AO[3] = {0u, 0u, 32768u};
    const uint32_t BO[3] = {65536u, 98304u, 65536u};
    #pragma unroll
    for (int pp = 0; pp < 3; ++pp) {
        const uint32_t ab = base + AO[pp], bb = base + BO[pp];
        #pragma unroll
        for (int ks = 0; ks < 8; ++ks) {
            uint32_t a_r[4][4], b_r[2][4];
            const int ra = wm*64 + ((lane>>3)&1)*8 + (lane&7);
            const int ca = ks*32 + ((lane>>4)&1)*16;
            #pragma unroll
            for (int mf = 0; mf < 4; ++mf)
                ldsm4(a_r[mf], ab + SWZ256((ra + mf*16)*256 + ca));
            const int rb = wn*32 + ((lane>>4)&1)*8 + (lane&7);
            const int cb2 = ks*32 + ((lane>>3)&1)*16;
            #pragma unroll
            for (int nf2 = 0; nf2 < 2; ++nf2)
                ldsm4(b_r[nf2], bb + SWZ256((rb + nf2*16)*256 + cb2));
            #pragma unroll
            for (int mf = 0; mf < 4; ++mf)
                #pragma unroll
                for (int nf = 0; nf < 4; ++nf)
                    mma16816(acc[mf][nf], a_r[mf], &b_r[nf>>1][(nf&1)*2], acc[mf][nf]);
        }
    }
    float* outb = &g_cb[(size_t)bc * CHUNKQ * CHUNKQ];
    const int mr = lane >> 2;
    const int nb = (lane & 3)*2;
    #pragma unroll
    for (int mf = 0; mf < 4; ++mf) {
        #pragma unroll
        for (int nf = 0; nf < 4; ++nf) {
            int l = wm*64 + mf*16 + mr;
            int s = wn*32 + nf*8 + nb;
            *(float2*)&outb[l*CHUNKQ + s]       = make_float2(acc[mf][nf][0], acc[mf][nf][1]);
            *(float2*)&outb[(l+8)*CHUNKQ + s]   = make_float2(acc[mf][nf][2], acc[mf][nf][3]);
        }
    }
}

// ================= states via mma.sync (split bf16) =================
#define STM_SMEM_BYTES 98304
__global__ __launch_bounds__(128, 2) void states_mma()
{
    char* sm = smbuf;
    __shared__ float wfac[128];
    const int h  = blockIdx.x % NH;
    const int bc = blockIdx.x / NH;
    const int tid = threadIdx.x;
    const int row0 = bc * CHUNKQ;

    if (tid < 128) {
        float alast = g_alast[bc*NH + h];
        wfac[tid] = g_dt[(row0+tid)*NH + h] * __expf(alast - g_acum[(row0+tid)*NH + h]);
    }
    __syncthreads();
    for (int i = tid; i < 8192; i += 128) {
        int l = i >> 6, p = i & 63;
        float v = g_xbc[(size_t)(row0+l)*DXBC + h*HD + p] * wfac[l];
        split_store(sm, sm + 16384, SWZ256(p*256 + l*2), v);
    }
    for (int i = tid; i < 16384; i += 128) {
        int l = i >> 7, n = i & 127;
        float v = g_xbc[(size_t)(row0+l)*DXBC + DIN + n];
        split_store(sm + 32768, sm + 65536, SWZ256(n*256 + l*2), v);
    }
    __syncthreads();

    const int lane = tid & 31;
    const int w = tid >> 5;
    const uint32_t base = smem_u32(sm);
    float acc[4][4][4] = {};
    const uint32_t AO[3] = {0u, 0u, 16384u};
    const uint32_t BO[3] = {32768u, 65536u, 32768u};
    #pragma unroll
    for (int pp = 0; pp < 3; ++pp) {
        const uint32_t ab = base + AO[pp], bb = base + BO[pp];
        #pragma unroll
        for (int ks = 0; ks < 8; ++ks) {
            uint32_t a_r[4][4], b_r[2][4];
            const int ra = ((lane>>3)&1)*8 + (lane&7);
            const int ca = ks*32 + ((lane>>4)&1)*16;
            #pragma unroll
            for (int mf = 0; mf < 4; ++mf)
                ldsm4(a_r[mf], ab + SWZ256((ra + mf*16)*256 + ca));
            const int rb = w*32 + ((lane>>4)&1)*8 + (lane&7);
            const int cb2 = ks*32 + ((lane>>3)&1)*16;
            #pragma unroll
            for (int nf2 = 0; nf2 < 2; ++nf2)
                ldsm4(b_r[nf2], bb + SWZ256((rb + nf2*16)*256 + cb2));
            #pragma unroll
            for (int mf = 0; mf < 4; ++mf)
                #pragma unroll
                for (int nf = 0; nf < 4; ++nf)
                    mma16816(acc[mf][nf], a_r[mf], &b_r[nf>>1][(nf&1)*2], acc[mf][nf]);
        }
    }
    float* outb = &g_states[((size_t)(bc*NH) + h) * HD * DSTATE];
    const int mr = lane >> 2;
    const int nb = w*32 + (lane & 3)*2;
    #pragma unroll
    for (int mf = 0; mf < 4; ++mf) {
        #pragma unroll
        for (int nf = 0; nf < 4; ++nf) {
            int p = mf*16 + mr, n = nb + nf*8;
            *(float2*)&outb[p*DSTATE + n]       = make_float2(acc[mf][nf][0], acc[mf][nf][1]);
            *(float2*)&outb[(p+8)*DSTATE + n]   = make_float2(acc[mf][nf][2], acc[mf][nf][3]);
        }
    }
}

// ---------------- inter-chunk state recurrence (one lane per thread) ----------------
__global__ void scan_kernel()
{
    int gl = blockIdx.x * blockDim.x + threadIdx.x;
    int bh = gl >> 13;
    int b = bh / NH, h = bh % NH;
    int e = gl & 8191;
    float S = 0.f;
    for (int c = 0; c < NCH; c++) {
        int bc = b*NCH + c;
        size_t base = ((size_t)(bc*NH) + h) * HD * DSTATE;
        float ed = __expf(g_alast[bc*NH + h]);
        float st = g_states[base + e];
        g_prev[base + e] = S;
        S = S*ed + st;
    }
}

// ================= Y via mma.sync (split bf16) =================
#define YM_SMEM_BYTES 98304
__device__ __forceinline__ void y_mma_block(float acc[2][4][4], uint32_t base,
                                            int lane, int wm, int wn)
{
    const uint32_t AO[3] = {0u, 0u, 32768u};
    const uint32_t BO[3] = {65536u, 81920u, 65536u};
    #pragma unroll
    for (int pp = 0; pp < 3; ++pp) {
        const uint32_t ab = base + AO[pp], bb = base + BO[pp];
        #pragma unroll
        for (int ks = 0; ks < 8; ++ks) {
            uint32_t a_r[2][4], b_r[2][4];
            const int ra = wm*32 + ((lane>>3)&1)*8 + (lane&7);
            const int ca = ks*32 + ((lane>>4)&1)*16;
            #pragma unroll
            for (int mf = 0; mf < 2; ++mf)
                ldsm4(a_r[mf], ab + SWZ256((ra + mf*16)*256 + ca));
            const int rb = wn*32 + ((lane>>4)&1)*8 + (lane&7);
            const int cb2 = ks*32 + ((lane>>3)&1)*16;
            #pragma unroll
            for (int nf2 = 0; nf2 < 2; ++nf2)
                ldsm4(b_r[nf2], bb + SWZ256((rb + nf2*16)*256 + cb2));
            #pragma unroll
            for (int mf = 0; mf < 2; ++mf)
                #pragma unroll
                for (int nf = 0; nf < 4; ++nf)
                    mma16816(acc[mf][nf], a_r[mf], &b_r[nf>>1][(nf&1)*2], acc[mf][nf]);
        }
    }
}

__global__ __launch_bounds__(256, 2) void y_mma(const float* __restrict__ Dv)
{
    char* sm = smbuf;
    __shared__ float acum_s[128], dt_s[128], eAl_s[128];
    const int h  = blockIdx.x % NH;
    const int bc = blockIdx.x / NH;
    const int tid = threadIdx.x;
    const int row0 = bc * CHUNKQ;

    if (tid < 128) {
        float a = g_acum[(row0+tid)*NH + h];
        acum_s[tid] = a;
        eAl_s[tid]  = __expf(a);
        dt_s[tid]   = g_dt[(row0+tid)*NH + h];
    }
    __syncthreads();

    for (int i = tid; i < 16384; i += 256) {
        int l = i >> 7, n = i & 127;
        float v = g_xbc[(size_t)(row0+l)*DXBC + DIN + DSTATE + n] * eAl_s[l];
        split_store(sm, sm + 32768, SWZ256(l*256 + n*2), v);
    }
    const size_t pbase = ((size_t)(bc*NH) + h) * HD * DSTATE;
    for (int i = tid; i < 8192; i += 256) {
        int p = i >> 7, n = i & 127;
        float v = g_prev[pbase + i];
        split_store(sm + 65536, sm + 81920, SWZ256(p*256 + n*2), v);
    }
    __syncthreads();

    const int lane = tid & 31;
    const int wid = tid >> 5;
    const int wm = wid >> 1;
    const int wn = wid & 1;
    const uint32_t base = smem_u32(sm);
    float acc[2][4][4] = {};
    y_mma_block(acc, base, lane, wm, wn);
    __syncthreads();

    for (int i = tid; i < 16384; i += 256) {
        int l = i >> 7, s = i & 127;
        float v = 0.f;
        if (s <= l)
            v = g_cb[(size_t)bc*CHUNKQ*CHUNKQ + i] * __expf(acum_s[l] - acum_s[s]) * dt_s[s];
        split_store(sm, sm + 32768, SWZ256(l*256 + s*2), v);
    }
    for (int i = tid; i < 8192; i += 256) {
        int l = i >> 6, p = i & 63;
        float v = g_xbc[(size_t)(row0+l)*DXBC + h*HD + p];
        split_store(sm + 65536, sm + 81920, SWZ256(p*256 + l*2), v);
    }
    __syncthreads();
    y_mma_block(acc, base, lane, wm, wn);

    const float dval = Dv[h];
    const int mr = lane >> 2;
    const int nb = (lane & 3)*2;
    #pragma unroll
    for (int mf = 0; mf < 2; ++mf) {
        #pragma unroll
        for (int nf = 0; nf < 4; ++nf) {
            int p = wn*32 + nf*8 + nb;
            #pragma unroll
            for (int rr = 0; rr < 2; ++rr) {
                int l = wm*32 + mf*16 + mr + rr*8;
                uint32_t o0 = SWZ256(p*256 + l*2);
                uint32_t o1 = SWZ256((p+1)*256 + l*2);
                float x0 = __bfloat162float(*(__nv_bfloat16*)(sm + 65536 + o0))
                         + __bfloat162float(*(__nv_bfloat16*)(sm + 81920 + o0));
                float x1 = __bfloat162float(*(__nv_bfloat16*)(sm + 65536 + o1))
                         + __bfloat162float(*(__nv_bfloat16*)(sm + 81920 + o1));
                float2 v = make_float2(acc[mf][nf][rr*2+0] + dval*x0,
                                       acc[mf][nf][rr*2+1] + dval*x1);
                *(float2*)&g_y[(size_t)(row0+l)*DIN + h*HD + p] = v;
            }
        }
    }
}

// ---------------- gating + RMSNorm + fused fp16 split_a for GEMM2 ----------------
__global__ void norm_split_kernel(const float* __restrict__ norm_w,
                                  __half* __restrict__ O)
{
    __shared__ float tbuf[DIN];
    __shared__ float red[256];
    int row = blockIdx.x;
    int tid = threadIdx.x;
    float partial = 0.f;
    for (int i = tid; i < DIN; i += 256) {
        float yv = g_y[(size_t)row*DIN + i];
        float zv = g_zx[(size_t)row*DPROJ + i];
        float t  = yv * (zv / (1.f + __expf(-zv)));
        tbuf[i] = t;
        partial += t*t;
    }
    red[tid] = partial;
    __syncthreads();
    for (int s = 128; s > 0; s >>= 1) {
        if (tid < s) red[tid] += red[tid + s];
        __syncthreads();
    }
    float scale = rsqrtf(red[0] / (float)DIN + 1e-5f);
    __half* ob = O + (size_t)row * KP2;
    for (int i = tid; i < DIN; i += 256) {
        float v = tbuf[i] * scale * norm_w[i];
        __half hi = __float2half(v);
        __half lo = __float2half(v - __half2float(hi));
        ob[i] = hi; ob[DIN + i] = lo;
    }
}

// ---------------- launch ----------------
extern "C" void kernel_launch(void* const* d_in, const int* in_sizes, int n_in,
                              void* d_out, int out_size)
{
    const float* feature = (const float*)d_in[0];
    const float* gate1   = (const float*)d_in[1];
    const float* in_w    = (const float*)d_in[2];
    const float* conv_w  = (const float*)d_in[3];
    const float* conv_b  = (const float*)d_in[4];
    const float* dt_bias = (const float*)d_in[5];
    const float* A_log   = (const float*)d_in[6];
    const float* Dv      = (const float*)d_in[7];
    const float* norm_w  = (const float*)d_in[8];
    const float* out_w   = (const float*)d_in[9];
    float* out = (float*)d_out;

    void* p_zx; cudaGetSymbolAddress(&p_zx, g_zx);
    void* p_a2; cudaGetSymbolAddress(&p_a2, g_a2);
    void* p_b2; cudaGetSymbolAddress(&p_b2, g_b2);
    __half* a2 = (__half*)p_a2;
    __half* b2 = (__half*)p_b2;

    cudaFuncSetAttribute(cb_mma,     cudaFuncAttributeMaxDynamicSharedMemorySize, CBM_SMEM_BYTES);
    cudaFuncSetAttribute(states_mma, cudaFuncAttributeMaxDynamicSharedMemorySize, STM_SMEM_BYTES);
    cudaFuncSetAttribute(y_mma,      cudaFuncAttributeMaxDynamicSharedMemorySize, YM_SMEM_BYTES);
    cudaFuncSetAttribute(gemm_mma,   cudaFuncAttributeMaxDynamicSharedMemorySize, GEMM_SMEM_BYTES);

    // 1. fp16 split conversion + GEMM1 (tensor cores, 2-stage)
    split_a_kernel<<<(NROWS*DMODEL + 255)/256, 256>>>(feature, a2, NROWS, DMODEL);
    split_b_kernel<<<(NPAD1*DMODEL + 255)/256, 256>>>(in_w, b2, DPROJ, NPAD1, DMODEL);
    gemm_mma<<<dim3(NPAD1/128, NROWS/128), 256, GEMM_SMEM_BYTES>>>(
        a2, b2, (float*)p_zx, KP1, DPROJ, DPROJ, nullptr, nullptr, 0);
    // 2. conv + silu (4 rows per thread)
    conv_silu_kernel<<<dim3(DXBC/256, NROWS/4), 256>>>(conv_w, conv_b);
    // 3. dt + per-chunk cumsum (fused)
    acum_kernel<<<NBC*NH, CHUNKQ>>>(A_log, dt_bias);
    // 4. CB per chunk (tensor cores, split bf16)
    cb_mma<<<NBC, 256, CBM_SMEM_BYTES>>>();
    // 5. chunk states (tensor cores, split bf16)
    states_mma<<<NBC*NH, 128, STM_SMEM_BYTES>>>();
    // 6. inter-chunk recurrence
    scan_kernel<<<(BSZ*NH*HD*DSTATE)/512, 512>>>();
    // 7. Y (tensor cores, split bf16)
    y_mma<<<NBC*NH, 256, YM_SMEM_BYTES>>>(Dv);
    // 8. gating + RMSNorm + fp16 split for GEMM2 (fused)
    norm_split_kernel<<<NROWS, 256>>>(norm_w, a2);
    // 9. fp16 split B + GEMM2 (tensor cores) + residual epilogue
    split_b_kernel<<<(DMODEL*DIN + 255)/256, 256>>>(out_w, b2, DMODEL, DMODEL, DIN);
    gemm_mma<<<dim3(DMODEL/128, NROWS/128), 256, GEMM_SMEM_BYTES>>>(
        a2, b2, out, KP2, DMODEL, DMODEL, feature, gate1, 1);
}

// round 13
// speedup vs baseline: 1.3458x; 1.0906x over previous
#include <cuda_runtime.h>
#include <cuda_bf16.h>
#include <cuda_fp16.h>
#include <math.h>
#include <stdint.h>

// ---------------- problem constants ----------------
#define BSZ     2
#define SEQL    4096
#define DMODEL  768
#define DSTATE  128
#define HD      64
#define DIN     1536
#define NH      24
#define DXBC    1792          // DIN + 2*DSTATE
#define DPROJ   3352          // 2*DIN + 2*DSTATE + NH
#define CHUNKQ  128
#define NCH     32            // SEQL / CHUNKQ
#define NROWS   (BSZ*SEQL)    // 8192
#define NBC     (BSZ*NCH)     // 64

#define KP1     (2*DMODEL)    // 1536 (fp16 2-term)
#define KP2     (2*DIN)       // 3072
#define NPAD1   3456          // 27*128

// single shared-memory extern symbol (consistent across all kernels)
extern __shared__ __align__(128) char smbuf[];

// ---------------- scratch (static device memory; no runtime allocs) ----------------
__device__ float g_zx[(size_t)NROWS*DPROJ];
__device__ float g_xbc[(size_t)NROWS*DXBC];
__device__ float g_dt[NROWS*NH];
__device__ float g_acum[NROWS*NH];
__device__ float g_alast[NBC*NH];
__device__ float g_cb[(size_t)NBC*CHUNKQ*CHUNKQ];
__device__ float g_states[(size_t)NBC*NH*HD*DSTATE];
__device__ float g_prev[(size_t)NBC*NH*HD*DSTATE];
__device__ float g_y[(size_t)NROWS*DIN];
__device__ __half g_a2[(size_t)NROWS*KP2];            // fp16 split A
__device__ __half g_b2[(size_t)NPAD1*KP1];            // fp16 split B

// ================= helpers (family-target safe) =================
__device__ __forceinline__ uint32_t smem_u32(const void* p) {
    uint32_t a;
    asm("{ .reg .u64 t; cvta.to.shared.u64 t, %1; cvt.u32.u64 %0, t; }" : "=r"(a) : "l"(p));
    return a;
}
__device__ __forceinline__ void cpasync16(uint32_t dst, const void* src) {
    asm volatile("cp.async.cg.shared.global [%0], [%1], 16;" :: "r"(dst), "l"(src) : "memory");
}
__device__ __forceinline__ void ldsm4(uint32_t* r, uint32_t addr) {
    asm volatile("ldmatrix.sync.aligned.m8n8.x4.shared.b16 {%0,%1,%2,%3}, [%4];"
                 : "=r"(r[0]), "=r"(r[1]), "=r"(r[2]), "=r"(r[3]) : "r"(addr));
}
// fp16 mma (all tensor-core kernels)
__device__ __forceinline__ void mma16816h(float* d, const uint32_t* a, const uint32_t* b,
                                          const float* c) {
    asm volatile("mma.sync.aligned.m16n8k16.row.col.f32.f16.f16.f32 "
        "{%0,%1,%2,%3}, {%4,%5,%6,%7}, {%8,%9}, {%10,%11,%12,%13};"
        : "=f"(d[0]), "=f"(d[1]), "=f"(d[2]), "=f"(d[3])
        : "r"(a[0]), "r"(a[1]), "r"(a[2]), "r"(a[3]), "r"(b[0]), "r"(b[1]),
          "f"(c[0]), "f"(c[1]), "f"(c[2]), "f"(c[3]));
}
#define SWZ128(x) ((x) ^ (((x) >> 3) & 0x70))
#define SWZ256(x) ((x) ^ (((x) >> 4) & 0x70))

// fp16 hi+lo split store (A-side, exact to ~2^-22)
__device__ __forceinline__ void split_store_h(char* hi_base, char* lo_base, uint32_t off, float v) {
    __half hi = __float2half(v);
    __half lo = __float2half(v - __half2float(hi));
    *(__half*)(hi_base + off) = hi;
    *(__half*)(lo_base + off) = lo;
}
// fp16 single store (B-side, one rounding)
__device__ __forceinline__ void store_h(char* base, uint32_t off, float v) {
    *(__half*)(base + off) = __float2half(v);
}

// ================= fp16 split conversions for big GEMMs =================
__global__ void split_a_kernel(const float* __restrict__ X, __half* __restrict__ O,
                               int M, int K)
{
    int idx = blockIdx.x * blockDim.x + threadIdx.x;
    if (idx >= M * K) return;
    int m = idx / K, k = idx % K;
    float x = X[idx];
    __half hi = __float2half(x);
    __half lo = __float2half(x - __half2float(hi));
    size_t base = (size_t)m * 2 * K;
    O[base + k] = hi; O[base + K + k] = lo;
}
__global__ void split_b_kernel(const float* __restrict__ W, __half* __restrict__ O,
                               int Nreal, int Npad, int K)
{
    int idx = blockIdx.x * blockDim.x + threadIdx.x;
    if (idx >= Npad * K) return;
    int n = idx / K, k = idx % K;
    __half hi = __float2half(0.f);
    if (n < Nreal) hi = __float2half(W[(size_t)n * K + k]);
    size_t base = (size_t)n * 2 * K;
    O[base + k] = hi; O[base + K + k] = hi;
}

// ================= mma.sync fp16 GEMM (2-stage cp.async, verified R12) =================
#define GEMM_SMEM_BYTES (1024 + 2*32768)
__global__ __launch_bounds__(256, 2)
void gemm_mma(const __half* __restrict__ A2, const __half* __restrict__ B2,
              float* __restrict__ C, int KP, int Nreal, int ldc,
              const float* __restrict__ feat, const float* __restrict__ gate1, int ep)
{
    const uint32_t base = (smem_u32(smbuf) + 1023) & ~1023u;
    const int tid  = threadIdx.x;
    const int lane = tid & 31;
    const int wid  = tid >> 5;
    const int m0 = blockIdx.y * 128;
    const int n0 = blockIdx.x * 128;
    const int wm = wid >> 2;
    const int wn = wid & 3;

    const int frow = tid >> 3;
    const int u16  = tid & 7;
    const __half* ag = A2 + (size_t)(m0 + frow) * KP + u16 * 8;
    const __half* bg = B2 + (size_t)(n0 + frow) * KP + u16 * 8;

    float acc[4][4][4] = {};
    const int nch = KP >> 6;

    uint32_t foff[4];
    #pragma unroll
    for (int j = 0; j < 4; ++j)
        foff[j] = SWZ128((frow + j*32)*128 + u16*16);

    {
        uint32_t ab = base, bb = base + 16384;
        #pragma unroll
        for (int j = 0; j < 4; ++j) {
            cpasync16(ab + foff[j], ag + (size_t)(j*32)*KP);
            cpasync16(bb + foff[j], bg + (size_t)(j*32)*KP);
        }
        asm volatile("cp.async.commit_group;" ::: "memory");
    }

    for (int c = 0; c < nch; ++c) {
        if (c + 1 < nch) {
            uint32_t ab = base + ((c+1)&1) * 32768, bb = ab + 16384;
            const __half* a = ag + (c+1) * 64;
            const __half* b = bg + (c+1) * 64;
            #pragma unroll
            for (int j = 0; j < 4; ++j) {
                cpasync16(ab + foff[j], a + (size_t)(j*32)*KP);
                cpasync16(bb + foff[j], b + (size_t)(j*32)*KP);
            }
            asm volatile("cp.async.commit_group;" ::: "memory");
            asm volatile("cp.async.wait_group 1;" ::: "memory");
        } else {
            asm volatile("cp.async.wait_group 0;" ::: "memory");
        }
        __syncthreads();

        const uint32_t ab = base + (c&1) * 32768;
        const uint32_t bb = ab + 16384;
        #pragma unroll
        for (int ks = 0; ks < 4; ++ks) {
            uint32_t a_r[4][4];
            uint32_t b_r[2][4];
            {
                const int ra = wm*64 + ((lane>>3)&1)*8 + (lane&7);
                const int ka = ks*32 + ((lane>>4)&1)*16;
                #pragma unroll
                for (int mf = 0; mf < 4; ++mf)
                    ldsm4(a_r[mf], ab + SWZ128((ra + mf*16)*128 + ka));
            }
            {
                const int rb = wn*32 + ((lane>>4)&1)*8 + (lane&7);
                const int kb = ks*32 + ((lane>>3)&1)*16;
                #pragma unroll
                for (int nf2 = 0; nf2 < 2; ++nf2)
                    ldsm4(b_r[nf2], bb + SWZ128((rb + nf2*16)*128 + kb));
            }
            #pragma unroll
            for (int mf = 0; mf < 4; ++mf)
                #pragma unroll
                for (int nf = 0; nf < 4; ++nf)
                    mma16816h(acc[mf][nf], a_r[mf], &b_r[nf>>1][(nf&1)*2], acc[mf][nf]);
        }
        __syncthreads();
    }

    float g = 0.f;
    if (ep) g = 1.f / (1.f + expf(-gate1[0]));
    const int mrow = m0 + wm*64 + (lane >> 2);
    const int nbase = n0 + wn*32 + (lane & 3)*2;
    #pragma unroll
    for (int mf = 0; mf < 4; ++mf) {
        #pragma unroll
        for (int nf = 0; nf < 4; ++nf) {
            int m = mrow + mf*16;
            int n = nbase + nf*8;
            if (n < Nreal) {
                float2 v0 = make_float2(acc[mf][nf][0], acc[mf][nf][1]);
                float2 v1 = make_float2(acc[mf][nf][2], acc[mf][nf][3]);
                if (ep) {
                    float2 f0 = *(const float2*)(feat + (size_t)m*ldc + n);
                    float2 f1 = *(const float2*)(feat + (size_t)(m+8)*ldc + n);
                    v0.x = g*v0.x + f0.x; v0.y = g*v0.y + f0.y;
                    v1.x = g*v1.x + f1.x; v1.y = g*v1.y + f1.y;
                }
                *(float2*)(C + (size_t)m*ldc + n)     = v0;
                *(float2*)(C + (size_t)(m+8)*ldc + n) = v1;
            }
        }
    }
}

// ---------------- depthwise causal conv (width 4) + bias + SiLU, 4 rows/thread ----------------
__global__ void conv_silu_kernel(const float* __restrict__ cw, const float* __restrict__ cb)
{
    int ch = blockIdx.x * 256 + threadIdx.x;
    int r0 = blockIdx.y * 4;
    int l0 = r0 % SEQL;
    float w0 = cw[ch*4+0], w1 = cw[ch*4+1], w2 = cw[ch*4+2], w3 = cw[ch*4+3];
    float bias = cb[ch];
    float v[7];
    #pragma unroll
    for (int t = 0; t < 7; ++t) {
        int lr = l0 + t - 3;
        v[t] = (lr >= 0) ? g_zx[(size_t)(r0 + t - 3) * DPROJ + DIN + ch] : 0.f;
    }
    #pragma unroll
    for (int j = 0; j < 4; ++j) {
        float acc = bias + w0*v[j] + w1*v[j+1] + w2*v[j+2] + w3*v[j+3];
        g_xbc[(size_t)(r0 + j) * DXBC + ch] = acc / (1.f + __expf(-acc));
    }
}

// ---------------- dt (softplus) + per-chunk inclusive cumsum of dt*A, fused ----------------
__global__ void acum_kernel(const float* __restrict__ A_log, const float* __restrict__ dt_bias)
{
    int h  = blockIdx.x % NH;
    int bc = blockIdx.x / NH;
    int l  = threadIdx.x;
    __shared__ float s[CHUNKQ];
    float Ah = -expf(A_log[h]);
    int row = bc * CHUNKQ + l;
    float v = g_zx[(size_t)row * DPROJ + (DIN + DXBC) + h] + dt_bias[h];
    float dt = (v > 20.f) ? v : log1pf(expf(v));
    g_dt[row * NH + h] = dt;
    s[l] = dt * Ah;
    __syncthreads();
    for (int off = 1; off < CHUNKQ; off <<= 1) {
        float t = (l >= off) ? s[l - off] : 0.f;
        __syncthreads();
        s[l] += t;
        __syncthreads();
    }
    g_acum[row * NH + h] = s[l];
    if (l == CHUNKQ - 1) g_alast[bc * NH + h] = s[l];
}

// ================= CB via mma.sync (fp16 2-term): CB[l,s] = sum_n C[l,n]*B[s,n] =================
// smem: Chi[128][128]@0 (32K), Clo@32K, Bhi@64K (32K). 2 passes: Chi*Bhi + Clo*Bhi.
#define CBM_SMEM_BYTES 98304
__global__ __launch_bounds__(256, 1) void cb_mma()
{
    char* sm = smbuf;
    const int bc  = blockIdx.x;
    const int tid = threadIdx.x;
    const int row0 = bc * CHUNKQ;

    for (int i = tid; i < 16384; i += 256) {
        int l = i >> 7, n = i & 127;
        const float* baseg = &g_xbc[(size_t)(row0 + l) * DXBC + DIN];
        uint32_t off = SWZ256(l*256 + n*2);
        split_store_h(sm, sm + 32768, off, baseg[DSTATE + n]);  // C[l][n] hi+lo
        store_h(sm + 65536, off, baseg[n]);                     // B[s=l][n] hi
    }
    __syncthreads();

    const int lane = tid & 31;
    const int wid  = tid >> 5;
    const int wm = wid >> 2;
    const int wn = wid & 3;
    const uint32_t base = smem_u32(sm);
    float acc[4][4][4] = {};
    const uint32_t AO[2] = {0u, 32768u};
    #pragma unroll
    for (int pp = 0; pp < 2; ++pp) {
        const uint32_t ab = base + AO[pp], bb = base + 65536u;
        #pragma unroll
        for (int ks = 0; ks < 8; ++ks) {
            uint32_t a_r[4][4], b_r[2][4];
            const int ra = wm*64 + ((lane>>3)&1)*8 + (lane&7);
            const int ca = ks*32 + ((lane>>4)&1)*16;
            #pragma unroll
            for (int mf = 0; mf < 4; ++mf)
                ldsm4(a_r[mf], ab + SWZ256((ra + mf*16)*256 + ca));
            const int rb = wn*32 + ((lane>>4)&1)*8 + (lane&7);
            const int cb2 = ks*32 + ((lane>>3)&1)*16;
            #pragma unroll
            for (int nf2 = 0; nf2 < 2; ++nf2)
                ldsm4(b_r[nf2], bb + SWZ256((rb + nf2*16)*256 + cb2));
            #pragma unroll
            for (int mf = 0; mf < 4; ++mf)
                #pragma unroll
                for (int nf = 0; nf < 4; ++nf)
                    mma16816h(acc[mf][nf], a_r[mf], &b_r[nf>>1][(nf&1)*2], acc[mf][nf]);
        }
    }
    float* outb = &g_cb[(size_t)bc * CHUNKQ * CHUNKQ];
    const int mr = lane >> 2;
    const int nb = (lane & 3)*2;
    #pragma unroll
    for (int mf = 0; mf < 4; ++mf) {
        #pragma unroll
        for (int nf = 0; nf < 4; ++nf) {
            int l = wm*64 + mf*16 + mr;
            int s = wn*32 + nf*8 + nb;
            *(float2*)&outb[l*CHUNKQ + s]       = make_float2(acc[mf][nf][0], acc[mf][nf][1]);
            *(float2*)&outb[(l+8)*CHUNKQ + s]   = make_float2(acc[mf][nf][2], acc[mf][nf][3]);
        }
    }
}

// ================= states via mma.sync (fp16 2-term) =================
// smem: Ahi[64][128]@0 (16K), Alo@16K, Bhi[128][128]@32K (32K). 2 passes.
#define STM_SMEM_BYTES 65536
__global__ __launch_bounds__(128, 2) void states_mma()
{
    char* sm = smbuf;
    __shared__ float wfac[128];
    const int h  = blockIdx.x % NH;
    const int bc = blockIdx.x / NH;
    const int tid = threadIdx.x;
    const int row0 = bc * CHUNKQ;

    if (tid < 128) {
        float alast = g_alast[bc*NH + h];
        wfac[tid] = g_dt[(row0+tid)*NH + h] * __expf(alast - g_acum[(row0+tid)*NH + h]);
    }
    __syncthreads();
    for (int i = tid; i < 8192; i += 128) {
        int l = i >> 6, p = i & 63;
        float v = g_xbc[(size_t)(row0+l)*DXBC + h*HD + p] * wfac[l];
        split_store_h(sm, sm + 16384, SWZ256(p*256 + l*2), v);
    }
    for (int i = tid; i < 16384; i += 128) {
        int l = i >> 7, n = i & 127;
        store_h(sm + 32768, SWZ256(n*256 + l*2), g_xbc[(size_t)(row0+l)*DXBC + DIN + n]);
    }
    __syncthreads();

    const int lane = tid & 31;
    const int w = tid >> 5;
    const uint32_t base = smem_u32(sm);
    float acc[4][4][4] = {};
    const uint32_t AO[2] = {0u, 16384u};
    #pragma unroll
    for (int pp = 0; pp < 2; ++pp) {
        const uint32_t ab = base + AO[pp], bb = base + 32768u;
        #pragma unroll
        for (int ks = 0; ks < 8; ++ks) {
            uint32_t a_r[4][4], b_r[2][4];
            const int ra = ((lane>>3)&1)*8 + (lane&7);
            const int ca = ks*32 + ((lane>>4)&1)*16;
            #pragma unroll
            for (int mf = 0; mf < 4; ++mf)
                ldsm4(a_r[mf], ab + SWZ256((ra + mf*16)*256 + ca));
            const int rb = w*32 + ((lane>>4)&1)*8 + (lane&7);
            const int cb2 = ks*32 + ((lane>>3)&1)*16;
            #pragma unroll
            for (int nf2 = 0; nf2 < 2; ++nf2)
                ldsm4(b_r[nf2], bb + SWZ256((rb + nf2*16)*256 + cb2));
            #pragma unroll
            for (int mf = 0; mf < 4; ++mf)
                #pragma unroll
                for (int nf = 0; nf < 4; ++nf)
                    mma16816h(acc[mf][nf], a_r[mf], &b_r[nf>>1][(nf&1)*2], acc[mf][nf]);
        }
    }
    float* outb = &g_states[((size_t)(bc*NH) + h) * HD * DSTATE];
    const int mr = lane >> 2;
    const int nb = w*32 + (lane & 3)*2;
    #pragma unroll
    for (int mf = 0; mf < 4; ++mf) {
        #pragma unroll
        for (int nf = 0; nf < 4; ++nf) {
            int p = mf*16 + mr, n = nb + nf*8;
            *(float2*)&outb[p*DSTATE + n]       = make_float2(acc[mf][nf][0], acc[mf][nf][1]);
            *(float2*)&outb[(p+8)*DSTATE + n]   = make_float2(acc[mf][nf][2], acc[mf][nf][3]);
        }
    }
}

// ---------------- inter-chunk state recurrence (one lane per thread) ----------------
__global__ void scan_kernel()
{
    int gl = blockIdx.x * blockDim.x + threadIdx.x;
    int bh = gl >> 13;
    int b = bh / NH, h = bh % NH;
    int e = gl & 8191;
    float S = 0.f;
    for (int c = 0; c < NCH; c++) {
        int bc = b*NCH + c;
        size_t base = ((size_t)(bc*NH) + h) * HD * DSTATE;
        float ed = __expf(g_alast[bc*NH + h]);
        float st = g_states[base + e];
        g_prev[base + e] = S;
        S = S*ed + st;
    }
}

// ================= Y via mma.sync (fp16 2-term) =================
// smem: Ahi[128][128]@0 (32K), Alo@32K, Bhi[64][128]@64K (16K). 2 passes per block.
#define YM_SMEM_BYTES 81920
__device__ __forceinline__ void y_mma_block(float acc[2][4][4], uint32_t base,
                                            int lane, int wm, int wn)
{
    const uint32_t AO[2] = {0u, 32768u};
    #pragma unroll
    for (int pp = 0; pp < 2; ++pp) {
        const uint32_t ab = base + AO[pp], bb = base + 65536u;
        #pragma unroll
        for (int ks = 0; ks < 8; ++ks) {
            uint32_t a_r[2][4], b_r[2][4];
            const int ra = wm*32 + ((lane>>3)&1)*8 + (lane&7);
            const int ca = ks*32 + ((lane>>4)&1)*16;
            #pragma unroll
            for (int mf = 0; mf < 2; ++mf)
                ldsm4(a_r[mf], ab + SWZ256((ra + mf*16)*256 + ca));
            const int rb = wn*32 + ((lane>>4)&1)*8 + (lane&7);
            const int cb2 = ks*32 + ((lane>>3)&1)*16;
            #pragma unroll
            for (int nf2 = 0; nf2 < 2; ++nf2)
                ldsm4(b_r[nf2], bb + SWZ256((rb + nf2*16)*256 + cb2));
            #pragma unroll
            for (int mf = 0; mf < 2; ++mf)
                #pragma unroll
                for (int nf = 0; nf < 4; ++nf)
                    mma16816h(acc[mf][nf], a_r[mf], &b_r[nf>>1][(nf&1)*2], acc[mf][nf]);
        }
    }
}

__global__ __launch_bounds__(256, 2) void y_mma(const float* __restrict__ Dv)
{
    char* sm = smbuf;
    __shared__ float acum_s[128], dt_s[128], eAl_s[128];
    const int h  = blockIdx.x % NH;
    const int bc = blockIdx.x / NH;
    const int tid = threadIdx.x;
    const int row0 = bc * CHUNKQ;

    if (tid < 128) {
        float a = g_acum[(row0+tid)*NH + h];
        acum_s[tid] = a;
        eAl_s[tid]  = __expf(a);
        dt_s[tid]   = g_dt[(row0+tid)*NH + h];
    }
    __syncthreads();

    // ---- pass 1 tiles: A = C*exp(acum[l]) [l][n] hi+lo, B = prev [p][n] hi
    for (int i = tid; i < 16384; i += 256) {
        int l = i >> 7, n = i & 127;
        float v = g_xbc[(size_t)(row0+l)*DXBC + DIN + DSTATE + n] * eAl_s[l];
        split_store_h(sm, sm + 32768, SWZ256(l*256 + n*2), v);
    }
    const size_t pbase = ((size_t)(bc*NH) + h) * HD * DSTATE;
    for (int i = tid; i < 8192; i += 256) {
        int p = i >> 7, n = i & 127;
        store_h(sm + 65536, SWZ256(p*256 + n*2), g_prev[pbase + i]);
    }
    __syncthreads();

    const int lane = tid & 31;
    const int wid = tid >> 5;
    const int wm = wid >> 1;
    const int wn = wid & 1;
    const uint32_t base = smem_u32(sm);
    float acc[2][4][4] = {};
    y_mma_block(acc, base, lane, wm, wn);
    __syncthreads();

    // ---- pass 2 tiles: A = W [l][s] hi+lo, B = xT [p][s] hi
    for (int i = tid; i < 16384; i += 256) {
        int l = i >> 7, s = i & 127;
        float v = 0.f;
        if (s <= l)
            v = g_cb[(size_t)bc*CHUNKQ*CHUNKQ + i] * __expf(acum_s[l] - acum_s[s]) * dt_s[s];
        split_store_h(sm, sm + 32768, SWZ256(l*256 + s*2), v);
    }
    for (int i = tid; i < 8192; i += 256) {
        int l = i >> 6, p = i & 63;
        store_h(sm + 65536, SWZ256(p*256 + l*2), g_xbc[(size_t)(row0+l)*DXBC + h*HD + p]);
    }
    __syncthreads();
    y_mma_block(acc, base, lane, wm, wn);

    // ---- epilogue: + D*x (x from hi fp16 plane), write Y
    const float dval = Dv[h];
    const int mr = lane >> 2;
    const int nb = (lane & 3)*2;
    #pragma unroll
    for (int mf = 0; mf < 2; ++mf) {
        #pragma unroll
        for (int nf = 0; nf < 4; ++nf) {
            int p = wn*32 + nf*8 + nb;
            #pragma unroll
            for (int rr = 0; rr < 2; ++rr) {
                int l = wm*32 + mf*16 + mr + rr*8;
                uint32_t o0 = SWZ256(p*256 + l*2);
                uint32_t o1 = SWZ256((p+1)*256 + l*2);
                float x0 = __half2float(*(__half*)(sm + 65536 + o0));
                float x1 = __half2float(*(__half*)(sm + 65536 + o1));
                float2 v = make_float2(acc[mf][nf][rr*2+0] + dval*x0,
                                       acc[mf][nf][rr*2+1] + dval*x1);
                *(float2*)&g_y[(size_t)(row0+l)*DIN + h*HD + p] = v;
            }
        }
    }
}

// ---------------- gating + RMSNorm + fused fp16 split_a for GEMM2 ----------------
__global__ void norm_split_kernel(const float* __restrict__ norm_w,
                                  __half* __restrict__ O)
{
    __shared__ float tbuf[DIN];
    __shared__ float red[256];
    int row = blockIdx.x;
    int tid = threadIdx.x;
    float partial = 0.f;
    for (int i = tid; i < DIN; i += 256) {
        float yv = g_y[(size_t)row*DIN + i];
        float zv = g_zx[(size_t)row*DPROJ + i];
        float t  = yv * (zv / (1.f + __expf(-zv)));
        tbuf[i] = t;
        partial += t*t;
    }
    red[tid] = partial;
    __syncthreads();
    for (int s = 128; s > 0; s >>= 1) {
        if (tid < s) red[tid] += red[tid + s];
        __syncthreads();
    }
    float scale = rsqrtf(red[0] / (float)DIN + 1e-5f);
    __half* ob = O + (size_t)row * KP2;
    for (int i = tid; i < DIN; i += 256) {
        float v = tbuf[i] * scale * norm_w[i];
        __half hi = __float2half(v);
        __half lo = __float2half(v - __half2float(hi));
        ob[i] = hi; ob[DIN + i] = lo;
    }
}

// ---------------- launch ----------------
extern "C" void kernel_launch(void* const* d_in, const int* in_sizes, int n_in,
                              void* d_out, int out_size)
{
    const float* feature = (const float*)d_in[0];
    const float* gate1   = (const float*)d_in[1];
    const float* in_w    = (const float*)d_in[2];
    const float* conv_w  = (const float*)d_in[3];
    const float* conv_b  = (const float*)d_in[4];
    const float* dt_bias = (const float*)d_in[5];
    const float* A_log   = (const float*)d_in[6];
    const float* Dv      = (const float*)d_in[7];
    const float* norm_w  = (const float*)d_in[8];
    const float* out_w   = (const float*)d_in[9];
    float* out = (float*)d_out;

    void* p_zx; cudaGetSymbolAddress(&p_zx, g_zx);
    void* p_a2; cudaGetSymbolAddress(&p_a2, g_a2);
    void* p_b2; cudaGetSymbolAddress(&p_b2, g_b2);
    __half* a2 = (__half*)p_a2;
    __half* b2 = (__half*)p_b2;

    cudaFuncSetAttribute(cb_mma,     cudaFuncAttributeMaxDynamicSharedMemorySize, CBM_SMEM_BYTES);
    cudaFuncSetAttribute(states_mma, cudaFuncAttributeMaxDynamicSharedMemorySize, STM_SMEM_BYTES);
    cudaFuncSetAttribute(y_mma,      cudaFuncAttributeMaxDynamicSharedMemorySize, YM_SMEM_BYTES);
    cudaFuncSetAttribute(gemm_mma,   cudaFuncAttributeMaxDynamicSharedMemorySize, GEMM_SMEM_BYTES);

    // 1. fp16 split conversion + GEMM1 (tensor cores, 2-stage)
    split_a_kernel<<<(NROWS*DMODEL + 255)/256, 256>>>(feature, a2, NROWS, DMODEL);
    split_b_kernel<<<(NPAD1*DMODEL + 255)/256, 256>>>(in_w, b2, DPROJ, NPAD1, DMODEL);
    gemm_mma<<<dim3(NPAD1/128, NROWS/128), 256, GEMM_SMEM_BYTES>>>(
        a2, b2, (float*)p_zx, KP1, DPROJ, DPROJ, nullptr, nullptr, 0);
    // 2. conv + silu (4 rows per thread)
    conv_silu_kernel<<<dim3(DXBC/256, NROWS/4), 256>>>(conv_w, conv_b);
    // 3. dt + per-chunk cumsum (fused)
    acum_kernel<<<NBC*NH, CHUNKQ>>>(A_log, dt_bias);
    // 4. CB per chunk (tensor cores, fp16 2-term)
    cb_mma<<<NBC, 256, CBM_SMEM_BYTES>>>();
    // 5. chunk states (tensor cores, fp16 2-term)
    states_mma<<<NBC*NH, 128, STM_SMEM_BYTES>>>();
    // 6. inter-chunk recurrence
    scan_kernel<<<(BSZ*NH*HD*DSTATE)/512, 512>>>();
    // 7. Y (tensor cores, fp16 2-term)
    y_mma<<<NBC*NH, 256, YM_SMEM_BYTES>>>(Dv);
    // 8. gating + RMSNorm + fp16 split for GEMM2 (fused)
    norm_split_kernel<<<NROWS, 256>>>(norm_w, a2);
    // 9. fp16 split B + GEMM2 (tensor cores) + residual epilogue
    split_b_kernel<<<(DMODEL*DIN + 255)/256, 256>>>(out_w, b2, DMODEL, DMODEL, DIN);
    gemm_mma<<<dim3(DMODEL/128, NROWS/128), 256, GEMM_SMEM_BYTES>>>(
        a2, b2, out, KP2, DMODEL, DMODEL, feature, gate1, 1);
}

// round 14
// speedup vs baseline: 1.6536x; 1.2287x over previous
#include <cuda_runtime.h>
#include <cuda_bf16.h>
#include <cuda_fp16.h>
#include <math.h>
#include <stdint.h>

// ---------------- problem constants ----------------
#define BSZ     2
#define SEQL    4096
#define DMODEL  768
#define DSTATE  128
#define HD      64
#define DIN     1536
#define NH      24
#define DXBC    1792          // DIN + 2*DSTATE
#define DPROJ   3352          // 2*DIN + 2*DSTATE + NH
#define CHUNKQ  128
#define NCH     32            // SEQL / CHUNKQ
#define NROWS   (BSZ*SEQL)    // 8192
#define NBC     (BSZ*NCH)     // 64

#define KP1     DMODEL        // 768  (fp16 1-term)
#define KP2     DIN           // 1536
#define NPAD1   3456          // 27*128

// single shared-memory extern symbol (consistent across all kernels)
extern __shared__ __align__(128) char smbuf[];

// ---------------- scratch (static device memory; no runtime allocs) ----------------
__device__ float g_zx[(size_t)NROWS*DPROJ];
__device__ float g_xbc[(size_t)NROWS*DXBC];
__device__ float g_dt[NROWS*NH];
__device__ float g_acum[NROWS*NH];
__device__ float g_alast[NBC*NH];
__device__ float g_cb[(size_t)NBC*CHUNKQ*CHUNKQ];
__device__ float g_states[(size_t)NBC*NH*HD*DSTATE];
__device__ float g_prev[(size_t)NBC*NH*HD*DSTATE];
__device__ float g_y[(size_t)NROWS*DIN];
__device__ __half g_a2[(size_t)NROWS*KP2];            // fp16 A (max 8192*1536)
__device__ __half g_b2[(size_t)NPAD1*KP1];            // fp16 B (3456*768 > 768*1536)

// ================= helpers (family-target safe) =================
__device__ __forceinline__ uint32_t smem_u32(const void* p) {
    uint32_t a;
    asm("{ .reg .u64 t; cvta.to.shared.u64 t, %1; cvt.u32.u64 %0, t; }" : "=r"(a) : "l"(p));
    return a;
}
__device__ __forceinline__ void cpasync16(uint32_t dst, const void* src) {
    asm volatile("cp.async.cg.shared.global [%0], [%1], 16;" :: "r"(dst), "l"(src) : "memory");
}
__device__ __forceinline__ void ldsm4(uint32_t* r, uint32_t addr) {
    asm volatile("ldmatrix.sync.aligned.m8n8.x4.shared.b16 {%0,%1,%2,%3}, [%4];"
                 : "=r"(r[0]), "=r"(r[1]), "=r"(r[2]), "=r"(r[3]) : "r"(addr));
}
// fp16 mma (all tensor-core kernels)
__device__ __forceinline__ void mma16816h(float* d, const uint32_t* a, const uint32_t* b,
                                          const float* c) {
    asm volatile("mma.sync.aligned.m16n8k16.row.col.f32.f16.f16.f32 "
        "{%0,%1,%2,%3}, {%4,%5,%6,%7}, {%8,%9}, {%10,%11,%12,%13};"
        : "=f"(d[0]), "=f"(d[1]), "=f"(d[2]), "=f"(d[3])
        : "r"(a[0]), "r"(a[1]), "r"(a[2]), "r"(a[3]), "r"(b[0]), "r"(b[1]),
          "f"(c[0]), "f"(c[1]), "f"(c[2]), "f"(c[3]));
}
#define SWZ128(x) ((x) ^ (((x) >> 3) & 0x70))
#define SWZ256(x) ((x) ^ (((x) >> 4) & 0x70))

// fp16 hi+lo split store (A-side of SSD kernels, exact to ~2^-22)
__device__ __forceinline__ void split_store_h(char* hi_base, char* lo_base, uint32_t off, float v) {
    __half hi = __float2half(v);
    __half lo = __float2half(v - __half2float(hi));
    *(__half*)(hi_base + off) = hi;
    *(__half*)(lo_base + off) = lo;
}
// fp16 single store
__device__ __forceinline__ void store_h(char* base, uint32_t off, float v) {
    *(__half*)(base + off) = __float2half(v);
}

// ================= fp16 cast conversions for big GEMMs (1-term) =================
__global__ void cast_a_kernel(const float* __restrict__ X, __half* __restrict__ O, int total)
{
    int idx = blockIdx.x * blockDim.x + threadIdx.x;
    if (idx >= total) return;
    O[idx] = __float2half(X[idx]);
}
__global__ void cast_b_kernel(const float* __restrict__ W, __half* __restrict__ O,
                              int Nreal, int Npad, int K)
{
    int idx = blockIdx.x * blockDim.x + threadIdx.x;
    if (idx >= Npad * K) return;
    int n = idx / K;
    O[idx] = __float2half((n < Nreal) ? W[idx] : 0.f);
}

// ================= mma.sync fp16 GEMM (2-stage cp.async, verified R12) =================
#define GEMM_SMEM_BYTES (1024 + 2*32768)
__global__ __launch_bounds__(256, 2)
void gemm_mma(const __half* __restrict__ A2, const __half* __restrict__ B2,
              float* __restrict__ C, int KP, int Nreal, int ldc,
              const float* __restrict__ feat, const float* __restrict__ gate1, int ep)
{
    const uint32_t base = (smem_u32(smbuf) + 1023) & ~1023u;
    const int tid  = threadIdx.x;
    const int lane = tid & 31;
    const int wid  = tid >> 5;
    const int m0 = blockIdx.y * 128;
    const int n0 = blockIdx.x * 128;
    const int wm = wid >> 2;
    const int wn = wid & 3;

    const int frow = tid >> 3;
    const int u16  = tid & 7;
    const __half* ag = A2 + (size_t)(m0 + frow) * KP + u16 * 8;
    const __half* bg = B2 + (size_t)(n0 + frow) * KP + u16 * 8;

    float acc[4][4][4] = {};
    const int nch = KP >> 6;

    uint32_t foff[4];
    #pragma unroll
    for (int j = 0; j < 4; ++j)
        foff[j] = SWZ128((frow + j*32)*128 + u16*16);

    {
        uint32_t ab = base, bb = base + 16384;
        #pragma unroll
        for (int j = 0; j < 4; ++j) {
            cpasync16(ab + foff[j], ag + (size_t)(j*32)*KP);
            cpasync16(bb + foff[j], bg + (size_t)(j*32)*KP);
        }
        asm volatile("cp.async.commit_group;" ::: "memory");
    }

    for (int c = 0; c < nch; ++c) {
        if (c + 1 < nch) {
            uint32_t ab = base + ((c+1)&1) * 32768, bb = ab + 16384;
            const __half* a = ag + (c+1) * 64;
            const __half* b = bg + (c+1) * 64;
            #pragma unroll
            for (int j = 0; j < 4; ++j) {
                cpasync16(ab + foff[j], a + (size_t)(j*32)*KP);
                cpasync16(bb + foff[j], b + (size_t)(j*32)*KP);
            }
            asm volatile("cp.async.commit_group;" ::: "memory");
            asm volatile("cp.async.wait_group 1;" ::: "memory");
        } else {
            asm volatile("cp.async.wait_group 0;" ::: "memory");
        }
        __syncthreads();

        const uint32_t ab = base + (c&1) * 32768;
        const uint32_t bb = ab + 16384;
        #pragma unroll
        for (int ks = 0; ks < 4; ++ks) {
            uint32_t a_r[4][4];
            uint32_t b_r[2][4];
            {
                const int ra = wm*64 + ((lane>>3)&1)*8 + (lane&7);
                const int ka = ks*32 + ((lane>>4)&1)*16;
                #pragma unroll
                for (int mf = 0; mf < 4; ++mf)
                    ldsm4(a_r[mf], ab + SWZ128((ra + mf*16)*128 + ka));
            }
            {
                const int rb = wn*32 + ((lane>>4)&1)*8 + (lane&7);
                const int kb = ks*32 + ((lane>>3)&1)*16;
                #pragma unroll
                for (int nf2 = 0; nf2 < 2; ++nf2)
                    ldsm4(b_r[nf2], bb + SWZ128((rb + nf2*16)*128 + kb));
            }
            #pragma unroll
            for (int mf = 0; mf < 4; ++mf)
                #pragma unroll
                for (int nf = 0; nf < 4; ++nf)
                    mma16816h(acc[mf][nf], a_r[mf], &b_r[nf>>1][(nf&1)*2], acc[mf][nf]);
        }
        __syncthreads();
    }

    float g = 0.f;
    if (ep) g = 1.f / (1.f + expf(-gate1[0]));
    const int mrow = m0 + wm*64 + (lane >> 2);
    const int nbase = n0 + wn*32 + (lane & 3)*2;
    #pragma unroll
    for (int mf = 0; mf < 4; ++mf) {
        #pragma unroll
        for (int nf = 0; nf < 4; ++nf) {
            int m = mrow + mf*16;
            int n = nbase + nf*8;
            if (n < Nreal) {
                float2 v0 = make_float2(acc[mf][nf][0], acc[mf][nf][1]);
                float2 v1 = make_float2(acc[mf][nf][2], acc[mf][nf][3]);
                if (ep) {
                    float2 f0 = *(const float2*)(feat + (size_t)m*ldc + n);
                    float2 f1 = *(const float2*)(feat + (size_t)(m+8)*ldc + n);
                    v0.x = g*v0.x + f0.x; v0.y = g*v0.y + f0.y;
                    v1.x = g*v1.x + f1.x; v1.y = g*v1.y + f1.y;
                }
                *(float2*)(C + (size_t)m*ldc + n)     = v0;
                *(float2*)(C + (size_t)(m+8)*ldc + n) = v1;
            }
        }
    }
}

// ---------------- depthwise causal conv (width 4) + bias + SiLU, 4 rows/thread ----------------
__global__ void conv_silu_kernel(const float* __restrict__ cw, const float* __restrict__ cb)
{
    int ch = blockIdx.x * 256 + threadIdx.x;
    int r0 = blockIdx.y * 4;
    int l0 = r0 % SEQL;
    float w0 = cw[ch*4+0], w1 = cw[ch*4+1], w2 = cw[ch*4+2], w3 = cw[ch*4+3];
    float bias = cb[ch];
    float v[7];
    #pragma unroll
    for (int t = 0; t < 7; ++t) {
        int lr = l0 + t - 3;
        v[t] = (lr >= 0) ? g_zx[(size_t)(r0 + t - 3) * DPROJ + DIN + ch] : 0.f;
    }
    #pragma unroll
    for (int j = 0; j < 4; ++j) {
        float acc = bias + w0*v[j] + w1*v[j+1] + w2*v[j+2] + w3*v[j+3];
        g_xbc[(size_t)(r0 + j) * DXBC + ch] = acc / (1.f + __expf(-acc));
    }
}

// ---------------- dt (softplus) + per-chunk inclusive cumsum of dt*A, fused ----------------
__global__ void acum_kernel(const float* __restrict__ A_log, const float* __restrict__ dt_bias)
{
    int h  = blockIdx.x % NH;
    int bc = blockIdx.x / NH;
    int l  = threadIdx.x;
    __shared__ float s[CHUNKQ];
    float Ah = -expf(A_log[h]);
    int row = bc * CHUNKQ + l;
    float v = g_zx[(size_t)row * DPROJ + (DIN + DXBC) + h] + dt_bias[h];
    float dt = (v > 20.f) ? v : log1pf(expf(v));
    g_dt[row * NH + h] = dt;
    s[l] = dt * Ah;
    __syncthreads();
    for (int off = 1; off < CHUNKQ; off <<= 1) {
        float t = (l >= off) ? s[l - off] : 0.f;
        __syncthreads();
        s[l] += t;
        __syncthreads();
    }
    g_acum[row * NH + h] = s[l];
    if (l == CHUNKQ - 1) g_alast[bc * NH + h] = s[l];
}

// ================= CB via mma.sync (fp16 2-term, verified R13) =================
#define CBM_SMEM_BYTES 98304
__global__ __launch_bounds__(256, 1) void cb_mma()
{
    char* sm = smbuf;
    const int bc  = blockIdx.x;
    const int tid = threadIdx.x;
    const int row0 = bc * CHUNKQ;

    for (int i = tid; i < 16384; i += 256) {
        int l = i >> 7, n = i & 127;
        const float* baseg = &g_xbc[(size_t)(row0 + l) * DXBC + DIN];
        uint32_t off = SWZ256(l*256 + n*2);
        split_store_h(sm, sm + 32768, off, baseg[DSTATE + n]);  // C[l][n] hi+lo
        store_h(sm + 65536, off, baseg[n]);                     // B[s=l][n] hi
    }
    __syncthreads();

    const int lane = tid & 31;
    const int wid  = tid >> 5;
    const int wm = wid >> 2;
    const int wn = wid & 3;
    const uint32_t base = smem_u32(sm);
    float acc[4][4][4] = {};
    const uint32_t AO[2] = {0u, 32768u};
    #pragma unroll
    for (int pp = 0; pp < 2; ++pp) {
        const uint32_t ab = base + AO[pp], bb = base + 65536u;
        #pragma unroll
        for (int ks = 0; ks < 8; ++ks) {
            uint32_t a_r[4][4], b_r[2][4];
            const int ra = wm*64 + ((lane>>3)&1)*8 + (lane&7);
            const int ca = ks*32 + ((lane>>4)&1)*16;
            #pragma unroll
            for (int mf = 0; mf < 4; ++mf)
                ldsm4(a_r[mf], ab + SWZ256((ra + mf*16)*256 + ca));
            const int rb = wn*32 + ((lane>>4)&1)*8 + (lane&7);
            const int cb2 = ks*32 + ((lane>>3)&1)*16;
            #pragma unroll
            for (int nf2 = 0; nf2 < 2; ++nf2)
                ldsm4(b_r[nf2], bb + SWZ256((rb + nf2*16)*256 + cb2));
            #pragma unroll
            for (int mf = 0; mf < 4; ++mf)
                #pragma unroll
                for (int nf = 0; nf < 4; ++nf)
                    mma16816h(acc[mf][nf], a_r[mf], &b_r[nf>>1][(nf&1)*2], acc[mf][nf]);
        }
    }
    float* outb = &g_cb[(size_t)bc * CHUNKQ * CHUNKQ];
    const int mr = lane >> 2;
    const int nb = (lane & 3)*2;
    #pragma unroll
    for (int mf = 0; mf < 4; ++mf) {
        #pragma unroll
        for (int nf = 0; nf < 4; ++nf) {
            int l = wm*64 + mf*16 + mr;
            int s = wn*32 + nf*8 + nb;
            *(float2*)&outb[l*CHUNKQ + s]       = make_float2(acc[mf][nf][0], acc[mf][nf][1]);
            *(float2*)&outb[(l+8)*CHUNKQ + s]   = make_float2(acc[mf][nf][2], acc[mf][nf][3]);
        }
    }
}

// ================= states via mma.sync (fp16 2-term, verified R13) =================
#define STM_SMEM_BYTES 65536
__global__ __launch_bounds__(128, 2) void states_mma()
{
    char* sm = smbuf;
    __shared__ float wfac[128];
    const int h  = blockIdx.x % NH;
    const int bc = blockIdx.x / NH;
    const int tid = threadIdx.x;
    const int row0 = bc * CHUNKQ;

    if (tid < 128) {
        float alast = g_alast[bc*NH + h];
        wfac[tid] = g_dt[(row0+tid)*NH + h] * __expf(alast - g_acum[(row0+tid)*NH + h]);
    }
    __syncthreads();
    for (int i = tid; i < 8192; i += 128) {
        int l = i >> 6, p = i & 63;
        float v = g_xbc[(size_t)(row0+l)*DXBC + h*HD + p] * wfac[l];
        split_store_h(sm, sm + 16384, SWZ256(p*256 + l*2), v);
    }
    for (int i = tid; i < 16384; i += 128) {
        int l = i >> 7, n = i & 127;
        store_h(sm + 32768, SWZ256(n*256 + l*2), g_xbc[(size_t)(row0+l)*DXBC + DIN + n]);
    }
    __syncthreads();

    const int lane = tid & 31;
    const int w = tid >> 5;
    const uint32_t base = smem_u32(sm);
    float acc[4][4][4] = {};
    const uint32_t AO[2] = {0u, 16384u};
    #pragma unroll
    for (int pp = 0; pp < 2; ++pp) {
        const uint32_t ab = base + AO[pp], bb = base + 32768u;
        #pragma unroll
        for (int ks = 0; ks < 8; ++ks) {
            uint32_t a_r[4][4], b_r[2][4];
            const int ra = ((lane>>3)&1)*8 + (lane&7);
            const int ca = ks*32 + ((lane>>4)&1)*16;
            #pragma unroll
            for (int mf = 0; mf < 4; ++mf)
                ldsm4(a_r[mf], ab + SWZ256((ra + mf*16)*256 + ca));
            const int rb = w*32 + ((lane>>4)&1)*8 + (lane&7);
            const int cb2 = ks*32 + ((lane>>3)&1)*16;
            #pragma unroll
            for (int nf2 = 0; nf2 < 2; ++nf2)
                ldsm4(b_r[nf2], bb + SWZ256((rb + nf2*16)*256 + cb2));
            #pragma unroll
            for (int mf = 0; mf < 4; ++mf)
                #pragma unroll
                for (int nf = 0; nf < 4; ++nf)
                    mma16816h(acc[mf][nf], a_r[mf], &b_r[nf>>1][(nf&1)*2], acc[mf][nf]);
        }
    }
    float* outb = &g_states[((size_t)(bc*NH) + h) * HD * DSTATE];
    const int mr = lane >> 2;
    const int nb = w*32 + (lane & 3)*2;
    #pragma unroll
    for (int mf = 0; mf < 4; ++mf) {
        #pragma unroll
        for (int nf = 0; nf < 4; ++nf) {
            int p = mf*16 + mr, n = nb + nf*8;
            *(float2*)&outb[p*DSTATE + n]       = make_float2(acc[mf][nf][0], acc[mf][nf][1]);
            *(float2*)&outb[(p+8)*DSTATE + n]   = make_float2(acc[mf][nf][2], acc[mf][nf][3]);
        }
    }
}

// ---------------- inter-chunk state recurrence (one lane per thread) ----------------
__global__ void scan_kernel()
{
    int gl = blockIdx.x * blockDim.x + threadIdx.x;
    int bh = gl >> 13;
    int b = bh / NH, h = bh % NH;
    int e = gl & 8191;
    float S = 0.f;
    for (int c = 0; c < NCH; c++) {
        int bc = b*NCH + c;
        size_t base = ((size_t)(bc*NH) + h) * HD * DSTATE;
        float ed = __expf(g_alast[bc*NH + h]);
        float st = g_states[base + e];
        g_prev[base + e] = S;
        S = S*ed + st;
    }
}

// ================= Y via mma.sync (fp16 2-term, verified R13) =================
#define YM_SMEM_BYTES 81920
__device__ __forceinline__ void y_mma_block(float acc[2][4][4], uint32_t base,
                                            int lane, int wm, int wn)
{
    const uint32_t AO[2] = {0u, 32768u};
    #pragma unroll
    for (int pp = 0; pp < 2; ++pp) {
        const uint32_t ab = base + AO[pp], bb = base + 65536u;
        #pragma unroll
        for (int ks = 0; ks < 8; ++ks) {
            uint32_t a_r[2][4], b_r[2][4];
            const int ra = wm*32 + ((lane>>3)&1)*8 + (lane&7);
            const int ca = ks*32 + ((lane>>4)&1)*16;
            #pragma unroll
            for (int mf = 0; mf < 2; ++mf)
                ldsm4(a_r[mf], ab + SWZ256((ra + mf*16)*256 + ca));
            const int rb = wn*32 + ((lane>>4)&1)*8 + (lane&7);
            const int cb2 = ks*32 + ((lane>>3)&1)*16;
            #pragma unroll
            for (int nf2 = 0; nf2 < 2; ++nf2)
                ldsm4(b_r[nf2], bb + SWZ256((rb + nf2*16)*256 + cb2));
            #pragma unroll
            for (int mf = 0; mf < 2; ++mf)
                #pragma unroll
                for (int nf = 0; nf < 4; ++nf)
                    mma16816h(acc[mf][nf], a_r[mf], &b_r[nf>>1][(nf&1)*2], acc[mf][nf]);
        }
    }
}

__global__ __launch_bounds__(256, 2) void y_mma(const float* __restrict__ Dv)
{
    char* sm = smbuf;
    __shared__ float acum_s[128], dt_s[128], eAl_s[128];
    const int h  = blockIdx.x % NH;
    const int bc = blockIdx.x / NH;
    const int tid = threadIdx.x;
    const int row0 = bc * CHUNKQ;

    if (tid < 128) {
        float a = g_acum[(row0+tid)*NH + h];
        acum_s[tid] = a;
        eAl_s[tid]  = __expf(a);
        dt_s[tid]   = g_dt[(row0+tid)*NH + h];
    }
    __syncthreads();

    for (int i = tid; i < 16384; i += 256) {
        int l = i >> 7, n = i & 127;
        float v = g_xbc[(size_t)(row0+l)*DXBC + DIN + DSTATE + n] * eAl_s[l];
        split_store_h(sm, sm + 32768, SWZ256(l*256 + n*2), v);
    }
    const size_t pbase = ((size_t)(bc*NH) + h) * HD * DSTATE;
    for (int i = tid; i < 8192; i += 256) {
        int p = i >> 7, n = i & 127;
        store_h(sm + 65536, SWZ256(p*256 + n*2), g_prev[pbase + i]);
    }
    __syncthreads();

    const int lane = tid & 31;
    const int wid = tid >> 5;
    const int wm = wid >> 1;
    const int wn = wid & 1;
    const uint32_t base = smem_u32(sm);
    float acc[2][4][4] = {};
    y_mma_block(acc, base, lane, wm, wn);
    __syncthreads();

    for (int i = tid; i < 16384; i += 256) {
        int l = i >> 7, s = i & 127;
        float v = 0.f;
        if (s <= l)
            v = g_cb[(size_t)bc*CHUNKQ*CHUNKQ + i] * __expf(acum_s[l] - acum_s[s]) * dt_s[s];
        split_store_h(sm, sm + 32768, SWZ256(l*256 + s*2), v);
    }
    for (int i = tid; i < 8192; i += 256) {
        int l = i >> 6, p = i & 63;
        store_h(sm + 65536, SWZ256(p*256 + l*2), g_xbc[(size_t)(row0+l)*DXBC + h*HD + p]);
    }
    __syncthreads();
    y_mma_block(acc, base, lane, wm, wn);

    const float dval = Dv[h];
    const int mr = lane >> 2;
    const int nb = (lane & 3)*2;
    #pragma unroll
    for (int mf = 0; mf < 2; ++mf) {
        #pragma unroll
        for (int nf = 0; nf < 4; ++nf) {
            int p = wn*32 + nf*8 + nb;
            #pragma unroll
            for (int rr = 0; rr < 2; ++rr) {
                int l = wm*32 + mf*16 + mr + rr*8;
                uint32_t o0 = SWZ256(p*256 + l*2);
                uint32_t o1 = SWZ256((p+1)*256 + l*2);
                float x0 = __half2float(*(__half*)(sm + 65536 + o0));
                float x1 = __half2float(*(__half*)(sm + 65536 + o1));
                float2 v = make_float2(acc[mf][nf][rr*2+0] + dval*x0,
                                       acc[mf][nf][rr*2+1] + dval*x1);
                *(float2*)&g_y[(size_t)(row0+l)*DIN + h*HD + p] = v;
            }
        }
    }
}

// ---------------- gating + RMSNorm + fused fp16 cast for GEMM2 (1-term) ----------------
__global__ void norm_split_kernel(const float* __restrict__ norm_w,
                                  __half* __restrict__ O)
{
    __shared__ float tbuf[DIN];
    __shared__ float red[256];
    int row = blockIdx.x;
    int tid = threadIdx.x;
    float partial = 0.f;
    for (int i = tid; i < DIN; i += 256) {
        float yv = g_y[(size_t)row*DIN + i];
        float zv = g_zx[(size_t)row*DPROJ + i];
        float t  = yv * (zv / (1.f + __expf(-zv)));
        tbuf[i] = t;
        partial += t*t;
    }
    red[tid] = partial;
    __syncthreads();
    for (int s = 128; s > 0; s >>= 1) {
        if (tid < s) red[tid] += red[tid + s];
        __syncthreads();
    }
    float scale = rsqrtf(red[0] / (float)DIN + 1e-5f);
    __half* ob = O + (size_t)row * KP2;
    for (int i = tid; i < DIN; i += 256)
        ob[i] = __float2half(tbuf[i] * scale * norm_w[i]);
}

// ---------------- launch ----------------
extern "C" void kernel_launch(void* const* d_in, const int* in_sizes, int n_in,
                              void* d_out, int out_size)
{
    const float* feature = (const float*)d_in[0];
    const float* gate1   = (const float*)d_in[1];
    const float* in_w    = (const float*)d_in[2];
    const float* conv_w  = (const float*)d_in[3];
    const float* conv_b  = (const float*)d_in[4];
    const float* dt_bias = (const float*)d_in[5];
    const float* A_log   = (const float*)d_in[6];
    const float* Dv      = (const float*)d_in[7];
    const float* norm_w  = (const float*)d_in[8];
    const float* out_w   = (const float*)d_in[9];
    float* out = (float*)d_out;

    void* p_zx; cudaGetSymbolAddress(&p_zx, g_zx);
    void* p_a2; cudaGetSymbolAddress(&p_a2, g_a2);
    void* p_b2; cudaGetSymbolAddress(&p_b2, g_b2);
    __half* a2 = (__half*)p_a2;
    __half* b2 = (__half*)p_b2;

    cudaFuncSetAttribute(cb_mma,     cudaFuncAttributeMaxDynamicSharedMemorySize, CBM_SMEM_BYTES);
    cudaFuncSetAttribute(states_mma, cudaFuncAttributeMaxDynamicSharedMemorySize, STM_SMEM_BYTES);
    cudaFuncSetAttribute(y_mma,      cudaFuncAttributeMaxDynamicSharedMemorySize, YM_SMEM_BYTES);
    cudaFuncSetAttribute(gemm_mma,   cudaFuncAttributeMaxDynamicSharedMemorySize, GEMM_SMEM_BYTES);

    // 1. fp16 casts + GEMM1 (tensor cores, 1-term)
    cast_a_kernel<<<(NROWS*DMODEL + 255)/256, 256>>>(feature, a2, NROWS*DMODEL);
    cast_b_kernel<<<(NPAD1*DMODEL + 255)/256, 256>>>(in_w, b2, DPROJ, NPAD1, DMODEL);
    gemm_mma<<<dim3(NPAD1/128, NROWS/128), 256, GEMM_SMEM_BYTES>>>(
        a2, b2, (float*)p_zx, KP1, DPROJ, DPROJ, nullptr, nullptr, 0);
    // 2. conv + silu (4 rows per thread)
    conv_silu_kernel<<<dim3(DXBC/256, NROWS/4), 256>>>(conv_w, conv_b);
    // 3. dt + per-chunk cumsum (fused)
    acum_kernel<<<NBC*NH, CHUNKQ>>>(A_log, dt_bias);
    // 4. CB per chunk (tensor cores, fp16 2-term)
    cb_mma<<<NBC, 256, CBM_SMEM_BYTES>>>();
    // 5. chunk states (tensor cores, fp16 2-term)
    states_mma<<<NBC*NH, 128, STM_SMEM_BYTES>>>();
    // 6. inter-chunk recurrence
    scan_kernel<<<(BSZ*NH*HD*DSTATE)/512, 512>>>();
    // 7. Y (tensor cores, fp16 2-term)
    y_mma<<<NBC*NH, 256, YM_SMEM_BYTES>>>(Dv);
    // 8. gating + RMSNorm + fp16 cast for GEMM2 (fused)
    norm_split_kernel<<<NROWS, 256>>>(norm_w, a2);
    // 9. fp16 cast B + GEMM2 (tensor cores) + residual epilogue
    cast_b_kernel<<<(DMODEL*DIN + 255)/256, 256>>>(out_w, b2, DMODEL, DMODEL, DIN);
    gemm_mma<<<dim3(DMODEL/128, NROWS/128), 256, GEMM_SMEM_BYTES>>>(
        a2, b2, out, KP2, DMODEL, DMODEL, feature, gate1, 1);
}

// round 15
// speedup vs baseline: 1.8725x; 1.1324x over previous
#include <cuda_runtime.h>
#include <cuda_bf16.h>
#include <cuda_fp16.h>
#include <math.h>
#include <stdint.h>

// ---------------- problem constants ----------------
#define BSZ     2
#define SEQL    4096
#define DMODEL  768
#define DSTATE  128
#define HD      64
#define DIN     1536
#define NH      24
#define DXBC    1792          // DIN + 2*DSTATE
#define DPROJ   3352          // 2*DIN + 2*DSTATE + NH
#define CHUNKQ  128
#define NCH     32            // SEQL / CHUNKQ
#define NROWS   (BSZ*SEQL)    // 8192
#define NBC     (BSZ*NCH)     // 64

#define KP1     DMODEL        // 768  (fp16 1-term)
#define KP2     DIN           // 1536
#define NPAD1   3456          // 27*128

// single shared-memory extern symbol (consistent across all kernels)
extern __shared__ __align__(128) char smbuf[];

// ---------------- scratch (static device memory; no runtime allocs) ----------------
__device__ float g_zx[(size_t)NROWS*DPROJ];
__device__ float g_xbc[(size_t)NROWS*DXBC];
__device__ float g_dt[NROWS*NH];
__device__ float g_acum[NROWS*NH];
__device__ float g_alast[NBC*NH];
__device__ float g_cb[(size_t)NBC*CHUNKQ*CHUNKQ];
__device__ float g_states[(size_t)NBC*NH*HD*DSTATE];
__device__ float g_prev[(size_t)NBC*NH*HD*DSTATE];
__device__ float g_y[(size_t)NROWS*DIN];
__device__ __half g_a2[(size_t)NROWS*KP2];            // fp16 A
__device__ __half g_b2[(size_t)NPAD1*KP1];            // fp16 B

// ================= helpers (family-target safe) =================
__device__ __forceinline__ uint32_t smem_u32(const void* p) {
    uint32_t a;
    asm("{ .reg .u64 t; cvta.to.shared.u64 t, %1; cvt.u32.u64 %0, t; }" : "=r"(a) : "l"(p));
    return a;
}
__device__ __forceinline__ void cpasync16(uint32_t dst, const void* src) {
    asm volatile("cp.async.cg.shared.global [%0], [%1], 16;" :: "r"(dst), "l"(src) : "memory");
}
__device__ __forceinline__ void ldsm4(uint32_t* r, uint32_t addr) {
    asm volatile("ldmatrix.sync.aligned.m8n8.x4.shared.b16 {%0,%1,%2,%3}, [%4];"
                 : "=r"(r[0]), "=r"(r[1]), "=r"(r[2]), "=r"(r[3]) : "r"(addr));
}
// fp16 mma (all tensor-core kernels)
__device__ __forceinline__ void mma16816h(float* d, const uint32_t* a, const uint32_t* b,
                                          const float* c) {
    asm volatile("mma.sync.aligned.m16n8k16.row.col.f32.f16.f16.f32 "
        "{%0,%1,%2,%3}, {%4,%5,%6,%7}, {%8,%9}, {%10,%11,%12,%13};"
        : "=f"(d[0]), "=f"(d[1]), "=f"(d[2]), "=f"(d[3])
        : "r"(a[0]), "r"(a[1]), "r"(a[2]), "r"(a[3]), "r"(b[0]), "r"(b[1]),
          "f"(c[0]), "f"(c[1]), "f"(c[2]), "f"(c[3]));
}
#define SWZ128(x) ((x) ^ (((x) >> 3) & 0x70))
#define SWZ256(x) ((x) ^ (((x) >> 4) & 0x70))

// fp16 single store
__device__ __forceinline__ void store_h(char* base, uint32_t off, float v) {
    *(__half*)(base + off) = __float2half(v);
}

// ================= fp16 cast conversions for big GEMMs (1-term) =================
__global__ void cast_a_kernel(const float* __restrict__ X, __half* __restrict__ O, int total)
{
    int idx = blockIdx.x * blockDim.x + threadIdx.x;
    if (idx >= total) return;
    O[idx] = __float2half(X[idx]);
}
__global__ void cast_b_kernel(const float* __restrict__ W, __half* __restrict__ O,
                              int Nreal, int Npad, int K)
{
    int idx = blockIdx.x * blockDim.x + threadIdx.x;
    if (idx >= Npad * K) return;
    int n = idx / K;
    O[idx] = __float2half((n < Nreal) ? W[idx] : 0.f);
}

// ================= mma.sync fp16 GEMM (2-stage cp.async, verified R12-R14) =================
#define GEMM_SMEM_BYTES (1024 + 2*32768)
__global__ __launch_bounds__(256, 2)
void gemm_mma(const __half* __restrict__ A2, const __half* __restrict__ B2,
              float* __restrict__ C, int KP, int Nreal, int ldc,
              const float* __restrict__ feat, const float* __restrict__ gate1, int ep)
{
    const uint32_t base = (smem_u32(smbuf) + 1023) & ~1023u;
    const int tid  = threadIdx.x;
    const int lane = tid & 31;
    const int wid  = tid >> 5;
    const int m0 = blockIdx.y * 128;
    const int n0 = blockIdx.x * 128;
    const int wm = wid >> 2;
    const int wn = wid & 3;

    const int frow = tid >> 3;
    const int u16  = tid & 7;
    const __half* ag = A2 + (size_t)(m0 + frow) * KP + u16 * 8;
    const __half* bg = B2 + (size_t)(n0 + frow) * KP + u16 * 8;

    float acc[4][4][4] = {};
    const int nch = KP >> 6;

    uint32_t foff[4];
    #pragma unroll
    for (int j = 0; j < 4; ++j)
        foff[j] = SWZ128((frow + j*32)*128 + u16*16);

    {
        uint32_t ab = base, bb = base + 16384;
        #pragma unroll
        for (int j = 0; j < 4; ++j) {
            cpasync16(ab + foff[j], ag + (size_t)(j*32)*KP);
            cpasync16(bb + foff[j], bg + (size_t)(j*32)*KP);
        }
        asm volatile("cp.async.commit_group;" ::: "memory");
    }

    for (int c = 0; c < nch; ++c) {
        if (c + 1 < nch) {
            uint32_t ab = base + ((c+1)&1) * 32768, bb = ab + 16384;
            const __half* a = ag + (c+1) * 64;
            const __half* b = bg + (c+1) * 64;
            #pragma unroll
            for (int j = 0; j < 4; ++j) {
                cpasync16(ab + foff[j], a + (size_t)(j*32)*KP);
                cpasync16(bb + foff[j], b + (size_t)(j*32)*KP);
            }
            asm volatile("cp.async.commit_group;" ::: "memory");
            asm volatile("cp.async.wait_group 1;" ::: "memory");
        } else {
            asm volatile("cp.async.wait_group 0;" ::: "memory");
        }
        __syncthreads();

        const uint32_t ab = base + (c&1) * 32768;
        const uint32_t bb = ab + 16384;
        #pragma unroll
        for (int ks = 0; ks < 4; ++ks) {
            uint32_t a_r[4][4];
            uint32_t b_r[2][4];
            {
                const int ra = wm*64 + ((lane>>3)&1)*8 + (lane&7);
                const int ka = ks*32 + ((lane>>4)&1)*16;
                #pragma unroll
                for (int mf = 0; mf < 4; ++mf)
                    ldsm4(a_r[mf], ab + SWZ128((ra + mf*16)*128 + ka));
            }
            {
                const int rb = wn*32 + ((lane>>4)&1)*8 + (lane&7);
                const int kb = ks*32 + ((lane>>3)&1)*16;
                #pragma unroll
                for (int nf2 = 0; nf2 < 2; ++nf2)
                    ldsm4(b_r[nf2], bb + SWZ128((rb + nf2*16)*128 + kb));
            }
            #pragma unroll
            for (int mf = 0; mf < 4; ++mf)
                #pragma unroll
                for (int nf = 0; nf < 4; ++nf)
                    mma16816h(acc[mf][nf], a_r[mf], &b_r[nf>>1][(nf&1)*2], acc[mf][nf]);
        }
        __syncthreads();
    }

    float g = 0.f;
    if (ep) g = 1.f / (1.f + expf(-gate1[0]));
    const int mrow = m0 + wm*64 + (lane >> 2);
    const int nbase = n0 + wn*32 + (lane & 3)*2;
    #pragma unroll
    for (int mf = 0; mf < 4; ++mf) {
        #pragma unroll
        for (int nf = 0; nf < 4; ++nf) {
            int m = mrow + mf*16;
            int n = nbase + nf*8;
            if (n < Nreal) {
                float2 v0 = make_float2(acc[mf][nf][0], acc[mf][nf][1]);
                float2 v1 = make_float2(acc[mf][nf][2], acc[mf][nf][3]);
                if (ep) {
                    float2 f0 = *(const float2*)(feat + (size_t)m*ldc + n);
                    float2 f1 = *(const float2*)(feat + (size_t)(m+8)*ldc + n);
                    v0.x = g*v0.x + f0.x; v0.y = g*v0.y + f0.y;
                    v1.x = g*v1.x + f1.x; v1.y = g*v1.y + f1.y;
                }
                *(float2*)(C + (size_t)m*ldc + n)     = v0;
                *(float2*)(C + (size_t)(m+8)*ldc + n) = v1;
            }
        }
    }
}

// ---------------- depthwise causal conv (width 4) + bias + SiLU, 4 rows/thread ----------------
__global__ void conv_silu_kernel(const float* __restrict__ cw, const float* __restrict__ cb)
{
    int ch = blockIdx.x * 256 + threadIdx.x;
    int r0 = blockIdx.y * 4;
    int l0 = r0 % SEQL;
    float w0 = cw[ch*4+0], w1 = cw[ch*4+1], w2 = cw[ch*4+2], w3 = cw[ch*4+3];
    float bias = cb[ch];
    float v[7];
    #pragma unroll
    for (int t = 0; t < 7; ++t) {
        int lr = l0 + t - 3;
        v[t] = (lr >= 0) ? g_zx[(size_t)(r0 + t - 3) * DPROJ + DIN + ch] : 0.f;
    }
    #pragma unroll
    for (int j = 0; j < 4; ++j) {
        float acc = bias + w0*v[j] + w1*v[j+1] + w2*v[j+2] + w3*v[j+3];
        g_xbc[(size_t)(r0 + j) * DXBC + ch] = acc / (1.f + __expf(-acc));
    }
}

// ---------------- dt (softplus) + per-chunk inclusive cumsum of dt*A, fused ----------------
__global__ void acum_kernel(const float* __restrict__ A_log, const float* __restrict__ dt_bias)
{
    int h  = blockIdx.x % NH;
    int bc = blockIdx.x / NH;
    int l  = threadIdx.x;
    __shared__ float s[CHUNKQ];
    float Ah = -expf(A_log[h]);
    int row = bc * CHUNKQ + l;
    float v = g_zx[(size_t)row * DPROJ + (DIN + DXBC) + h] + dt_bias[h];
    float dt = (v > 20.f) ? v : log1pf(expf(v));
    g_dt[row * NH + h] = dt;
    s[l] = dt * Ah;
    __syncthreads();
    for (int off = 1; off < CHUNKQ; off <<= 1) {
        float t = (l >= off) ? s[l - off] : 0.f;
        __syncthreads();
        s[l] += t;
        __syncthreads();
    }
    g_acum[row * NH + h] = s[l];
    if (l == CHUNKQ - 1) g_alast[bc * NH + h] = s[l];
}

// ================= CB via mma.sync (fp16 1-term): CB[l,s] = sum_n C[l,n]*B[s,n] =================
// smem: C[128][128]@0 (32K), B@32K (32K). Single pass.
#define CBM_SMEM_BYTES 65536
__global__ __launch_bounds__(256, 1) void cb_mma()
{
    char* sm = smbuf;
    const int bc  = blockIdx.x;
    const int tid = threadIdx.x;
    const int row0 = bc * CHUNKQ;

    for (int i = tid; i < 16384; i += 256) {
        int l = i >> 7, n = i & 127;
        const float* baseg = &g_xbc[(size_t)(row0 + l) * DXBC + DIN];
        uint32_t off = SWZ256(l*256 + n*2);
        store_h(sm,         off, baseg[DSTATE + n]);  // C[l][n]
        store_h(sm + 32768, off, baseg[n]);           // B[s=l][n]
    }
    __syncthreads();

    const int lane = tid & 31;
    const int wid  = tid >> 5;
    const int wm = wid >> 2;
    const int wn = wid & 3;
    const uint32_t base = smem_u32(sm);
    float acc[4][4][4] = {};
    {
        const uint32_t ab = base, bb = base + 32768u;
        #pragma unroll
        for (int ks = 0; ks < 8; ++ks) {
            uint32_t a_r[4][4], b_r[2][4];
            const int ra = wm*64 + ((lane>>3)&1)*8 + (lane&7);
            const int ca = ks*32 + ((lane>>4)&1)*16;
            #pragma unroll
            for (int mf = 0; mf < 4; ++mf)
                ldsm4(a_r[mf], ab + SWZ256((ra + mf*16)*256 + ca));
            const int rb = wn*32 + ((lane>>4)&1)*8 + (lane&7);
            const int cb2 = ks*32 + ((lane>>3)&1)*16;
            #pragma unroll
            for (int nf2 = 0; nf2 < 2; ++nf2)
                ldsm4(b_r[nf2], bb + SWZ256((rb + nf2*16)*256 + cb2));
            #pragma unroll
            for (int mf = 0; mf < 4; ++mf)
                #pragma unroll
                for (int nf = 0; nf < 4; ++nf)
                    mma16816h(acc[mf][nf], a_r[mf], &b_r[nf>>1][(nf&1)*2], acc[mf][nf]);
        }
    }
    float* outb = &g_cb[(size_t)bc * CHUNKQ * CHUNKQ];
    const int mr = lane >> 2;
    const int nb = (lane & 3)*2;
    #pragma unroll
    for (int mf = 0; mf < 4; ++mf) {
        #pragma unroll
        for (int nf = 0; nf < 4; ++nf) {
            int l = wm*64 + mf*16 + mr;
            int s = wn*32 + nf*8 + nb;
            *(float2*)&outb[l*CHUNKQ + s]       = make_float2(acc[mf][nf][0], acc[mf][nf][1]);
            *(float2*)&outb[(l+8)*CHUNKQ + s]   = make_float2(acc[mf][nf][2], acc[mf][nf][3]);
        }
    }
}

// ================= states via mma.sync (fp16 1-term) =================
// smem: A[64][128]@0 (16K), B[128][128]@16K (32K). Single pass.
#define STM_SMEM_BYTES 49152
__global__ __launch_bounds__(128, 2) void states_mma()
{
    char* sm = smbuf;
    __shared__ float wfac[128];
    const int h  = blockIdx.x % NH;
    const int bc = blockIdx.x / NH;
    const int tid = threadIdx.x;
    const int row0 = bc * CHUNKQ;

    if (tid < 128) {
        float alast = g_alast[bc*NH + h];
        wfac[tid] = g_dt[(row0+tid)*NH + h] * __expf(alast - g_acum[(row0+tid)*NH + h]);
    }
    __syncthreads();
    for (int i = tid; i < 8192; i += 128) {
        int l = i >> 6, p = i & 63;
        float v = g_xbc[(size_t)(row0+l)*DXBC + h*HD + p] * wfac[l];
        store_h(sm, SWZ256(p*256 + l*2), v);
    }
    for (int i = tid; i < 16384; i += 128) {
        int l = i >> 7, n = i & 127;
        store_h(sm + 16384, SWZ256(n*256 + l*2), g_xbc[(size_t)(row0+l)*DXBC + DIN + n]);
    }
    __syncthreads();

    const int lane = tid & 31;
    const int w = tid >> 5;
    const uint32_t base = smem_u32(sm);
    float acc[4][4][4] = {};
    {
        const uint32_t ab = base, bb = base + 16384u;
        #pragma unroll
        for (int ks = 0; ks < 8; ++ks) {
            uint32_t a_r[4][4], b_r[2][4];
            const int ra = ((lane>>3)&1)*8 + (lane&7);
            const int ca = ks*32 + ((lane>>4)&1)*16;
            #pragma unroll
            for (int mf = 0; mf < 4; ++mf)
                ldsm4(a_r[mf], ab + SWZ256((ra + mf*16)*256 + ca));
            const int rb = w*32 + ((lane>>4)&1)*8 + (lane&7);
            const int cb2 = ks*32 + ((lane>>3)&1)*16;
            #pragma unroll
            for (int nf2 = 0; nf2 < 2; ++nf2)
                ldsm4(b_r[nf2], bb + SWZ256((rb + nf2*16)*256 + cb2));
            #pragma unroll
            for (int mf = 0; mf < 4; ++mf)
                #pragma unroll
                for (int nf = 0; nf < 4; ++nf)
                    mma16816h(acc[mf][nf], a_r[mf], &b_r[nf>>1][(nf&1)*2], acc[mf][nf]);
        }
    }
    float* outb = &g_states[((size_t)(bc*NH) + h) * HD * DSTATE];
    const int mr = lane >> 2;
    const int nb = w*32 + (lane & 3)*2;
    #pragma unroll
    for (int mf = 0; mf < 4; ++mf) {
        #pragma unroll
        for (int nf = 0; nf < 4; ++nf) {
            int p = mf*16 + mr, n = nb + nf*8;
            *(float2*)&outb[p*DSTATE + n]       = make_float2(acc[mf][nf][0], acc[mf][nf][1]);
            *(float2*)&outb[(p+8)*DSTATE + n]   = make_float2(acc[mf][nf][2], acc[mf][nf][3]);
        }
    }
}

// ---------------- inter-chunk state recurrence (one lane per thread) ----------------
__global__ void scan_kernel()
{
    int gl = blockIdx.x * blockDim.x + threadIdx.x;
    int bh = gl >> 13;
    int b = bh / NH, h = bh % NH;
    int e = gl & 8191;
    float S = 0.f;
    for (int c = 0; c < NCH; c++) {
        int bc = b*NCH + c;
        size_t base = ((size_t)(bc*NH) + h) * HD * DSTATE;
        float ed = __expf(g_alast[bc*NH + h]);
        float st = g_states[base + e];
        g_prev[base + e] = S;
        S = S*ed + st;
    }
}

// ================= Y via mma.sync (fp16 1-term) =================
// smem: A[128][128]@0 (32K), B[64][128]@32K (16K). Single pass per block.
#define YM_SMEM_BYTES 49152
__device__ __forceinline__ void y_mma_block(float acc[2][4][4], uint32_t base,
                                            int lane, int wm, int wn)
{
    const uint32_t ab = base, bb = base + 32768u;
    #pragma unroll
    for (int ks = 0; ks < 8; ++ks) {
        uint32_t a_r[2][4], b_r[2][4];
        const int ra = wm*32 + ((lane>>3)&1)*8 + (lane&7);
        const int ca = ks*32 + ((lane>>4)&1)*16;
        #pragma unroll
        for (int mf = 0; mf < 2; ++mf)
            ldsm4(a_r[mf], ab + SWZ256((ra + mf*16)*256 + ca));
        const int rb = wn*32 + ((lane>>4)&1)*8 + (lane&7);
        const int cb2 = ks*32 + ((lane>>3)&1)*16;
        #pragma unroll
        for (int nf2 = 0; nf2 < 2; ++nf2)
            ldsm4(b_r[nf2], bb + SWZ256((rb + nf2*16)*256 + cb2));
        #pragma unroll
        for (int mf = 0; mf < 2; ++mf)
            #pragma unroll
            for (int nf = 0; nf < 4; ++nf)
                mma16816h(acc[mf][nf], a_r[mf], &b_r[nf>>1][(nf&1)*2], acc[mf][nf]);
    }
}

__global__ __launch_bounds__(256, 2) void y_mma(const float* __restrict__ Dv)
{
    char* sm = smbuf;
    __shared__ float acum_s[128], dt_s[128], eAl_s[128];
    const int h  = blockIdx.x % NH;
    const int bc = blockIdx.x / NH;
    const int tid = threadIdx.x;
    const int row0 = bc * CHUNKQ;

    if (tid < 128) {
        float a = g_acum[(row0+tid)*NH + h];
        acum_s[tid] = a;
        eAl_s[tid]  = __expf(a);
        dt_s[tid]   = g_dt[(row0+tid)*NH + h];
    }
    __syncthreads();

    // ---- pass 1 tiles: A = C*exp(acum[l]) [l][n], B = prev [p][n]
    for (int i = tid; i < 16384; i += 256) {
        int l = i >> 7, n = i & 127;
        float v = g_xbc[(size_t)(row0+l)*DXBC + DIN + DSTATE + n] * eAl_s[l];
        store_h(sm, SWZ256(l*256 + n*2), v);
    }
    const size_t pbase = ((size_t)(bc*NH) + h) * HD * DSTATE;
    for (int i = tid; i < 8192; i += 256) {
        int p = i >> 7, n = i & 127;
        store_h(sm + 32768, SWZ256(p*256 + n*2), g_prev[pbase + i]);
    }
    __syncthreads();

    const int lane = tid & 31;
    const int wid = tid >> 5;
    const int wm = wid >> 1;
    const int wn = wid & 1;
    const uint32_t base = smem_u32(sm);
    float acc[2][4][4] = {};
    y_mma_block(acc, base, lane, wm, wn);
    __syncthreads();

    // ---- pass 2 tiles: A = W [l][s], B = xT [p][s]
    for (int i = tid; i < 16384; i += 256) {
        int l = i >> 7, s = i & 127;
        float v = 0.f;
        if (s <= l)
            v = g_cb[(size_t)bc*CHUNKQ*CHUNKQ + i] * __expf(acum_s[l] - acum_s[s]) * dt_s[s];
        store_h(sm, SWZ256(l*256 + s*2), v);
    }
    for (int i = tid; i < 8192; i += 256) {
        int l = i >> 6, p = i & 63;
        store_h(sm + 32768, SWZ256(p*256 + l*2), g_xbc[(size_t)(row0+l)*DXBC + h*HD + p]);
    }
    __syncthreads();
    y_mma_block(acc, base, lane, wm, wn);

    // ---- epilogue: + D*x (x from fp16 plane), write Y
    const float dval = Dv[h];
    const int mr = lane >> 2;
    const int nb = (lane & 3)*2;
    #pragma unroll
    for (int mf = 0; mf < 2; ++mf) {
        #pragma unroll
        for (int nf = 0; nf < 4; ++nf) {
            int p = wn*32 + nf*8 + nb;
            #pragma unroll
            for (int rr = 0; rr < 2; ++rr) {
                int l = wm*32 + mf*16 + mr + rr*8;
                uint32_t o0 = SWZ256(p*256 + l*2);
                uint32_t o1 = SWZ256((p+1)*256 + l*2);
                float x0 = __half2float(*(__half*)(sm + 32768 + o0));
                float x1 = __half2float(*(__half*)(sm + 32768 + o1));
                float2 v = make_float2(acc[mf][nf][rr*2+0] + dval*x0,
                                       acc[mf][nf][rr*2+1] + dval*x1);
                *(float2*)&g_y[(size_t)(row0+l)*DIN + h*HD + p] = v;
            }
        }
    }
}

// ---------------- gating + RMSNorm + fused fp16 cast for GEMM2 (1-term) ----------------
__global__ void norm_split_kernel(const float* __restrict__ norm_w,
                                  __half* __restrict__ O)
{
    __shared__ float tbuf[DIN];
    __shared__ float red[256];
    int row = blockIdx.x;
    int tid = threadIdx.x;
    float partial = 0.f;
    for (int i = tid; i < DIN; i += 256) {
        float yv = g_y[(size_t)row*DIN + i];
        float zv = g_zx[(size_t)row*DPROJ + i];
        float t  = yv * (zv / (1.f + __expf(-zv)));
        tbuf[i] = t;
        partial += t*t;
    }
    red[tid] = partial;
    __syncthreads();
    for (int s = 128; s > 0; s >>= 1) {
        if (tid < s) red[tid] += red[tid + s];
        __syncthreads();
    }
    float scale = rsqrtf(red[0] / (float)DIN + 1e-5f);
    __half* ob = O + (size_t)row * KP2;
    for (int i = tid; i < DIN; i += 256)
        ob[i] = __float2half(tbuf[i] * scale * norm_w[i]);
}

// ---------------- launch ----------------
extern "C" void kernel_launch(void* const* d_in, const int* in_sizes, int n_in,
                              void* d_out, int out_size)
{
    const float* feature = (const float*)d_in[0];
    const float* gate1   = (const float*)d_in[1];
    const float* in_w    = (const float*)d_in[2];
    const float* conv_w  = (const float*)d_in[3];
    const float* conv_b  = (const float*)d_in[4];
    const float* dt_bias = (const float*)d_in[5];
    const float* A_log   = (const float*)d_in[6];
    const float* Dv      = (const float*)d_in[7];
    const float* norm_w  = (const float*)d_in[8];
    const float* out_w   = (const float*)d_in[9];
    float* out = (float*)d_out;

    void* p_zx; cudaGetSymbolAddress(&p_zx, g_zx);
    void* p_a2; cudaGetSymbolAddress(&p_a2, g_a2);
    void* p_b2; cudaGetSymbolAddress(&p_b2, g_b2);
    __half* a2 = (__half*)p_a2;
    __half* b2 = (__half*)p_b2;

    cudaFuncSetAttribute(cb_mma,     cudaFuncAttributeMaxDynamicSharedMemorySize, CBM_SMEM_BYTES);
    cudaFuncSetAttribute(states_mma, cudaFuncAttributeMaxDynamicSharedMemorySize, STM_SMEM_BYTES);
    cudaFuncSetAttribute(y_mma,      cudaFuncAttributeMaxDynamicSharedMemorySize, YM_SMEM_BYTES);
    cudaFuncSetAttribute(gemm_mma,   cudaFuncAttributeMaxDynamicSharedMemorySize, GEMM_SMEM_BYTES);

    // 1. fp16 casts + GEMM1 (tensor cores, 1-term)
    cast_a_kernel<<<(NROWS*DMODEL + 255)/256, 256>>>(feature, a2, NROWS*DMODEL);
    cast_b_kernel<<<(NPAD1*DMODEL + 255)/256, 256>>>(in_w, b2, DPROJ, NPAD1, DMODEL);
    gemm_mma<<<dim3(NPAD1/128, NROWS/128), 256, GEMM_SMEM_BYTES>>>(
        a2, b2, (float*)p_zx, KP1, DPROJ, DPROJ, nullptr, nullptr, 0);
    // 2. conv + silu (4 rows per thread)
    conv_silu_kernel<<<dim3(DXBC/256, NROWS/4), 256>>>(conv_w, conv_b);
    // 3. dt + per-chunk cumsum (fused)
    acum_kernel<<<NBC*NH, CHUNKQ>>>(A_log, dt_bias);
    // 4. CB per chunk (tensor cores, fp16 1-term)
    cb_mma<<<NBC, 256, CBM_SMEM_BYTES>>>();
    // 5. chunk states (tensor cores, fp16 1-term)
    states_mma<<<NBC*NH, 128, STM_SMEM_BYTES>>>();
    // 6. inter-chunk recurrence
    scan_kernel<<<(BSZ*NH*HD*DSTATE)/512, 512>>>();
    // 7. Y (tensor cores, fp16 1-term)
    y_mma<<<NBC*NH, 256, YM_SMEM_BYTES>>>(Dv);
    // 8. gating + RMSNorm + fp16 cast for GEMM2 (fused)
    norm_split_kernel<<<NROWS, 256>>>(norm_w, a2);
    // 9. fp16 cast B + GEMM2 (tensor cores) + residual epilogue
    cast_b_kernel<<<(DMODEL*DIN + 255)/256, 256>>>(out_w, b2, DMODEL, DMODEL, DIN);
    gemm_mma<<<dim3(DMODEL/128, NROWS/128), 256, GEMM_SMEM_BYTES>>>(
        a2, b2, out, KP2, DMODEL, DMODEL, feature, gate1, 1);
}

// round 16
// speedup vs baseline: 2.1399x; 1.1428x over previous
#include <cuda_runtime.h>
#include <cuda_bf16.h>
#include <cuda_fp16.h>
#include <math.h>
#include <stdint.h>

// ---------------- problem constants ----------------
#define BSZ     2
#define SEQL    4096
#define DMODEL  768
#define DSTATE  128
#define HD      64
#define DIN     1536
#define NH      24
#define DXBC    1792          // DIN + 2*DSTATE
#define DPROJ   3352          // 2*DIN + 2*DSTATE + NH
#define CHUNKQ  128
#define NCH     32            // SEQL / CHUNKQ
#define NROWS   (BSZ*SEQL)    // 8192
#define NBC     (BSZ*NCH)     // 64

#define KP1     DMODEL        // 768  (fp16 1-term)
#define KP2     DIN           // 1536
#define NPAD1   3456          // 27*128

// single shared-memory extern symbol (consistent across all kernels)
extern __shared__ __align__(128) char smbuf[];

// ---------------- scratch (static device memory; no runtime allocs) ----------------
__device__ __half g_zx[(size_t)NROWS*DPROJ];           // in_proj output (fp16)
__device__ __half g_xbc[(size_t)NROWS*DXBC];           // conv+silu out (fp16)
__device__ float g_dt[NROWS*NH];
__device__ float g_acum[NROWS*NH];
__device__ float g_alast[NBC*NH];
__device__ float g_cb[(size_t)NBC*CHUNKQ*CHUNKQ];
__device__ __half g_states[(size_t)NBC*NH*HD*DSTATE];  // fp16
__device__ __half g_prev[(size_t)NBC*NH*HD*DSTATE];    // fp16
__device__ float g_y[(size_t)NROWS*DIN];
__device__ __half g_a2[(size_t)NROWS*KP2];             // fp16 A
__device__ __half g_b2[(size_t)NPAD1*KP1];             // fp16 B

// ================= helpers (family-target safe) =================
__device__ __forceinline__ uint32_t smem_u32(const void* p) {
    uint32_t a;
    asm("{ .reg .u64 t; cvta.to.shared.u64 t, %1; cvt.u32.u64 %0, t; }" : "=r"(a) : "l"(p));
    return a;
}
__device__ __forceinline__ void cpasync16(uint32_t dst, const void* src) {
    asm volatile("cp.async.cg.shared.global [%0], [%1], 16;" :: "r"(dst), "l"(src) : "memory");
}
__device__ __forceinline__ void ldsm4(uint32_t* r, uint32_t addr) {
    asm volatile("ldmatrix.sync.aligned.m8n8.x4.shared.b16 {%0,%1,%2,%3}, [%4];"
                 : "=r"(r[0]), "=r"(r[1]), "=r"(r[2]), "=r"(r[3]) : "r"(addr));
}
// fp16 mma (all tensor-core kernels)
__device__ __forceinline__ void mma16816h(float* d, const uint32_t* a, const uint32_t* b,
                                          const float* c) {
    asm volatile("mma.sync.aligned.m16n8k16.row.col.f32.f16.f16.f32 "
        "{%0,%1,%2,%3}, {%4,%5,%6,%7}, {%8,%9}, {%10,%11,%12,%13};"
        : "=f"(d[0]), "=f"(d[1]), "=f"(d[2]), "=f"(d[3])
        : "r"(a[0]), "r"(a[1]), "r"(a[2]), "r"(a[3]), "r"(b[0]), "r"(b[1]),
          "f"(c[0]), "f"(c[1]), "f"(c[2]), "f"(c[3]));
}
#define SWZ128(x) ((x) ^ (((x) >> 3) & 0x70))
#define SWZ256(x) ((x) ^ (((x) >> 4) & 0x70))

// fp16 single store
__device__ __forceinline__ void store_h(char* base, uint32_t off, float v) {
    *(__half*)(base + off) = __float2half(v);
}
__device__ __forceinline__ void copy_h(char* base, uint32_t off, __half v) {
    *(__half*)(base + off) = v;
}

// ================= fp16 cast conversions for big GEMMs (1-term) =================
__global__ void cast_a_kernel(const float* __restrict__ X, __half* __restrict__ O, int total)
{
    int idx = blockIdx.x * blockDim.x + threadIdx.x;
    if (idx >= total) return;
    O[idx] = __float2half(X[idx]);
}
__global__ void cast_b_kernel(const float* __restrict__ W, __half* __restrict__ O,
                              int Nreal, int Npad, int K)
{
    int idx = blockIdx.x * blockDim.x + threadIdx.x;
    if (idx >= Npad * K) return;
    int n = idx / K;
    O[idx] = __float2half((n < Nreal) ? W[idx] : 0.f);
}

// ================= mma.sync fp16 GEMM (2-stage cp.async, verified R12-R15) =================
// ep=0: write fp16 to C; ep=1: write fp32 with sigmoid(gate1)*acc + feat residual
#define GEMM_SMEM_BYTES (1024 + 2*32768)
__global__ __launch_bounds__(256, 2)
void gemm_mma(const __half* __restrict__ A2, const __half* __restrict__ B2,
              void* __restrict__ Cv, int KP, int Nreal, int ldc,
              const float* __restrict__ feat, const float* __restrict__ gate1, int ep)
{
    const uint32_t base = (smem_u32(smbuf) + 1023) & ~1023u;
    const int tid  = threadIdx.x;
    const int lane = tid & 31;
    const int wid  = tid >> 5;
    const int m0 = blockIdx.y * 128;
    const int n0 = blockIdx.x * 128;
    const int wm = wid >> 2;
    const int wn = wid & 3;

    const int frow = tid >> 3;
    const int u16  = tid & 7;
    const __half* ag = A2 + (size_t)(m0 + frow) * KP + u16 * 8;
    const __half* bg = B2 + (size_t)(n0 + frow) * KP + u16 * 8;

    float acc[4][4][4] = {};
    const int nch = KP >> 6;

    uint32_t foff[4];
    #pragma unroll
    for (int j = 0; j < 4; ++j)
        foff[j] = SWZ128((frow + j*32)*128 + u16*16);

    {
        uint32_t ab = base, bb = base + 16384;
        #pragma unroll
        for (int j = 0; j < 4; ++j) {
            cpasync16(ab + foff[j], ag + (size_t)(j*32)*KP);
            cpasync16(bb + foff[j], bg + (size_t)(j*32)*KP);
        }
        asm volatile("cp.async.commit_group;" ::: "memory");
    }

    for (int c = 0; c < nch; ++c) {
        if (c + 1 < nch) {
            uint32_t ab = base + ((c+1)&1) * 32768, bb = ab + 16384;
            const __half* a = ag + (c+1) * 64;
            const __half* b = bg + (c+1) * 64;
            #pragma unroll
            for (int j = 0; j < 4; ++j) {
                cpasync16(ab + foff[j], a + (size_t)(j*32)*KP);
                cpasync16(bb + foff[j], b + (size_t)(j*32)*KP);
            }
            asm volatile("cp.async.commit_group;" ::: "memory");
            asm volatile("cp.async.wait_group 1;" ::: "memory");
        } else {
            asm volatile("cp.async.wait_group 0;" ::: "memory");
        }
        __syncthreads();

        const uint32_t ab = base + (c&1) * 32768;
        const uint32_t bb = ab + 16384;
        #pragma unroll
        for (int ks = 0; ks < 4; ++ks) {
            uint32_t a_r[4][4];
            uint32_t b_r[2][4];
            {
                const int ra = wm*64 + ((lane>>3)&1)*8 + (lane&7);
                const int ka = ks*32 + ((lane>>4)&1)*16;
                #pragma unroll
                for (int mf = 0; mf < 4; ++mf)
                    ldsm4(a_r[mf], ab + SWZ128((ra + mf*16)*128 + ka));
            }
            {
                const int rb = wn*32 + ((lane>>4)&1)*8 + (lane&7);
                const int kb = ks*32 + ((lane>>3)&1)*16;
                #pragma unroll
                for (int nf2 = 0; nf2 < 2; ++nf2)
                    ldsm4(b_r[nf2], bb + SWZ128((rb + nf2*16)*128 + kb));
            }
            #pragma unroll
            for (int mf = 0; mf < 4; ++mf)
                #pragma unroll
                for (int nf = 0; nf < 4; ++nf)
                    mma16816h(acc[mf][nf], a_r[mf], &b_r[nf>>1][(nf&1)*2], acc[mf][nf]);
        }
        __syncthreads();
    }

    float g = 0.f;
    if (ep) g = 1.f / (1.f + expf(-gate1[0]));
    const int mrow = m0 + wm*64 + (lane >> 2);
    const int nbase = n0 + wn*32 + (lane & 3)*2;
    #pragma unroll
    for (int mf = 0; mf < 4; ++mf) {
        #pragma unroll
        for (int nf = 0; nf < 4; ++nf) {
            int m = mrow + mf*16;
            int n = nbase + nf*8;
            if (n < Nreal) {
                if (ep) {
                    float* C = (float*)Cv;
                    float2 v0 = make_float2(acc[mf][nf][0], acc[mf][nf][1]);
                    float2 v1 = make_float2(acc[mf][nf][2], acc[mf][nf][3]);
                    float2 f0 = *(const float2*)(feat + (size_t)m*ldc + n);
                    float2 f1 = *(const float2*)(feat + (size_t)(m+8)*ldc + n);
                    v0.x = g*v0.x + f0.x; v0.y = g*v0.y + f0.y;
                    v1.x = g*v1.x + f1.x; v1.y = g*v1.y + f1.y;
                    *(float2*)(C + (size_t)m*ldc + n)     = v0;
                    *(float2*)(C + (size_t)(m+8)*ldc + n) = v1;
                } else {
                    __half* C = (__half*)Cv;
                    *(__half2*)(C + (size_t)m*ldc + n)     = __floats2half2_rn(acc[mf][nf][0], acc[mf][nf][1]);
                    *(__half2*)(C + (size_t)(m+8)*ldc + n) = __floats2half2_rn(acc[mf][nf][2], acc[mf][nf][3]);
                }
            }
        }
    }
}

// ---------------- depthwise causal conv (width 4) + bias + SiLU, 4 rows/thread ----------------
__global__ void conv_silu_kernel(const float* __restrict__ cw, const float* __restrict__ cb)
{
    int ch = blockIdx.x * 256 + threadIdx.x;
    int r0 = blockIdx.y * 4;
    int l0 = r0 % SEQL;
    float w0 = cw[ch*4+0], w1 = cw[ch*4+1], w2 = cw[ch*4+2], w3 = cw[ch*4+3];
    float bias = cb[ch];
    float v[7];
    #pragma unroll
    for (int t = 0; t < 7; ++t) {
        int lr = l0 + t - 3;
        v[t] = (lr >= 0) ? __half2float(g_zx[(size_t)(r0 + t - 3) * DPROJ + DIN + ch]) : 0.f;
    }
    #pragma unroll
    for (int j = 0; j < 4; ++j) {
        float acc = bias + w0*v[j] + w1*v[j+1] + w2*v[j+2] + w3*v[j+3];
        g_xbc[(size_t)(r0 + j) * DXBC + ch] = __float2half(acc / (1.f + __expf(-acc)));
    }
}

// ---------------- dt (softplus) + per-chunk inclusive cumsum of dt*A, fused ----------------
__global__ void acum_kernel(const float* __restrict__ A_log, const float* __restrict__ dt_bias)
{
    int h  = blockIdx.x % NH;
    int bc = blockIdx.x / NH;
    int l  = threadIdx.x;
    __shared__ float s[CHUNKQ];
    float Ah = -expf(A_log[h]);
    int row = bc * CHUNKQ + l;
    float v = __half2float(g_zx[(size_t)row * DPROJ + (DIN + DXBC) + h]) + dt_bias[h];
    float dt = (v > 20.f) ? v : log1pf(expf(v));
    g_dt[row * NH + h] = dt;
    s[l] = dt * Ah;
    __syncthreads();
    for (int off = 1; off < CHUNKQ; off <<= 1) {
        float t = (l >= off) ? s[l - off] : 0.f;
        __syncthreads();
        s[l] += t;
        __syncthreads();
    }
    g_acum[row * NH + h] = s[l];
    if (l == CHUNKQ - 1) g_alast[bc * NH + h] = s[l];
}

// ================= CB via mma.sync (fp16 1-term): CB[l,s] = sum_n C[l,n]*B[s,n] =================
#define CBM_SMEM_BYTES 65536
__global__ __launch_bounds__(256, 1) void cb_mma()
{
    char* sm = smbuf;
    const int bc  = blockIdx.x;
    const int tid = threadIdx.x;
    const int row0 = bc * CHUNKQ;

    for (int i = tid; i < 16384; i += 256) {
        int l = i >> 7, n = i & 127;
        const __half* baseg = &g_xbc[(size_t)(row0 + l) * DXBC + DIN];
        uint32_t off = SWZ256(l*256 + n*2);
        copy_h(sm,         off, baseg[DSTATE + n]);  // C[l][n]
        copy_h(sm + 32768, off, baseg[n]);           // B[s=l][n]
    }
    __syncthreads();

    const int lane = tid & 31;
    const int wid  = tid >> 5;
    const int wm = wid >> 2;
    const int wn = wid & 3;
    const uint32_t base = smem_u32(sm);
    float acc[4][4][4] = {};
    {
        const uint32_t ab = base, bb = base + 32768u;
        #pragma unroll
        for (int ks = 0; ks < 8; ++ks) {
            uint32_t a_r[4][4], b_r[2][4];
            const int ra = wm*64 + ((lane>>3)&1)*8 + (lane&7);
            const int ca = ks*32 + ((lane>>4)&1)*16;
            #pragma unroll
            for (int mf = 0; mf < 4; ++mf)
                ldsm4(a_r[mf], ab + SWZ256((ra + mf*16)*256 + ca));
            const int rb = wn*32 + ((lane>>4)&1)*8 + (lane&7);
            const int cb2 = ks*32 + ((lane>>3)&1)*16;
            #pragma unroll
            for (int nf2 = 0; nf2 < 2; ++nf2)
                ldsm4(b_r[nf2], bb + SWZ256((rb + nf2*16)*256 + cb2));
            #pragma unroll
            for (int mf = 0; mf < 4; ++mf)
                #pragma unroll
                for (int nf = 0; nf < 4; ++nf)
                    mma16816h(acc[mf][nf], a_r[mf], &b_r[nf>>1][(nf&1)*2], acc[mf][nf]);
        }
    }
    float* outb = &g_cb[(size_t)bc * CHUNKQ * CHUNKQ];
    const int mr = lane >> 2;
    const int nb = (lane & 3)*2;
    #pragma unroll
    for (int mf = 0; mf < 4; ++mf) {
        #pragma unroll
        for (int nf = 0; nf < 4; ++nf) {
            int l = wm*64 + mf*16 + mr;
            int s = wn*32 + nf*8 + nb;
            *(float2*)&outb[l*CHUNKQ + s]       = make_float2(acc[mf][nf][0], acc[mf][nf][1]);
            *(float2*)&outb[(l+8)*CHUNKQ + s]   = make_float2(acc[mf][nf][2], acc[mf][nf][3]);
        }
    }
}

// ================= states via mma.sync (fp16 1-term) =================
#define STM_SMEM_BYTES 49152
__global__ __launch_bounds__(128, 2) void states_mma()
{
    char* sm = smbuf;
    __shared__ float wfac[128];
    const int h  = blockIdx.x % NH;
    const int bc = blockIdx.x / NH;
    const int tid = threadIdx.x;
    const int row0 = bc * CHUNKQ;

    if (tid < 128) {
        float alast = g_alast[bc*NH + h];
        wfac[tid] = g_dt[(row0+tid)*NH + h] * __expf(alast - g_acum[(row0+tid)*NH + h]);
    }
    __syncthreads();
    for (int i = tid; i < 8192; i += 128) {
        int l = i >> 6, p = i & 63;
        float v = __half2float(g_xbc[(size_t)(row0+l)*DXBC + h*HD + p]) * wfac[l];
        store_h(sm, SWZ256(p*256 + l*2), v);
    }
    for (int i = tid; i < 16384; i += 128) {
        int l = i >> 7, n = i & 127;
        copy_h(sm + 16384, SWZ256(n*256 + l*2), g_xbc[(size_t)(row0+l)*DXBC + DIN + n]);
    }
    __syncthreads();

    const int lane = tid & 31;
    const int w = tid >> 5;
    const uint32_t base = smem_u32(sm);
    float acc[4][4][4] = {};
    {
        const uint32_t ab = base, bb = base + 16384u;
        #pragma unroll
        for (int ks = 0; ks < 8; ++ks) {
            uint32_t a_r[4][4], b_r[2][4];
            const int ra = ((lane>>3)&1)*8 + (lane&7);
            const int ca = ks*32 + ((lane>>4)&1)*16;
            #pragma unroll
            for (int mf = 0; mf < 4; ++mf)
                ldsm4(a_r[mf], ab + SWZ256((ra + mf*16)*256 + ca));
            const int rb = w*32 + ((lane>>4)&1)*8 + (lane&7);
            const int cb2 = ks*32 + ((lane>>3)&1)*16;
            #pragma unroll
            for (int nf2 = 0; nf2 < 2; ++nf2)
                ldsm4(b_r[nf2], bb + SWZ256((rb + nf2*16)*256 + cb2));
            #pragma unroll
            for (int mf = 0; mf < 4; ++mf)
                #pragma unroll
                for (int nf = 0; nf < 4; ++nf)
                    mma16816h(acc[mf][nf], a_r[mf], &b_r[nf>>1][(nf&1)*2], acc[mf][nf]);
        }
    }
    __half* outb = &g_states[((size_t)(bc*NH) + h) * HD * DSTATE];
    const int mr = lane >> 2;
    const int nb = w*32 + (lane & 3)*2;
    #pragma unroll
    for (int mf = 0; mf < 4; ++mf) {
        #pragma unroll
        for (int nf = 0; nf < 4; ++nf) {
            int p = mf*16 + mr, n = nb + nf*8;
            *(__half2*)&outb[p*DSTATE + n]     = __floats2half2_rn(acc[mf][nf][0], acc[mf][nf][1]);
            *(__half2*)&outb[(p+8)*DSTATE + n] = __floats2half2_rn(acc[mf][nf][2], acc[mf][nf][3]);
        }
    }
}

// ---------------- inter-chunk state recurrence (one lane per thread, fp16 storage) ----------------
__global__ void scan_kernel()
{
    int gl = blockIdx.x * blockDim.x + threadIdx.x;
    int bh = gl >> 13;
    int b = bh / NH, h = bh % NH;
    int e = gl & 8191;
    float S = 0.f;
    for (int c = 0; c < NCH; c++) {
        int bc = b*NCH + c;
        size_t base = ((size_t)(bc*NH) + h) * HD * DSTATE;
        float ed = __expf(g_alast[bc*NH + h]);
        float st = __half2float(g_states[base + e]);
        g_prev[base + e] = __float2half(S);
        S = S*ed + st;
    }
}

// ================= Y via mma.sync (fp16 1-term) =================
#define YM_SMEM_BYTES 49152
__device__ __forceinline__ void y_mma_block(float acc[2][4][4], uint32_t base,
                                            int lane, int wm, int wn)
{
    const uint32_t ab = base, bb = base + 32768u;
    #pragma unroll
    for (int ks = 0; ks < 8; ++ks) {
        uint32_t a_r[2][4], b_r[2][4];
        const int ra = wm*32 + ((lane>>3)&1)*8 + (lane&7);
        const int ca = ks*32 + ((lane>>4)&1)*16;
        #pragma unroll
        for (int mf = 0; mf < 2; ++mf)
            ldsm4(a_r[mf], ab + SWZ256((ra + mf*16)*256 + ca));
        const int rb = wn*32 + ((lane>>4)&1)*8 + (lane&7);
        const int cb2 = ks*32 + ((lane>>3)&1)*16;
        #pragma unroll
        for (int nf2 = 0; nf2 < 2; ++nf2)
            ldsm4(b_r[nf2], bb + SWZ256((rb + nf2*16)*256 + cb2));
        #pragma unroll
        for (int mf = 0; mf < 2; ++mf)
            #pragma unroll
            for (int nf = 0; nf < 4; ++nf)
                mma16816h(acc[mf][nf], a_r[mf], &b_r[nf>>1][(nf&1)*2], acc[mf][nf]);
    }
}

__global__ __launch_bounds__(256, 2) void y_mma(const float* __restrict__ Dv)
{
    char* sm = smbuf;
    __shared__ float acum_s[128], dt_s[128], eAl_s[128];
    const int h  = blockIdx.x % NH;
    const int bc = blockIdx.x / NH;
    const int tid = threadIdx.x;
    const int row0 = bc * CHUNKQ;

    if (tid < 128) {
        float a = g_acum[(row0+tid)*NH + h];
        acum_s[tid] = a;
        eAl_s[tid]  = __expf(a);
        dt_s[tid]   = g_dt[(row0+tid)*NH + h];
    }
    __syncthreads();

    // ---- pass 1 tiles: A = C*exp(acum[l]) [l][n], B = prev [p][n]
    for (int i = tid; i < 16384; i += 256) {
        int l = i >> 7, n = i & 127;
        float v = __half2float(g_xbc[(size_t)(row0+l)*DXBC + DIN + DSTATE + n]) * eAl_s[l];
        store_h(sm, SWZ256(l*256 + n*2), v);
    }
    const size_t pbase = ((size_t)(bc*NH) + h) * HD * DSTATE;
    for (int i = tid; i < 8192; i += 256) {
        int p = i >> 7, n = i & 127;
        copy_h(sm + 32768, SWZ256(p*256 + n*2), g_prev[pbase + i]);
    }
    __syncthreads();

    const int lane = tid & 31;
    const int wid = tid >> 5;
    const int wm = wid >> 1;
    const int wn = wid & 1;
    const uint32_t base = smem_u32(sm);
    float acc[2][4][4] = {};
    y_mma_block(acc, base, lane, wm, wn);
    __syncthreads();

    // ---- pass 2 tiles: A = W [l][s], B = xT [p][s]
    for (int i = tid; i < 16384; i += 256) {
        int l = i >> 7, s = i & 127;
        float v = 0.f;
        if (s <= l)
            v = g_cb[(size_t)bc*CHUNKQ*CHUNKQ + i] * __expf(acum_s[l] - acum_s[s]) * dt_s[s];
        store_h(sm, SWZ256(l*256 + s*2), v);
    }
    for (int i = tid; i < 8192; i += 256) {
        int l = i >> 6, p = i & 63;
        copy_h(sm + 32768, SWZ256(p*256 + l*2), g_xbc[(size_t)(row0+l)*DXBC + h*HD + p]);
    }
    __syncthreads();
    y_mma_block(acc, base, lane, wm, wn);

    // ---- epilogue: + D*x (x from fp16 plane), write Y
    const float dval = Dv[h];
    const int mr = lane >> 2;
    const int nb = (lane & 3)*2;
    #pragma unroll
    for (int mf = 0; mf < 2; ++mf) {
        #pragma unroll
        for (int nf = 0; nf < 4; ++nf) {
            int p = wn*32 + nf*8 + nb;
            #pragma unroll
            for (int rr = 0; rr < 2; ++rr) {
                int l = wm*32 + mf*16 + mr + rr*8;
                uint32_t o0 = SWZ256(p*256 + l*2);
                uint32_t o1 = SWZ256((p+1)*256 + l*2);
                float x0 = __half2float(*(__half*)(sm + 32768 + o0));
                float x1 = __half2float(*(__half*)(sm + 32768 + o1));
                float2 v = make_float2(acc[mf][nf][rr*2+0] + dval*x0,
                                       acc[mf][nf][rr*2+1] + dval*x1);
                *(float2*)&g_y[(size_t)(row0+l)*DIN + h*HD + p] = v;
            }
        }
    }
}

// ---------------- gating + RMSNorm + fused fp16 cast for GEMM2 (1-term) ----------------
__global__ void norm_split_kernel(const float* __restrict__ norm_w,
                                  __half* __restrict__ O)
{
    __shared__ float tbuf[DIN];
    __shared__ float red[256];
    int row = blockIdx.x;
    int tid = threadIdx.x;
    float partial = 0.f;
    for (int i = tid; i < DIN; i += 256) {
        float yv = g_y[(size_t)row*DIN + i];
        float zv = __half2float(g_zx[(size_t)row*DPROJ + i]);
        float t  = yv * (zv / (1.f + __expf(-zv)));
        tbuf[i] = t;
        partial += t*t;
    }
    red[tid] = partial;
    __syncthreads();
    for (int s = 128; s > 0; s >>= 1) {
        if (tid < s) red[tid] += red[tid + s];
        __syncthreads();
    }
    float scale = rsqrtf(red[0] / (float)DIN + 1e-5f);
    __half* ob = O + (size_t)row * KP2;
    for (int i = tid; i < DIN; i += 256)
        ob[i] = __float2half(tbuf[i] * scale * norm_w[i]);
}

// ---------------- launch ----------------
extern "C" void kernel_launch(void* const* d_in, const int* in_sizes, int n_in,
                              void* d_out, int out_size)
{
    const float* feature = (const float*)d_in[0];
    const float* gate1   = (const float*)d_in[1];
    const float* in_w    = (const float*)d_in[2];
    const float* conv_w  = (const float*)d_in[3];
    const float* conv_b  = (const float*)d_in[4];
    const float* dt_bias = (const float*)d_in[5];
    const float* A_log   = (const float*)d_in[6];
    const float* Dv      = (const float*)d_in[7];
    const float* norm_w  = (const float*)d_in[8];
    const float* out_w   = (const float*)d_in[9];
    float* out = (float*)d_out;

    void* p_zx; cudaGetSymbolAddress(&p_zx, g_zx);
    void* p_a2; cudaGetSymbolAddress(&p_a2, g_a2);
    void* p_b2; cudaGetSymbolAddress(&p_b2, g_b2);
    __half* a2 = (__half*)p_a2;
    __half* b2 = (__half*)p_b2;

    cudaFuncSetAttribute(cb_mma,     cudaFuncAttributeMaxDynamicSharedMemorySize, CBM_SMEM_BYTES);
    cudaFuncSetAttribute(states_mma, cudaFuncAttributeMaxDynamicSharedMemorySize, STM_SMEM_BYTES);
    cudaFuncSetAttribute(y_mma,      cudaFuncAttributeMaxDynamicSharedMemorySize, YM_SMEM_BYTES);
    cudaFuncSetAttribute(gemm_mma,   cudaFuncAttributeMaxDynamicSharedMemorySize, GEMM_SMEM_BYTES);

    // 1. fp16 casts + GEMM1 (tensor cores, fp16 output)
    cast_a_kernel<<<(NROWS*DMODEL + 255)/256, 256>>>(feature, a2, NROWS*DMODEL);
    cast_b_kernel<<<(NPAD1*DMODEL + 255)/256, 256>>>(in_w, b2, DPROJ, NPAD1, DMODEL);
    gemm_mma<<<dim3(NPAD1/128, NROWS/128), 256, GEMM_SMEM_BYTES>>>(
        a2, b2, p_zx, KP1, DPROJ, DPROJ, nullptr, nullptr, 0);
    // 2. conv + silu (4 rows per thread, fp16 in/out)
    conv_silu_kernel<<<dim3(DXBC/256, NROWS/4), 256>>>(conv_w, conv_b);
    // 3. dt + per-chunk cumsum (fused)
    acum_kernel<<<NBC*NH, CHUNKQ>>>(A_log, dt_bias);
    // 4. CB per chunk (tensor cores, fp16 1-term)
    cb_mma<<<NBC, 256, CBM_SMEM_BYTES>>>();
    // 5. chunk states (tensor cores, fp16 1-term, fp16 out)
    states_mma<<<NBC*NH, 128, STM_SMEM_BYTES>>>();
    // 6. inter-chunk recurrence (fp16 storage)
    scan_kernel<<<(BSZ*NH*HD*DSTATE)/512, 512>>>();
    // 7. Y (tensor cores, fp16 1-term)
    y_mma<<<NBC*NH, 256, YM_SMEM_BYTES>>>(Dv);
    // 8. gating + RMSNorm + fp16 cast for GEMM2 (fused)
    norm_split_kernel<<<NROWS, 256>>>(norm_w, a2);
    // 9. fp16 cast B + GEMM2 (tensor cores) + residual epilogue
    cast_b_kernel<<<(DMODEL*DIN + 255)/256, 256>>>(out_w, b2, DMODEL, DMODEL, DIN);
    gemm_mma<<<dim3(DMODEL/128, NROWS/128), 256, GEMM_SMEM_BYTES>>>(
        a2, b2, out, KP2, DMODEL, DMODEL, feature, gate1, 1);
}

// round 17
// speedup vs baseline: 2.2447x; 1.0490x over previous
#include <cuda_runtime.h>
#include <cuda_bf16.h>
#include <cuda_fp16.h>
#include <math.h>
#include <stdint.h>

// ---------------- problem constants ----------------
#define BSZ     2
#define SEQL    4096
#define DMODEL  768
#define DSTATE  128
#define HD      64
#define DIN     1536
#define NH      24
#define DXBC    1792          // DIN + 2*DSTATE
#define DPROJ   3352          // 2*DIN + 2*DSTATE + NH
#define CHUNKQ  128
#define NCH     32            // SEQL / CHUNKQ
#define NROWS   (BSZ*SEQL)    // 8192
#define NBC     (BSZ*NCH)     // 64

#define KP1     DMODEL        // 768  (fp16 1-term)
#define KP2     DIN           // 1536
#define NPAD1   3456          // 27*128

// single shared-memory extern symbol (consistent across all kernels)
extern __shared__ __align__(128) char smbuf[];

// ---------------- scratch (static device memory; no runtime allocs) ----------------
__device__ __half g_zx[(size_t)NROWS*DPROJ];           // in_proj output (fp16)
__device__ __half g_xbc[(size_t)NROWS*DXBC];           // conv+silu out (fp16)
__device__ float g_dt[NROWS*NH];
__device__ float g_acum[NROWS*NH];
__device__ float g_alast[NBC*NH];
__device__ float g_cb[(size_t)NBC*CHUNKQ*CHUNKQ];
__device__ __half g_states[(size_t)NBC*NH*HD*DSTATE];  // fp16
__device__ __half g_prev[(size_t)NBC*NH*HD*DSTATE];    // fp16
__device__ __half g_y[(size_t)NROWS*DIN];              // fp16
__device__ __half g_a2[(size_t)NROWS*KP2];             // fp16 A
__device__ __half g_b2[(size_t)NPAD1*KP1];             // fp16 B

// ================= helpers (family-target safe) =================
__device__ __forceinline__ uint32_t smem_u32(const void* p) {
    uint32_t a;
    asm("{ .reg .u64 t; cvta.to.shared.u64 t, %1; cvt.u32.u64 %0, t; }" : "=r"(a) : "l"(p));
    return a;
}
__device__ __forceinline__ void cpasync16(uint32_t dst, const void* src) {
    asm volatile("cp.async.cg.shared.global [%0], [%1], 16;" :: "r"(dst), "l"(src) : "memory");
}
__device__ __forceinline__ void ldsm4(uint32_t* r, uint32_t addr) {
    asm volatile("ldmatrix.sync.aligned.m8n8.x4.shared.b16 {%0,%1,%2,%3}, [%4];"
                 : "=r"(r[0]), "=r"(r[1]), "=r"(r[2]), "=r"(r[3]) : "r"(addr));
}
// fp16 mma (all tensor-core kernels)
__device__ __forceinline__ void mma16816h(float* d, const uint32_t* a, const uint32_t* b,
                                          const float* c) {
    asm volatile("mma.sync.aligned.m16n8k16.row.col.f32.f16.f16.f32 "
        "{%0,%1,%2,%3}, {%4,%5,%6,%7}, {%8,%9}, {%10,%11,%12,%13};"
        : "=f"(d[0]), "=f"(d[1]), "=f"(d[2]), "=f"(d[3])
        : "r"(a[0]), "r"(a[1]), "r"(a[2]), "r"(a[3]), "r"(b[0]), "r"(b[1]),
          "f"(c[0]), "f"(c[1]), "f"(c[2]), "f"(c[3]));
}
#define SWZ128(x) ((x) ^ (((x) >> 3) & 0x70))
#define SWZ256(x) ((x) ^ (((x) >> 4) & 0x70))

// fp16 single store
__device__ __forceinline__ void store_h(char* base, uint32_t off, float v) {
    *(__half*)(base + off) = __float2half(v);
}
__device__ __forceinline__ void copy_h(char* base, uint32_t off, __half v) {
    *(__half*)(base + off) = v;
}

// ================= fp16 cast conversions for big GEMMs (1-term) =================
__global__ void cast_a_kernel(const float* __restrict__ X, __half* __restrict__ O, int total)
{
    int idx = blockIdx.x * blockDim.x + threadIdx.x;
    if (idx >= total) return;
    O[idx] = __float2half(X[idx]);
}
__global__ void cast_b_kernel(const float* __restrict__ W, __half* __restrict__ O,
                              int Nreal, int Npad, int K)
{
    int idx = blockIdx.x * blockDim.x + threadIdx.x;
    if (idx >= Npad * K) return;
    int n = idx / K;
    O[idx] = __float2half((n < Nreal) ? W[idx] : 0.f);
}

// ================= mma.sync fp16 GEMM (2-stage cp.async, verified R12-R16) =================
// ep=0: write fp16 to C; ep=1: write fp32 with sigmoid(gate1)*acc + feat residual
#define GEMM_SMEM_BYTES (1024 + 2*32768)
__global__ __launch_bounds__(256, 2)
void gemm_mma(const __half* __restrict__ A2, const __half* __restrict__ B2,
              void* __restrict__ Cv, int KP, int Nreal, int ldc,
              const float* __restrict__ feat, const float* __restrict__ gate1, int ep)
{
    const uint32_t base = (smem_u32(smbuf) + 1023) & ~1023u;
    const int tid  = threadIdx.x;
    const int lane = tid & 31;
    const int wid  = tid >> 5;
    const int m0 = blockIdx.y * 128;
    const int n0 = blockIdx.x * 128;
    const int wm = wid >> 2;
    const int wn = wid & 3;

    const int frow = tid >> 3;
    const int u16  = tid & 7;
    const __half* ag = A2 + (size_t)(m0 + frow) * KP + u16 * 8;
    const __half* bg = B2 + (size_t)(n0 + frow) * KP + u16 * 8;

    float acc[4][4][4] = {};
    const int nch = KP >> 6;

    uint32_t foff[4];
    #pragma unroll
    for (int j = 0; j < 4; ++j)
        foff[j] = SWZ128((frow + j*32)*128 + u16*16);

    {
        uint32_t ab = base, bb = base + 16384;
        #pragma unroll
        for (int j = 0; j < 4; ++j) {
            cpasync16(ab + foff[j], ag + (size_t)(j*32)*KP);
            cpasync16(bb + foff[j], bg + (size_t)(j*32)*KP);
        }
        asm volatile("cp.async.commit_group;" ::: "memory");
    }

    for (int c = 0; c < nch; ++c) {
        if (c + 1 < nch) {
            uint32_t ab = base + ((c+1)&1) * 32768, bb = ab + 16384;
            const __half* a = ag + (c+1) * 64;
            const __half* b = bg + (c+1) * 64;
            #pragma unroll
            for (int j = 0; j < 4; ++j) {
                cpasync16(ab + foff[j], a + (size_t)(j*32)*KP);
                cpasync16(bb + foff[j], b + (size_t)(j*32)*KP);
            }
            asm volatile("cp.async.commit_group;" ::: "memory");
            asm volatile("cp.async.wait_group 1;" ::: "memory");
        } else {
            asm volatile("cp.async.wait_group 0;" ::: "memory");
        }
        __syncthreads();

        const uint32_t ab = base + (c&1) * 32768;
        const uint32_t bb = ab + 16384;
        #pragma unroll
        for (int ks = 0; ks < 4; ++ks) {
            uint32_t a_r[4][4];
            uint32_t b_r[2][4];
            {
                const int ra = wm*64 + ((lane>>3)&1)*8 + (lane&7);
                const int ka = ks*32 + ((lane>>4)&1)*16;
                #pragma unroll
                for (int mf = 0; mf < 4; ++mf)
                    ldsm4(a_r[mf], ab + SWZ128((ra + mf*16)*128 + ka));
            }
            {
                const int rb = wn*32 + ((lane>>4)&1)*8 + (lane&7);
                const int kb = ks*32 + ((lane>>3)&1)*16;
                #pragma unroll
                for (int nf2 = 0; nf2 < 2; ++nf2)
                    ldsm4(b_r[nf2], bb + SWZ128((rb + nf2*16)*128 + kb));
            }
            #pragma unroll
            for (int mf = 0; mf < 4; ++mf)
                #pragma unroll
                for (int nf = 0; nf < 4; ++nf)
                    mma16816h(acc[mf][nf], a_r[mf], &b_r[nf>>1][(nf&1)*2], acc[mf][nf]);
        }
        __syncthreads();
    }

    float g = 0.f;
    if (ep) g = 1.f / (1.f + expf(-gate1[0]));
    const int mrow = m0 + wm*64 + (lane >> 2);
    const int nbase = n0 + wn*32 + (lane & 3)*2;
    #pragma unroll
    for (int mf = 0; mf < 4; ++mf) {
        #pragma unroll
        for (int nf = 0; nf < 4; ++nf) {
            int m = mrow + mf*16;
            int n = nbase + nf*8;
            if (n < Nreal) {
                if (ep) {
                    float* C = (float*)Cv;
                    float2 v0 = make_float2(acc[mf][nf][0], acc[mf][nf][1]);
                    float2 v1 = make_float2(acc[mf][nf][2], acc[mf][nf][3]);
                    float2 f0 = *(const float2*)(feat + (size_t)m*ldc + n);
                    float2 f1 = *(const float2*)(feat + (size_t)(m+8)*ldc + n);
                    v0.x = g*v0.x + f0.x; v0.y = g*v0.y + f0.y;
                    v1.x = g*v1.x + f1.x; v1.y = g*v1.y + f1.y;
                    *(float2*)(C + (size_t)m*ldc + n)     = v0;
                    *(float2*)(C + (size_t)(m+8)*ldc + n) = v1;
                } else {
                    __half* C = (__half*)Cv;
                    *(__half2*)(C + (size_t)m*ldc + n)     = __floats2half2_rn(acc[mf][nf][0], acc[mf][nf][1]);
                    *(__half2*)(C + (size_t)(m+8)*ldc + n) = __floats2half2_rn(acc[mf][nf][2], acc[mf][nf][3]);
                }
            }
        }
    }
}

// ---------------- depthwise causal conv + bias + SiLU, 2 channels x 4 rows per thread ----------------
__global__ void conv_silu_kernel(const float* __restrict__ cw, const float* __restrict__ cb)
{
    int cpair = blockIdx.x * 128 + threadIdx.x;     // 0..895 (DXBC/2)
    int ch = cpair * 2;
    int r0 = blockIdx.y * 4;
    int l0 = r0 % SEQL;
    float w0a = cw[ch*4+0], w1a = cw[ch*4+1], w2a = cw[ch*4+2], w3a = cw[ch*4+3];
    float w0b = cw[ch*4+4], w1b = cw[ch*4+5], w2b = cw[ch*4+6], w3b = cw[ch*4+7];
    float ba = cb[ch], bb2 = cb[ch+1];
    float2 v[7];
    #pragma unroll
    for (int t = 0; t < 7; ++t) {
        int lr = l0 + t - 3;
        if (lr >= 0) {
            __half2 h = *(const __half2*)&g_zx[(size_t)(r0 + t - 3) * DPROJ + DIN + ch];
            v[t] = __half22float2(h);
        } else v[t] = make_float2(0.f, 0.f);
    }
    #pragma unroll
    for (int j = 0; j < 4; ++j) {
        float aa = ba  + w0a*v[j].x + w1a*v[j+1].x + w2a*v[j+2].x + w3a*v[j+3].x;
        float ab = bb2 + w0b*v[j].y + w1b*v[j+1].y + w2b*v[j+2].y + w3b*v[j+3].y;
        aa = aa / (1.f + __expf(-aa));
        ab = ab / (1.f + __expf(-ab));
        *(__half2*)&g_xbc[(size_t)(r0 + j) * DXBC + ch] = __floats2half2_rn(aa, ab);
    }
}

// ---------------- dt (softplus) + per-chunk inclusive cumsum of dt*A, fused ----------------
__global__ void acum_kernel(const float* __restrict__ A_log, const float* __restrict__ dt_bias)
{
    int h  = blockIdx.x % NH;
    int bc = blockIdx.x / NH;
    int l  = threadIdx.x;
    __shared__ float s[CHUNKQ];
    float Ah = -expf(A_log[h]);
    int row = bc * CHUNKQ + l;
    float v = __half2float(g_zx[(size_t)row * DPROJ + (DIN + DXBC) + h]) + dt_bias[h];
    float dt = (v > 20.f) ? v : log1pf(expf(v));
    g_dt[row * NH + h] = dt;
    s[l] = dt * Ah;
    __syncthreads();
    for (int off = 1; off < CHUNKQ; off <<= 1) {
        float t = (l >= off) ? s[l - off] : 0.f;
        __syncthreads();
        s[l] += t;
        __syncthreads();
    }
    g_acum[row * NH + h] = s[l];
    if (l == CHUNKQ - 1) g_alast[bc * NH + h] = s[l];
}

// ================= CB via mma.sync (fp16 1-term) =================
#define CBM_SMEM_BYTES 65536
__global__ __launch_bounds__(256, 1) void cb_mma()
{
    char* sm = smbuf;
    const int bc  = blockIdx.x;
    const int tid = threadIdx.x;
    const int row0 = bc * CHUNKQ;

    for (int i = tid; i < 16384; i += 256) {
        int l = i >> 7, n = i & 127;
        const __half* baseg = &g_xbc[(size_t)(row0 + l) * DXBC + DIN];
        uint32_t off = SWZ256(l*256 + n*2);
        copy_h(sm,         off, baseg[DSTATE + n]);  // C[l][n]
        copy_h(sm + 32768, off, baseg[n]);           // B[s=l][n]
    }
    __syncthreads();

    const int lane = tid & 31;
    const int wid  = tid >> 5;
    const int wm = wid >> 2;
    const int wn = wid & 3;
    const uint32_t base = smem_u32(sm);
    float acc[4][4][4] = {};
    {
        const uint32_t ab = base, bb = base + 32768u;
        #pragma unroll
        for (int ks = 0; ks < 8; ++ks) {
            uint32_t a_r[4][4], b_r[2][4];
            const int ra = wm*64 + ((lane>>3)&1)*8 + (lane&7);
            const int ca = ks*32 + ((lane>>4)&1)*16;
            #pragma unroll
            for (int mf = 0; mf < 4; ++mf)
                ldsm4(a_r[mf], ab + SWZ256((ra + mf*16)*256 + ca));
            const int rb = wn*32 + ((lane>>4)&1)*8 + (lane&7);
            const int cb2 = ks*32 + ((lane>>3)&1)*16;
            #pragma unroll
            for (int nf2 = 0; nf2 < 2; ++nf2)
                ldsm4(b_r[nf2], bb + SWZ256((rb + nf2*16)*256 + cb2));
            #pragma unroll
            for (int mf = 0; mf < 4; ++mf)
                #pragma unroll
                for (int nf = 0; nf < 4; ++nf)
                    mma16816h(acc[mf][nf], a_r[mf], &b_r[nf>>1][(nf&1)*2], acc[mf][nf]);
        }
    }
    float* outb = &g_cb[(size_t)bc * CHUNKQ * CHUNKQ];
    const int mr = lane >> 2;
    const int nb = (lane & 3)*2;
    #pragma unroll
    for (int mf = 0; mf < 4; ++mf) {
        #pragma unroll
        for (int nf = 0; nf < 4; ++nf) {
            int l = wm*64 + mf*16 + mr;
            int s = wn*32 + nf*8 + nb;
            *(float2*)&outb[l*CHUNKQ + s]       = make_float2(acc[mf][nf][0], acc[mf][nf][1]);
            *(float2*)&outb[(l+8)*CHUNKQ + s]   = make_float2(acc[mf][nf][2], acc[mf][nf][3]);
        }
    }
}

// ================= states via mma.sync (fp16 1-term) =================
#define STM_SMEM_BYTES 49152
__global__ __launch_bounds__(128, 2) void states_mma()
{
    char* sm = smbuf;
    __shared__ float wfac[128];
    const int h  = blockIdx.x % NH;
    const int bc = blockIdx.x / NH;
    const int tid = threadIdx.x;
    const int row0 = bc * CHUNKQ;

    if (tid < 128) {
        float alast = g_alast[bc*NH + h];
        wfac[tid] = g_dt[(row0+tid)*NH + h] * __expf(alast - g_acum[(row0+tid)*NH + h]);
    }
    __syncthreads();
    for (int i = tid; i < 8192; i += 128) {
        int l = i >> 6, p = i & 63;
        float v = __half2float(g_xbc[(size_t)(row0+l)*DXBC + h*HD + p]) * wfac[l];
        store_h(sm, SWZ256(p*256 + l*2), v);
    }
    for (int i = tid; i < 16384; i += 128) {
        int l = i >> 7, n = i & 127;
        copy_h(sm + 16384, SWZ256(n*256 + l*2), g_xbc[(size_t)(row0+l)*DXBC + DIN + n]);
    }
    __syncthreads();

    const int lane = tid & 31;
    const int w = tid >> 5;
    const uint32_t base = smem_u32(sm);
    float acc[4][4][4] = {};
    {
        const uint32_t ab = base, bb = base + 16384u;
        #pragma unroll
        for (int ks = 0; ks < 8; ++ks) {
            uint32_t a_r[4][4], b_r[2][4];
            const int ra = ((lane>>3)&1)*8 + (lane&7);
            const int ca = ks*32 + ((lane>>4)&1)*16;
            #pragma unroll
            for (int mf = 0; mf < 4; ++mf)
                ldsm4(a_r[mf], ab + SWZ256((ra + mf*16)*256 + ca));
            const int rb = w*32 + ((lane>>4)&1)*8 + (lane&7);
            const int cb2 = ks*32 + ((lane>>3)&1)*16;
            #pragma unroll
            for (int nf2 = 0; nf2 < 2; ++nf2)
                ldsm4(b_r[nf2], bb + SWZ256((rb + nf2*16)*256 + cb2));
            #pragma unroll
            for (int mf = 0; mf < 4; ++mf)
                #pragma unroll
                for (int nf = 0; nf < 4; ++nf)
                    mma16816h(acc[mf][nf], a_r[mf], &b_r[nf>>1][(nf&1)*2], acc[mf][nf]);
        }
    }
    __half* outb = &g_states[((size_t)(bc*NH) + h) * HD * DSTATE];
    const int mr = lane >> 2;
    const int nb = w*32 + (lane & 3)*2;
    #pragma unroll
    for (int mf = 0; mf < 4; ++mf) {
        #pragma unroll
        for (int nf = 0; nf < 4; ++nf) {
            int p = mf*16 + mr, n = nb + nf*8;
            *(__half2*)&outb[p*DSTATE + n]     = __floats2half2_rn(acc[mf][nf][0], acc[mf][nf][1]);
            *(__half2*)&outb[(p+8)*DSTATE + n] = __floats2half2_rn(acc[mf][nf][2], acc[mf][nf][3]);
        }
    }
}

// ---------------- inter-chunk state recurrence (half2, 2 lanes per thread) ----------------
__global__ void scan_kernel()
{
    int gl = blockIdx.x * blockDim.x + threadIdx.x;  // 0..196607
    int bh = gl >> 12;                               // 4096 half2 per (bc,h)
    int b = bh / NH, h = bh % NH;
    int e2 = gl & 4095;
    float2 S = make_float2(0.f, 0.f);
    for (int c = 0; c < NCH; c++) {
        int bc = b*NCH + c;
        size_t base = ((size_t)(bc*NH) + h) * HD * DSTATE;
        float ed = __expf(g_alast[bc*NH + h]);
        float2 st = __half22float2(*(const __half2*)&g_states[base + e2*2]);
        *(__half2*)&g_prev[base + e2*2] = __floats2half2_rn(S.x, S.y);
        S.x = S.x*ed + st.x;
        S.y = S.y*ed + st.y;
    }
}

// ================= Y via mma.sync (fp16 1-term) =================
#define YM_SMEM_BYTES 49152
__device__ __forceinline__ void y_mma_block(float acc[2][4][4], uint32_t base,
                                            int lane, int wm, int wn)
{
    const uint32_t ab = base, bb = base + 32768u;
    #pragma unroll
    for (int ks = 0; ks < 8; ++ks) {
        uint32_t a_r[2][4], b_r[2][4];
        const int ra = wm*32 + ((lane>>3)&1)*8 + (lane&7);
        const int ca = ks*32 + ((lane>>4)&1)*16;
        #pragma unroll
        for (int mf = 0; mf < 2; ++mf)
            ldsm4(a_r[mf], ab + SWZ256((ra + mf*16)*256 + ca));
        const int rb = wn*32 + ((lane>>4)&1)*8 + (lane&7);
        const int cb2 = ks*32 + ((lane>>3)&1)*16;
        #pragma unroll
        for (int nf2 = 0; nf2 < 2; ++nf2)
            ldsm4(b_r[nf2], bb + SWZ256((rb + nf2*16)*256 + cb2));
        #pragma unroll
        for (int mf = 0; mf < 2; ++mf)
            #pragma unroll
            for (int nf = 0; nf < 4; ++nf)
                mma16816h(acc[mf][nf], a_r[mf], &b_r[nf>>1][(nf&1)*2], acc[mf][nf]);
    }
}

__global__ __launch_bounds__(256, 2) void y_mma(const float* __restrict__ Dv)
{
    char* sm = smbuf;
    __shared__ float acum_s[128], dt_s[128], eAl_s[128];
    const int h  = blockIdx.x % NH;
    const int bc = blockIdx.x / NH;
    const int tid = threadIdx.x;
    const int row0 = bc * CHUNKQ;

    if (tid < 128) {
        float a = g_acum[(row0+tid)*NH + h];
        acum_s[tid] = a;
        eAl_s[tid]  = __expf(a);
        dt_s[tid]   = g_dt[(row0+tid)*NH + h];
    }
    __syncthreads();

    // ---- pass 1 tiles: A = C*exp(acum[l]) [l][n], B = prev [p][n]
    for (int i = tid; i < 16384; i += 256) {
        int l = i >> 7, n = i & 127;
        float v = __half2float(g_xbc[(size_t)(row0+l)*DXBC + DIN + DSTATE + n]) * eAl_s[l];
        store_h(sm, SWZ256(l*256 + n*2), v);
    }
    const size_t pbase = ((size_t)(bc*NH) + h) * HD * DSTATE;
    for (int i = tid; i < 8192; i += 256) {
        int p = i >> 7, n = i & 127;
        copy_h(sm + 32768, SWZ256(p*256 + n*2), g_prev[pbase + i]);
    }
    __syncthreads();

    const int lane = tid & 31;
    const int wid = tid >> 5;
    const int wm = wid >> 1;
    const int wn = wid & 1;
    const uint32_t base = smem_u32(sm);
    float acc[2][4][4] = {};
    y_mma_block(acc, base, lane, wm, wn);
    __syncthreads();

    // ---- pass 2 tiles: A = W [l][s], B = xT [p][s]
    for (int i = tid; i < 16384; i += 256) {
        int l = i >> 7, s = i & 127;
        float v = 0.f;
        if (s <= l)
            v = g_cb[(size_t)bc*CHUNKQ*CHUNKQ + i] * __expf(acum_s[l] - acum_s[s]) * dt_s[s];
        store_h(sm, SWZ256(l*256 + s*2), v);
    }
    for (int i = tid; i < 8192; i += 256) {
        int l = i >> 6, p = i & 63;
        copy_h(sm + 32768, SWZ256(p*256 + l*2), g_xbc[(size_t)(row0+l)*DXBC + h*HD + p]);
    }
    __syncthreads();
    y_mma_block(acc, base, lane, wm, wn);

    // ---- epilogue: + D*x (x from fp16 plane), write Y (fp16)
    const float dval = Dv[h];
    const int mr = lane >> 2;
    const int nb = (lane & 3)*2;
    #pragma unroll
    for (int mf = 0; mf < 2; ++mf) {
        #pragma unroll
        for (int nf = 0; nf < 4; ++nf) {
            int p = wn*32 + nf*8 + nb;
            #pragma unroll
            for (int rr = 0; rr < 2; ++rr) {
                int l = wm*32 + mf*16 + mr + rr*8;
                uint32_t o0 = SWZ256(p*256 + l*2);
                uint32_t o1 = SWZ256((p+1)*256 + l*2);
                float x0 = __half2float(*(__half*)(sm + 32768 + o0));
                float x1 = __half2float(*(__half*)(sm + 32768 + o1));
                *(__half2*)&g_y[(size_t)(row0+l)*DIN + h*HD + p] =
                    __floats2half2_rn(acc[mf][nf][rr*2+0] + dval*x0,
                                      acc[mf][nf][rr*2+1] + dval*x1);
            }
        }
    }
}

// ---------------- gating + RMSNorm + fused fp16 cast for GEMM2 (half2 I/O) ----------------
__global__ void norm_split_kernel(const float* __restrict__ norm_w,
                                  __half* __restrict__ O)
{
    __shared__ float tbuf[DIN];
    __shared__ float red[256];
    int row = blockIdx.x;
    int tid = threadIdx.x;
    float partial = 0.f;
    for (int i = tid*2; i < DIN; i += 512) {
        float2 yv = __half22float2(*(const __half2*)&g_y[(size_t)row*DIN + i]);
        float2 zv = __half22float2(*(const __half2*)&g_zx[(size_t)row*DPROJ + i]);
        float t0 = yv.x * (zv.x / (1.f + __expf(-zv.x)));
        float t1 = yv.y * (zv.y / (1.f + __expf(-zv.y)));
        tbuf[i] = t0; tbuf[i+1] = t1;
        partial += t0*t0 + t1*t1;
    }
    red[tid] = partial;
    __syncthreads();
    for (int s = 128; s > 0; s >>= 1) {
        if (tid < s) red[tid] += red[tid + s];
        __syncthreads();
    }
    float scale = rsqrtf(red[0] / (float)DIN + 1e-5f);
    __half* ob = O + (size_t)row * KP2;
    for (int i = tid*2; i < DIN; i += 512)
        *(__half2*)&ob[i] = __floats2half2_rn(tbuf[i] * scale * norm_w[i],
                                              tbuf[i+1] * scale * norm_w[i+1]);
}

// ---------------- launch ----------------
extern "C" void kernel_launch(void* const* d_in, const int* in_sizes, int n_in,
                              void* d_out, int out_size)
{
    const float* feature = (const float*)d_in[0];
    const float* gate1   = (const float*)d_in[1];
    const float* in_w    = (const float*)d_in[2];
    const float* conv_w  = (const float*)d_in[3];
    const float* conv_b  = (const float*)d_in[4];
    const float* dt_bias = (const float*)d_in[5];
    const float* A_log   = (const float*)d_in[6];
    const float* Dv      = (const float*)d_in[7];
    const float* norm_w  = (const float*)d_in[8];
    const float* out_w   = (const float*)d_in[9];
    float* out = (float*)d_out;

    void* p_zx; cudaGetSymbolAddress(&p_zx, g_zx);
    void* p_a2; cudaGetSymbolAddress(&p_a2, g_a2);
    void* p_b2; cudaGetSymbolAddress(&p_b2, g_b2);
    __half* a2 = (__half*)p_a2;
    __half* b2 = (__half*)p_b2;

    cudaFuncSetAttribute(cb_mma,     cudaFuncAttributeMaxDynamicSharedMemorySize, CBM_SMEM_BYTES);
    cudaFuncSetAttribute(states_mma, cudaFuncAttributeMaxDynamicSharedMemorySize, STM_SMEM_BYTES);
    cudaFuncSetAttribute(y_mma,      cudaFuncAttributeMaxDynamicSharedMemorySize, YM_SMEM_BYTES);
    cudaFuncSetAttribute(gemm_mma,   cudaFuncAttributeMaxDynamicSharedMemorySize, GEMM_SMEM_BYTES);

    // 1. fp16 casts + GEMM1 (tensor cores, fp16 output)
    cast_a_kernel<<<(NROWS*DMODEL + 255)/256, 256>>>(feature, a2, NROWS*DMODEL);
    cast_b_kernel<<<(NPAD1*DMODEL + 255)/256, 256>>>(in_w, b2, DPROJ, NPAD1, DMODEL);
    gemm_mma<<<dim3(NPAD1/128, NROWS/128), 256, GEMM_SMEM_BYTES>>>(
        a2, b2, p_zx, KP1, DPROJ, DPROJ, nullptr, nullptr, 0);
    // 2. conv + silu (2 channels x 4 rows per thread, half2 I/O)
    conv_silu_kernel<<<dim3(DXBC/256, NROWS/4), 128>>>(conv_w, conv_b);
    // 3. dt + per-chunk cumsum (fused)
    acum_kernel<<<NBC*NH, CHUNKQ>>>(A_log, dt_bias);
    // 4. CB per chunk (tensor cores, fp16 1-term)
    cb_mma<<<NBC, 256, CBM_SMEM_BYTES>>>();
    // 5. chunk states (tensor cores, fp16 1-term, fp16 out)
    states_mma<<<NBC*NH, 128, STM_SMEM_BYTES>>>();
    // 6. inter-chunk recurrence (half2)
    scan_kernel<<<(BSZ*NH*HD*DSTATE)/1024, 512>>>();
    // 7. Y (tensor cores, fp16 1-term, fp16 out)
    y_mma<<<NBC*NH, 256, YM_SMEM_BYTES>>>(Dv);
    // 8. gating + RMSNorm + fp16 cast for GEMM2 (fused, half2)
    norm_split_kernel<<<NROWS, 256>>>(norm_w, a2);
    // 9. fp16 cast B + GEMM2 (tensor cores) + residual epilogue
    cast_b_kernel<<<(DMODEL*DIN + 255)/256, 256>>>(out_w, b2, DMODEL, DMODEL, DIN);
    gemm_mma<<<dim3(DMODEL/128, NROWS/128), 256, GEMM_SMEM_BYTES>>>(
        a2, b2, out, KP2, DMODEL, DMODEL, feature, gate1, 1);
}